// round 1
// baseline (speedup 1.0000x reference)
#include <cuda_runtime.h>

#define BSZ 4
#define SEQ 2048
#define NH 16
#define DH 64
#define DM 1024
#define TD 3072
#define MROWS (BSZ * SEQ)

#define NEG_INF (-1e30f)

// Scratch (allocation-free rule: __device__ globals)
__device__ float g_qkv[(size_t)MROWS * TD];   // [8192][3072] qkv projection output
__device__ float g_att[(size_t)MROWS * DM];   // [8192][1024] attention output (heads concat)

// ---------------------------------------------------------------------------
// GEMM 1: qkv = input @ W_qkv + b_qkv     A:[8192,1024] W:[1024,3072]
// 128x128 tile, BK=8, 256 threads, 8x8 per-thread microtile, fp32
// ---------------------------------------------------------------------------
__global__ void __launch_bounds__(256) gemm_qkv_kernel(
    const float* __restrict__ A, const float* __restrict__ W,
    const float* __restrict__ bias)
{
    __shared__ float As[8][128];   // transposed A tile
    __shared__ float Bs[8][128];
    const int bm = blockIdx.x;
    const int bn = blockIdx.y;
    const int tid = (int)threadIdx.x;
    const int aRow = tid >> 1;
    const int aCol = (tid & 1) << 2;
    const int bRow = tid >> 5;
    const int bCol = (tid & 31) << 2;
    const int ty = tid >> 4;
    const int tx = tid & 15;

    const float* Ap = A + (size_t)(bm * 128 + aRow) * DM + aCol;
    const float* Wp = W + (size_t)bRow * TD + bn * 128 + bCol;

    float acc[8][8];
#pragma unroll
    for (int i = 0; i < 8; i++)
#pragma unroll
        for (int j = 0; j < 8; j++) acc[i][j] = 0.f;

    for (int k0 = 0; k0 < DM; k0 += 8) {
        const float4 a4 = *(const float4*)(Ap + k0);
        const float4 w4 = *(const float4*)(Wp + (size_t)k0 * TD);
        __syncthreads();
        As[aCol + 0][aRow] = a4.x;
        As[aCol + 1][aRow] = a4.y;
        As[aCol + 2][aRow] = a4.z;
        As[aCol + 3][aRow] = a4.w;
        *(float4*)&Bs[bRow][bCol] = w4;
        __syncthreads();
#pragma unroll
        for (int kk = 0; kk < 8; kk++) {
            const float4 a0 = *(const float4*)&As[kk][ty << 3];
            const float4 a1 = *(const float4*)&As[kk][(ty << 3) + 4];
            const float4 b0 = *(const float4*)&Bs[kk][tx << 3];
            const float4 b1 = *(const float4*)&Bs[kk][(tx << 3) + 4];
            const float ar[8] = {a0.x, a0.y, a0.z, a0.w, a1.x, a1.y, a1.z, a1.w};
            const float br[8] = {b0.x, b0.y, b0.z, b0.w, b1.x, b1.y, b1.z, b1.w};
#pragma unroll
            for (int i = 0; i < 8; i++)
#pragma unroll
                for (int j = 0; j < 8; j++) acc[i][j] += ar[i] * br[j];
        }
    }

    const float4 bv0 = *(const float4*)&bias[bn * 128 + (tx << 3)];
    const float4 bv1 = *(const float4*)&bias[bn * 128 + (tx << 3) + 4];
    const float bb[8] = {bv0.x, bv0.y, bv0.z, bv0.w, bv1.x, bv1.y, bv1.z, bv1.w};
#pragma unroll
    for (int i = 0; i < 8; i++) {
        float* dst = g_qkv + (size_t)(bm * 128 + (ty << 3) + i) * TD + bn * 128 + (tx << 3);
        const float4 o0 = make_float4(acc[i][0] + bb[0], acc[i][1] + bb[1],
                                      acc[i][2] + bb[2], acc[i][3] + bb[3]);
        const float4 o1 = make_float4(acc[i][4] + bb[4], acc[i][5] + bb[5],
                                      acc[i][6] + bb[6], acc[i][7] + bb[7]);
        *(float4*)dst = o0;
        *(float4*)(dst + 4) = o1;
    }
}

// ---------------------------------------------------------------------------
// GEMM 2: out = g_att @ W_out + b_out     A:[8192,1024] W:[1024,1024]
// ---------------------------------------------------------------------------
__global__ void __launch_bounds__(256) gemm_out_kernel(
    const float* __restrict__ W, const float* __restrict__ bias,
    float* __restrict__ C)
{
    __shared__ float As[8][128];
    __shared__ float Bs[8][128];
    const int bm = blockIdx.x;
    const int bn = blockIdx.y;
    const int tid = (int)threadIdx.x;
    const int aRow = tid >> 1;
    const int aCol = (tid & 1) << 2;
    const int bRow = tid >> 5;
    const int bCol = (tid & 31) << 2;
    const int ty = tid >> 4;
    const int tx = tid & 15;

    const float* Ap = g_att + (size_t)(bm * 128 + aRow) * DM + aCol;
    const float* Wp = W + (size_t)bRow * DM + bn * 128 + bCol;

    float acc[8][8];
#pragma unroll
    for (int i = 0; i < 8; i++)
#pragma unroll
        for (int j = 0; j < 8; j++) acc[i][j] = 0.f;

    for (int k0 = 0; k0 < DM; k0 += 8) {
        const float4 a4 = *(const float4*)(Ap + k0);
        const float4 w4 = *(const float4*)(Wp + (size_t)k0 * DM);
        __syncthreads();
        As[aCol + 0][aRow] = a4.x;
        As[aCol + 1][aRow] = a4.y;
        As[aCol + 2][aRow] = a4.z;
        As[aCol + 3][aRow] = a4.w;
        *(float4*)&Bs[bRow][bCol] = w4;
        __syncthreads();
#pragma unroll
        for (int kk = 0; kk < 8; kk++) {
            const float4 a0 = *(const float4*)&As[kk][ty << 3];
            const float4 a1 = *(const float4*)&As[kk][(ty << 3) + 4];
            const float4 b0 = *(const float4*)&Bs[kk][tx << 3];
            const float4 b1 = *(const float4*)&Bs[kk][(tx << 3) + 4];
            const float ar[8] = {a0.x, a0.y, a0.z, a0.w, a1.x, a1.y, a1.z, a1.w};
            const float br[8] = {b0.x, b0.y, b0.z, b0.w, b1.x, b1.y, b1.z, b1.w};
#pragma unroll
            for (int i = 0; i < 8; i++)
#pragma unroll
                for (int j = 0; j < 8; j++) acc[i][j] += ar[i] * br[j];
        }
    }

    const float4 bv0 = *(const float4*)&bias[bn * 128 + (tx << 3)];
    const float4 bv1 = *(const float4*)&bias[bn * 128 + (tx << 3) + 4];
    const float bb[8] = {bv0.x, bv0.y, bv0.z, bv0.w, bv1.x, bv1.y, bv1.z, bv1.w};
#pragma unroll
    for (int i = 0; i < 8; i++) {
        float* dst = C + (size_t)(bm * 128 + (ty << 3) + i) * DM + bn * 128 + (tx << 3);
        const float4 o0 = make_float4(acc[i][0] + bb[0], acc[i][1] + bb[1],
                                      acc[i][2] + bb[2], acc[i][3] + bb[3]);
        const float4 o1 = make_float4(acc[i][4] + bb[4], acc[i][5] + bb[5],
                                      acc[i][6] + bb[6], acc[i][7] + bb[7]);
        *(float4*)dst = o0;
        *(float4*)(dst + 4) = o1;
    }
}

// ---------------------------------------------------------------------------
// Flash-style causal attention, fp32.
// Block = 64 query rows of one (b,h). 256 threads, 16x16 layout, 4x4 microtile.
// Q and K staged d-major (transposed) in smem for conflict-free LDS.128.
// ---------------------------------------------------------------------------
#define KT_S 68
#define PS_S 68
#define ATTN_SMEM_FLOATS (4096 + 64 * KT_S + 4096 + 64 * PS_S)
#define ATTN_SMEM_BYTES (ATTN_SMEM_FLOATS * 4)

__global__ void __launch_bounds__(256) attn_kernel()
{
    extern __shared__ float sh[];
    float* Qt = sh;                    // [64 d][64 r]   (scaled by 1/8)
    float* Kt = sh + 4096;             // [64 d][KT_S]
    float* Vs = Kt + 64 * KT_S;        // [64 k][64 c]
    float* Ps = Vs + 4096;             // [64 r][PS_S]

    const int qt = 31 - (int)blockIdx.x;     // heavy tiles first
    const int bh = (int)blockIdx.y;
    const int b = bh >> 4;
    const int h = bh & 15;
    const int tid = (int)threadIdx.x;
    const int ty = tid >> 4;
    const int tx = tid & 15;
    const int d4 = tid & 15;   // staging: d-chunk
    const int rr = tid >> 4;   // staging: row

    const float* Qg = g_qkv + (size_t)b * SEQ * TD + h * DH;
    const float* Kg = Qg + DM;
    const float* Vg = Qg + 2 * DM;

    // stage Q transposed & pre-scaled (1/sqrt(64) = 0.125)
#pragma unroll
    for (int rb = 0; rb < 64; rb += 16) {
        const int r = rr + rb;
        const float4 q4 = *(const float4*)(Qg + (size_t)(qt * 64 + r) * TD + (d4 << 2));
        Qt[(d4 * 4 + 0) * 64 + r] = q4.x * 0.125f;
        Qt[(d4 * 4 + 1) * 64 + r] = q4.y * 0.125f;
        Qt[(d4 * 4 + 2) * 64 + r] = q4.z * 0.125f;
        Qt[(d4 * 4 + 3) * 64 + r] = q4.w * 0.125f;
    }

    float o[4][4];
    float m[4], l[4];
#pragma unroll
    for (int i = 0; i < 4; i++) {
        m[i] = NEG_INF;
        l[i] = 0.f;
#pragma unroll
        for (int j = 0; j < 4; j++) o[i][j] = 0.f;
    }

    for (int kt = 0; kt <= qt; kt++) {
        __syncthreads();   // prior iteration done with Kt/Vs/Ps (and Q staged)
#pragma unroll
        for (int rb = 0; rb < 64; rb += 16) {
            const int r = rr + rb;
            const float4 k4 = *(const float4*)(Kg + (size_t)(kt * 64 + r) * TD + (d4 << 2));
            Kt[(d4 * 4 + 0) * KT_S + r] = k4.x;
            Kt[(d4 * 4 + 1) * KT_S + r] = k4.y;
            Kt[(d4 * 4 + 2) * KT_S + r] = k4.z;
            Kt[(d4 * 4 + 3) * KT_S + r] = k4.w;
            const float4 v4 = *(const float4*)(Vg + (size_t)(kt * 64 + r) * TD + (d4 << 2));
            *(float4*)&Vs[r * 64 + (d4 << 2)] = v4;
        }
        __syncthreads();

        // S = Q K^T (scaled)
        float s[4][4];
#pragma unroll
        for (int i = 0; i < 4; i++)
#pragma unroll
            for (int j = 0; j < 4; j++) s[i][j] = 0.f;

#pragma unroll 16
        for (int d = 0; d < 64; d++) {
            const float4 qv = *(const float4*)&Qt[d * 64 + (ty << 2)];
            const float4 kv = *(const float4*)&Kt[d * KT_S + (tx << 2)];
            const float qa[4] = {qv.x, qv.y, qv.z, qv.w};
            const float ka[4] = {kv.x, kv.y, kv.z, kv.w};
#pragma unroll
            for (int i = 0; i < 4; i++)
#pragma unroll
                for (int j = 0; j < 4; j++) s[i][j] += qa[i] * ka[j];
        }

        // causal mask on the diagonal tile
        if (kt == qt) {
            const int r0 = ty << 2, c0 = tx << 2;
#pragma unroll
            for (int i = 0; i < 4; i++)
#pragma unroll
                for (int j = 0; j < 4; j++)
                    if (c0 + j > r0 + i) s[i][j] = NEG_INF;
        }

        // online softmax (row groups = 16 consecutive lanes)
#pragma unroll
        for (int i = 0; i < 4; i++) {
            float pm = fmaxf(fmaxf(s[i][0], s[i][1]), fmaxf(s[i][2], s[i][3]));
            pm = fmaxf(pm, __shfl_xor_sync(0xffffffffu, pm, 8));
            pm = fmaxf(pm, __shfl_xor_sync(0xffffffffu, pm, 4));
            pm = fmaxf(pm, __shfl_xor_sync(0xffffffffu, pm, 2));
            pm = fmaxf(pm, __shfl_xor_sync(0xffffffffu, pm, 1));
            const float nm = fmaxf(m[i], pm);
            const float al = __expf(m[i] - nm);
            m[i] = nm;
            float ps = 0.f;
#pragma unroll
            for (int j = 0; j < 4; j++) {
                s[i][j] = __expf(s[i][j] - nm);
                ps += s[i][j];
            }
            ps += __shfl_xor_sync(0xffffffffu, ps, 8);
            ps += __shfl_xor_sync(0xffffffffu, ps, 4);
            ps += __shfl_xor_sync(0xffffffffu, ps, 2);
            ps += __shfl_xor_sync(0xffffffffu, ps, 1);
            l[i] = l[i] * al + ps;
#pragma unroll
            for (int j = 0; j < 4; j++) o[i][j] *= al;
            *(float4*)&Ps[((ty << 2) + i) * PS_S + (tx << 2)] =
                make_float4(s[i][0], s[i][1], s[i][2], s[i][3]);
        }
        __syncthreads();

        // O += P V
#pragma unroll 8
        for (int k = 0; k < 64; k++) {
            const float4 v4 = *(const float4*)&Vs[k * 64 + (tx << 2)];
            const float va[4] = {v4.x, v4.y, v4.z, v4.w};
#pragma unroll
            for (int i = 0; i < 4; i++) {
                const float p = Ps[((ty << 2) + i) * PS_S + k];
#pragma unroll
                for (int j = 0; j < 4; j++) o[i][j] += p * va[j];
            }
        }
    }

    // normalize + store (heads concatenated: col = h*64 + c)
#pragma unroll
    for (int i = 0; i < 4; i++) {
        const float inv = 1.f / l[i];
        const int n = qt * 64 + (ty << 2) + i;
        const float4 r = make_float4(o[i][0] * inv, o[i][1] * inv,
                                     o[i][2] * inv, o[i][3] * inv);
        *(float4*)(g_att + (size_t)(b * SEQ + n) * DM + h * DH + (tx << 2)) = r;
    }
}

// ---------------------------------------------------------------------------
extern "C" void kernel_launch(void* const* d_in, const int* in_sizes, int n_in,
                              void* d_out, int out_size)
{
    const float* input = (const float*)d_in[0];
    const float* W_qkv = (const float*)d_in[1];
    const float* b_qkv = (const float*)d_in[2];
    const float* W_out = (const float*)d_in[3];
    const float* b_out = (const float*)d_in[4];
    // d_in[5] = causal mask (bool) — causality is hardcoded in attn_kernel
    float* out = (float*)d_out;

    cudaFuncSetAttribute(attn_kernel,
                         cudaFuncAttributeMaxDynamicSharedMemorySize,
                         ATTN_SMEM_BYTES);

    gemm_qkv_kernel<<<dim3(MROWS / 128, TD / 128), 256>>>(input, W_qkv, b_qkv);
    attn_kernel<<<dim3(SEQ / 64, BSZ * NH), 256, ATTN_SMEM_BYTES>>>();
    gemm_out_kernel<<<dim3(MROWS / 128, DM / 128), 256>>>(W_out, b_out, out);
}

// round 3
// speedup vs baseline: 1.5049x; 1.5049x over previous
#include <cuda_runtime.h>
#include <cuda_bf16.h>
#include <cstdint>

#define BSZ 4
#define SEQ 2048
#define NH 16
#define DH 64
#define DM 1024
#define TD 3072
#define MROWS (BSZ * SEQ)

#define NEG_INF (-1e30f)

// ---------------------------------------------------------------------------
// Scratch (__device__ globals; no allocation allowed)
// ---------------------------------------------------------------------------
__device__ float g_qkv[(size_t)MROWS * TD];                 // fp32 qkv (bias added)
__device__ __nv_bfloat16 g_xhi[(size_t)MROWS * DM];         // input split hi
__device__ __nv_bfloat16 g_xlo[(size_t)MROWS * DM];         // input split lo
__device__ __nv_bfloat16 g_wqkvT_hi[(size_t)TD * DM];       // W_qkv^T split [3072][1024]
__device__ __nv_bfloat16 g_wqkvT_lo[(size_t)TD * DM];
__device__ __nv_bfloat16 g_woutT_hi[(size_t)DM * DM];       // W_out^T split [1024][1024]
__device__ __nv_bfloat16 g_woutT_lo[(size_t)DM * DM];
__device__ __nv_bfloat16 g_ahi[(size_t)MROWS * DM];         // attention out split hi
__device__ __nv_bfloat16 g_alo[(size_t)MROWS * DM];         // attention out split lo

// ---------------------------------------------------------------------------
// PTX helpers: cp.async, ldmatrix, mma.sync (all valid for target sm_100)
// ---------------------------------------------------------------------------
__device__ __forceinline__ uint32_t smem_u32(const void* p) {
    uint32_t a;
    asm("{ .reg .u64 t; cvta.to.shared.u64 t, %1; cvt.u32.u64 %0, t; }" : "=r"(a) : "l"(p));
    return a;
}

#define CP_ASYNC16(dst, src) \
    asm volatile("cp.async.cg.shared.global [%0], [%1], 16;" :: "r"(dst), "l"(src))
#define CP_COMMIT() asm volatile("cp.async.commit_group;" ::: "memory")
#define CP_WAIT(n)  asm volatile("cp.async.wait_group %0;" :: "n"(n) : "memory")

#define LDSM_X4(r0, r1, r2, r3, addr) \
    asm volatile("ldmatrix.sync.aligned.m8n8.x4.shared.b16 {%0,%1,%2,%3}, [%4];" \
                 : "=r"(r0), "=r"(r1), "=r"(r2), "=r"(r3) : "r"(addr))

#define MMA_16816(d, a, b0, b1) \
    asm volatile("mma.sync.aligned.m16n8k16.row.col.f32.bf16.bf16.f32 " \
                 "{%0,%1,%2,%3}, {%4,%5,%6,%7}, {%8,%9}, {%0,%1,%2,%3};" \
                 : "+f"((d)[0]), "+f"((d)[1]), "+f"((d)[2]), "+f"((d)[3]) \
                 : "r"((a)[0]), "r"((a)[1]), "r"((a)[2]), "r"((a)[3]), \
                   "r"(b0), "r"(b1))

// smem tile layout: logical (row, kc16B) -> swizzled byte offset.
// Two 64B rows per 128B line; chunk = (kc + 4*(row&1)) ^ (line & 7).
__device__ __forceinline__ uint32_t tile_addr(uint32_t base, int row, int kc) {
    const int line = row >> 1;
    const int chunk = (kc + ((row & 1) << 2)) ^ (line & 7);
    return base + (uint32_t)(line * 128 + chunk * 16);
}

// ---------------------------------------------------------------------------
// Conversion kernels
// ---------------------------------------------------------------------------
__global__ void __launch_bounds__(256) split_input_kernel(
    const float4* __restrict__ in, __nv_bfloat162* __restrict__ hi,
    __nv_bfloat162* __restrict__ lo)
{
    const int i = blockIdx.x * 256 + threadIdx.x;
    const float4 v = in[i];
    const __nv_bfloat16 h0 = __float2bfloat16(v.x);
    const __nv_bfloat16 h1 = __float2bfloat16(v.y);
    const __nv_bfloat16 h2 = __float2bfloat16(v.z);
    const __nv_bfloat16 h3 = __float2bfloat16(v.w);
    const __nv_bfloat16 l0 = __float2bfloat16(v.x - __bfloat162float(h0));
    const __nv_bfloat16 l1 = __float2bfloat16(v.y - __bfloat162float(h1));
    const __nv_bfloat16 l2 = __float2bfloat16(v.z - __bfloat162float(h2));
    const __nv_bfloat16 l3 = __float2bfloat16(v.w - __bfloat162float(h3));
    hi[i * 2 + 0] = __halves2bfloat162(h0, h1);
    hi[i * 2 + 1] = __halves2bfloat162(h2, h3);
    lo[i * 2 + 0] = __halves2bfloat162(l0, l1);
    lo[i * 2 + 1] = __halves2bfloat162(l2, l3);
}

// W [1024][N] fp32 -> Wt hi/lo [N][1024] bf16 (tiled transpose + split)
__global__ void __launch_bounds__(256) transpose_split_kernel(
    const float* __restrict__ W, int N,
    __nv_bfloat16* __restrict__ Thi, __nv_bfloat16* __restrict__ Tlo)
{
    __shared__ float t[32][33];
    const int n0 = blockIdx.x * 32;
    const int k0 = blockIdx.y * 32;
    const int tx = threadIdx.x & 31;
    const int ty = threadIdx.x >> 5;
#pragma unroll
    for (int i = 0; i < 32; i += 8)
        t[ty + i][tx] = W[(size_t)(k0 + ty + i) * N + n0 + tx];
    __syncthreads();
#pragma unroll
    for (int i = 0; i < 32; i += 8) {
        const float v = t[tx][ty + i];
        const __nv_bfloat16 h = __float2bfloat16(v);
        const __nv_bfloat16 l = __float2bfloat16(v - __bfloat162float(h));
        const size_t o = (size_t)(n0 + ty + i) * DM + k0 + tx;
        Thi[o] = h;
        Tlo[o] = l;
    }
}

// ---------------------------------------------------------------------------
// mma.sync GEMM: C[M, Ntot] = [Ahi|Ahi|Alo](K'=3072) x [Bhi;Blo;Bhi]^T + bias
// CTA 128x128, BK=32, 8 warps (2m x 4n), cp.async double buffer.
// ---------------------------------------------------------------------------
#define NCHUNK 96

__device__ __forceinline__ void stage_tile(uint32_t sbase,
    const __nv_bfloat16* __restrict__ src, int row0, int k0, int tid)
{
#pragma unroll
    for (int it = 0; it < 2; ++it) {
        const int idx = tid + it * 256;          // 0..511
        const int r = idx >> 2;
        const int kc = idx & 3;
        const __nv_bfloat16* g = src + (size_t)(row0 + r) * DM + k0 + kc * 8;
        CP_ASYNC16(tile_addr(sbase, r, kc), g);
    }
}

__global__ void __launch_bounds__(256) gemm_mma_kernel(
    const __nv_bfloat16* __restrict__ Ahi, const __nv_bfloat16* __restrict__ Alo,
    const __nv_bfloat16* __restrict__ Bhi, const __nv_bfloat16* __restrict__ Blo,
    const float* __restrict__ bias, float* __restrict__ C, int Ntot)
{
    __shared__ __align__(1024) uint8_t smem_raw[32768];  // A0 A1 B0 B1 (8KB each)
    const uint32_t sbase = smem_u32(smem_raw);

    const int tid = (int)threadIdx.x;
    const int wid = tid >> 5;
    const int lane = tid & 31;
    const int wm = wid & 1;          // 0,1 -> 64-row half
    const int wn = wid >> 1;         // 0..3 -> 32-col slice

    const int m0g = blockIdx.x * 128;
    const int n0g = blockIdx.y * 128;

    float acc[4][4][4];
#pragma unroll
    for (int mt = 0; mt < 4; mt++)
#pragma unroll
        for (int nt = 0; nt < 4; nt++)
#pragma unroll
            for (int j = 0; j < 4; j++) acc[mt][nt][j] = 0.f;

    // chunk c: g=c>>5 (0,1,2), k0=(c&31)*32.  A: g==2 -> Alo else Ahi.
    //                                         B: g==1 -> Blo else Bhi.
    stage_tile(sbase,         Ahi, m0g, 0, tid);
    stage_tile(sbase + 16384, Bhi, n0g, 0, tid);
    CP_COMMIT();

    int buf = 0;
    for (int c = 0; c < NCHUNK; ++c) {
        if (c + 1 < NCHUNK) {
            const int cn = c + 1;
            const int g = cn >> 5;
            const int k0 = (cn & 31) * 32;
            const int nb = buf ^ 1;
            stage_tile(sbase + nb * 8192,         (g == 2) ? Alo : Ahi, m0g, k0, tid);
            stage_tile(sbase + 16384 + nb * 8192, (g == 1) ? Blo : Bhi, n0g, k0, tid);
            CP_COMMIT();
            CP_WAIT(1);
        } else {
            CP_WAIT(0);
        }
        __syncthreads();

        const uint32_t abase = sbase + buf * 8192;
        const uint32_t bbase = sbase + 16384 + buf * 8192;

#pragma unroll
        for (int ks = 0; ks < 2; ++ks) {
            uint32_t af[4][4];
#pragma unroll
            for (int mt = 0; mt < 4; mt++) {
                // matrix id = lane>>3: bit0 -> +8 rows, bit1 -> k halves
                const int mat = lane >> 3;
                const int row = wm * 64 + mt * 16 + (lane & 7) + ((mat & 1) << 3);
                const int kc = ks * 2 + (mat >> 1);
                LDSM_X4(af[mt][0], af[mt][1], af[mt][2], af[mt][3],
                        tile_addr(abase, row, kc));
            }
            uint32_t bf[2][4];
#pragma unroll
            for (int ntp = 0; ntp < 2; ntp++) {
                // matrix id: bit0 -> k half, bit1 -> +8 n rows
                const int mat = lane >> 3;
                const int row = wn * 32 + ntp * 16 + (lane & 7) + ((mat >> 1) << 3);
                const int kc = ks * 2 + (mat & 1);
                LDSM_X4(bf[ntp][0], bf[ntp][1], bf[ntp][2], bf[ntp][3],
                        tile_addr(bbase, row, kc));
            }
#pragma unroll
            for (int mt = 0; mt < 4; mt++)
#pragma unroll
                for (int nt = 0; nt < 4; nt++)
                    MMA_16816(acc[mt][nt], af[mt],
                              bf[nt >> 1][2 * (nt & 1)], bf[nt >> 1][2 * (nt & 1) + 1]);
        }
        __syncthreads();
        buf ^= 1;
    }

    // Epilogue: add bias, store fp32
    const int qrow = lane >> 2;
    const int qcol = (lane & 3) << 1;
    float2 bv[4];
#pragma unroll
    for (int nt = 0; nt < 4; nt++) {
        const int n = n0g + wn * 32 + nt * 8 + qcol;
        bv[nt] = make_float2(bias[n], bias[n + 1]);
    }
#pragma unroll
    for (int mt = 0; mt < 4; mt++) {
        const int r0 = m0g + wm * 64 + mt * 16 + qrow;
#pragma unroll
        for (int nt = 0; nt < 4; nt++) {
            const int n = n0g + wn * 32 + nt * 8 + qcol;
            *(float2*)(C + (size_t)r0 * Ntot + n) =
                make_float2(acc[mt][nt][0] + bv[nt].x, acc[mt][nt][1] + bv[nt].y);
            *(float2*)(C + (size_t)(r0 + 8) * Ntot + n) =
                make_float2(acc[mt][nt][2] + bv[nt].x, acc[mt][nt][3] + bv[nt].y);
        }
    }
}

// ---------------------------------------------------------------------------
// Flash-style causal attention, fp32; epilogue writes bf16 hi/lo split.
// ---------------------------------------------------------------------------
#define KT_S 68
#define PS_S 68
#define ATTN_SMEM_FLOATS (4096 + 64 * KT_S + 4096 + 64 * PS_S)
#define ATTN_SMEM_BYTES (ATTN_SMEM_FLOATS * 4)

__global__ void __launch_bounds__(256) attn_kernel()
{
    extern __shared__ float sh[];
    float* Qt = sh;                    // [64 d][64 r] (scaled by 1/8)
    float* Kt = sh + 4096;             // [64 d][KT_S]
    float* Vs = Kt + 64 * KT_S;        // [64 k][64 c]
    float* Ps = Vs + 4096;             // [64 r][PS_S]

    const int qt = 31 - (int)blockIdx.x;
    const int bh = (int)blockIdx.y;
    const int b = bh >> 4;
    const int h = bh & 15;
    const int tid = (int)threadIdx.x;
    const int ty = tid >> 4;
    const int tx = tid & 15;
    const int d4 = tid & 15;
    const int rr = tid >> 4;

    const float* Qg = g_qkv + (size_t)b * SEQ * TD + h * DH;
    const float* Kg = Qg + DM;
    const float* Vg = Qg + 2 * DM;

#pragma unroll
    for (int rb = 0; rb < 64; rb += 16) {
        const int r = rr + rb;
        const float4 q4 = *(const float4*)(Qg + (size_t)(qt * 64 + r) * TD + (d4 << 2));
        Qt[(d4 * 4 + 0) * 64 + r] = q4.x * 0.125f;
        Qt[(d4 * 4 + 1) * 64 + r] = q4.y * 0.125f;
        Qt[(d4 * 4 + 2) * 64 + r] = q4.z * 0.125f;
        Qt[(d4 * 4 + 3) * 64 + r] = q4.w * 0.125f;
    }

    float o[4][4];
    float m[4], l[4];
#pragma unroll
    for (int i = 0; i < 4; i++) {
        m[i] = NEG_INF;
        l[i] = 0.f;
#pragma unroll
        for (int j = 0; j < 4; j++) o[i][j] = 0.f;
    }

    for (int kt = 0; kt <= qt; kt++) {
        __syncthreads();
#pragma unroll
        for (int rb = 0; rb < 64; rb += 16) {
            const int r = rr + rb;
            const float4 k4 = *(const float4*)(Kg + (size_t)(kt * 64 + r) * TD + (d4 << 2));
            Kt[(d4 * 4 + 0) * KT_S + r] = k4.x;
            Kt[(d4 * 4 + 1) * KT_S + r] = k4.y;
            Kt[(d4 * 4 + 2) * KT_S + r] = k4.z;
            Kt[(d4 * 4 + 3) * KT_S + r] = k4.w;
            const float4 v4 = *(const float4*)(Vg + (size_t)(kt * 64 + r) * TD + (d4 << 2));
            *(float4*)&Vs[r * 64 + (d4 << 2)] = v4;
        }
        __syncthreads();

        float s[4][4];
#pragma unroll
        for (int i = 0; i < 4; i++)
#pragma unroll
            for (int j = 0; j < 4; j++) s[i][j] = 0.f;

#pragma unroll 16
        for (int d = 0; d < 64; d++) {
            const float4 qv = *(const float4*)&Qt[d * 64 + (ty << 2)];
            const float4 kv = *(const float4*)&Kt[d * KT_S + (tx << 2)];
            const float qa[4] = {qv.x, qv.y, qv.z, qv.w};
            const float ka[4] = {kv.x, kv.y, kv.z, kv.w};
#pragma unroll
            for (int i = 0; i < 4; i++)
#pragma unroll
                for (int j = 0; j < 4; j++) s[i][j] += qa[i] * ka[j];
        }

        if (kt == qt) {
            const int r0 = ty << 2, c0 = tx << 2;
#pragma unroll
            for (int i = 0; i < 4; i++)
#pragma unroll
                for (int j = 0; j < 4; j++)
                    if (c0 + j > r0 + i) s[i][j] = NEG_INF;
        }

#pragma unroll
        for (int i = 0; i < 4; i++) {
            float pm = fmaxf(fmaxf(s[i][0], s[i][1]), fmaxf(s[i][2], s[i][3]));
            pm = fmaxf(pm, __shfl_xor_sync(0xffffffffu, pm, 8));
            pm = fmaxf(pm, __shfl_xor_sync(0xffffffffu, pm, 4));
            pm = fmaxf(pm, __shfl_xor_sync(0xffffffffu, pm, 2));
            pm = fmaxf(pm, __shfl_xor_sync(0xffffffffu, pm, 1));
            const float nm = fmaxf(m[i], pm);
            const float al = __expf(m[i] - nm);
            m[i] = nm;
            float ps = 0.f;
#pragma unroll
            for (int j = 0; j < 4; j++) {
                s[i][j] = __expf(s[i][j] - nm);
                ps += s[i][j];
            }
            ps += __shfl_xor_sync(0xffffffffu, ps, 8);
            ps += __shfl_xor_sync(0xffffffffu, ps, 4);
            ps += __shfl_xor_sync(0xffffffffu, ps, 2);
            ps += __shfl_xor_sync(0xffffffffu, ps, 1);
            l[i] = l[i] * al + ps;
#pragma unroll
            for (int j = 0; j < 4; j++) o[i][j] *= al;
            *(float4*)&Ps[((ty << 2) + i) * PS_S + (tx << 2)] =
                make_float4(s[i][0], s[i][1], s[i][2], s[i][3]);
        }
        __syncthreads();

#pragma unroll 8
        for (int k = 0; k < 64; k++) {
            const float4 v4 = *(const float4*)&Vs[k * 64 + (tx << 2)];
            const float va[4] = {v4.x, v4.y, v4.z, v4.w};
#pragma unroll
            for (int i = 0; i < 4; i++) {
                const float p = Ps[((ty << 2) + i) * PS_S + k];
#pragma unroll
                for (int j = 0; j < 4; j++) o[i][j] += p * va[j];
            }
        }
    }

#pragma unroll
    for (int i = 0; i < 4; i++) {
        const float inv = 1.f / l[i];
        const int n = qt * 64 + (ty << 2) + i;
        const size_t base = (size_t)(b * SEQ + n) * DM + h * DH + (tx << 2);
        const float v0 = o[i][0] * inv, v1 = o[i][1] * inv;
        const float v2 = o[i][2] * inv, v3 = o[i][3] * inv;
        const __nv_bfloat16 h0 = __float2bfloat16(v0), h1 = __float2bfloat16(v1);
        const __nv_bfloat16 h2 = __float2bfloat16(v2), h3 = __float2bfloat16(v3);
        const __nv_bfloat16 q0 = __float2bfloat16(v0 - __bfloat162float(h0));
        const __nv_bfloat16 q1 = __float2bfloat16(v1 - __bfloat162float(h1));
        const __nv_bfloat16 q2 = __float2bfloat16(v2 - __bfloat162float(h2));
        const __nv_bfloat16 q3 = __float2bfloat16(v3 - __bfloat162float(h3));
        *(__nv_bfloat162*)(g_ahi + base)     = __halves2bfloat162(h0, h1);
        *(__nv_bfloat162*)(g_ahi + base + 2) = __halves2bfloat162(h2, h3);
        *(__nv_bfloat162*)(g_alo + base)     = __halves2bfloat162(q0, q1);
        *(__nv_bfloat162*)(g_alo + base + 2) = __halves2bfloat162(q2, q3);
    }
}

// ---------------------------------------------------------------------------
extern "C" void kernel_launch(void* const* d_in, const int* in_sizes, int n_in,
                              void* d_out, int out_size)
{
    const float* input = (const float*)d_in[0];
    const float* W_qkv = (const float*)d_in[1];
    const float* b_qkv = (const float*)d_in[2];
    const float* W_out = (const float*)d_in[3];
    const float* b_out = (const float*)d_in[4];
    float* out = (float*)d_out;

    cudaFuncSetAttribute(attn_kernel,
                         cudaFuncAttributeMaxDynamicSharedMemorySize, ATTN_SMEM_BYTES);

    __nv_bfloat16 *xhi, *xlo, *wqh, *wql, *woh, *wol, *ahi, *alo;
    float* qkv;
    cudaGetSymbolAddress((void**)&xhi, g_xhi);
    cudaGetSymbolAddress((void**)&xlo, g_xlo);
    cudaGetSymbolAddress((void**)&wqh, g_wqkvT_hi);
    cudaGetSymbolAddress((void**)&wql, g_wqkvT_lo);
    cudaGetSymbolAddress((void**)&woh, g_woutT_hi);
    cudaGetSymbolAddress((void**)&wol, g_woutT_lo);
    cudaGetSymbolAddress((void**)&ahi, g_ahi);
    cudaGetSymbolAddress((void**)&alo, g_alo);
    cudaGetSymbolAddress((void**)&qkv, g_qkv);

    // 1. split input into bf16 hi/lo
    split_input_kernel<<<(MROWS * DM / 4) / 256, 256>>>(
        (const float4*)input, (__nv_bfloat162*)xhi, (__nv_bfloat162*)xlo);

    // 2. transpose+split weights
    transpose_split_kernel<<<dim3(TD / 32, DM / 32), 256>>>(W_qkv, TD, wqh, wql);
    transpose_split_kernel<<<dim3(DM / 32, DM / 32), 256>>>(W_out, DM, woh, wol);

    // 3. qkv = x @ W_qkv + b  (HMMA bf16x3, fp32 out)
    gemm_mma_kernel<<<dim3(MROWS / 128, TD / 128), 256>>>(
        xhi, xlo, wqh, wql, b_qkv, qkv, TD);

    // 4. causal attention (fp32), writes bf16 hi/lo split
    attn_kernel<<<dim3(SEQ / 64, BSZ * NH), 256, ATTN_SMEM_BYTES>>>();

    // 5. out = att @ W_out + b  (HMMA bf16x3)
    gemm_mma_kernel<<<dim3(MROWS / 128, DM / 128), 256>>>(
        ahi, alo, woh, wol, b_out, out, DM);
}

// round 5
// speedup vs baseline: 2.7995x; 1.8603x over previous
#include <cuda_runtime.h>
#include <cuda_bf16.h>
#include <cstdint>

#define BSZ 4
#define SEQ 2048
#define NH 16
#define DH 64
#define DM 1024
#define TD 3072
#define MROWS (BSZ * SEQ)
#define NBH (BSZ * NH)

#define NEG_BIG (-1e30f)
#define SCALE_L2E 0.18033688011112042f   // 0.125 * log2(e)

// ---------------------------------------------------------------------------
// Scratch (__device__ globals; no allocation allowed)
// ---------------------------------------------------------------------------
__device__ float g_qkv[(size_t)MROWS * TD];                 // fp32 qkv (bias added)
__device__ __nv_bfloat16 g_xhi[(size_t)MROWS * DM];
__device__ __nv_bfloat16 g_xlo[(size_t)MROWS * DM];
__device__ __nv_bfloat16 g_wqkvT_hi[(size_t)TD * DM];
__device__ __nv_bfloat16 g_wqkvT_lo[(size_t)TD * DM];
__device__ __nv_bfloat16 g_woutT_hi[(size_t)DM * DM];
__device__ __nv_bfloat16 g_woutT_lo[(size_t)DM * DM];
__device__ __nv_bfloat16 g_ahi[(size_t)MROWS * DM];
__device__ __nv_bfloat16 g_alo[(size_t)MROWS * DM];
// per-head bf16 splits for attention (bh-major)
__device__ __nv_bfloat16 g_qh[(size_t)NBH * SEQ * DH];      // [bh][s][d], pre-scaled
__device__ __nv_bfloat16 g_ql[(size_t)NBH * SEQ * DH];
__device__ __nv_bfloat16 g_kh[(size_t)NBH * SEQ * DH];      // [bh][s][d]
__device__ __nv_bfloat16 g_kl[(size_t)NBH * SEQ * DH];
__device__ __nv_bfloat16 g_vth[(size_t)NBH * DH * SEQ];     // [bh][d][s] (transposed)
__device__ __nv_bfloat16 g_vtl[(size_t)NBH * DH * SEQ];

// ---------------------------------------------------------------------------
// PTX helpers (valid for target sm_100)
// ---------------------------------------------------------------------------
__device__ __forceinline__ uint32_t smem_u32(const void* p) {
    uint32_t a;
    asm("{ .reg .u64 t; cvta.to.shared.u64 t, %1; cvt.u32.u64 %0, t; }" : "=r"(a) : "l"(p));
    return a;
}

#define CP_ASYNC16(dst, src) \
    asm volatile("cp.async.cg.shared.global [%0], [%1], 16;" :: "r"(dst), "l"(src))
#define CP_COMMIT() asm volatile("cp.async.commit_group;" ::: "memory")
#define CP_WAIT(n)  asm volatile("cp.async.wait_group %0;" :: "n"(n) : "memory")

#define LDSM_X4(r0, r1, r2, r3, addr) \
    asm volatile("ldmatrix.sync.aligned.m8n8.x4.shared.b16 {%0,%1,%2,%3}, [%4];" \
                 : "=r"(r0), "=r"(r1), "=r"(r2), "=r"(r3) : "r"(addr))

#define MMA_16816(d, a, b0, b1) \
    asm volatile("mma.sync.aligned.m16n8k16.row.col.f32.bf16.bf16.f32 " \
                 "{%0,%1,%2,%3}, {%4,%5,%6,%7}, {%8,%9}, {%0,%1,%2,%3};" \
                 : "+f"((d)[0]), "+f"((d)[1]), "+f"((d)[2]), "+f"((d)[3]) \
                 : "r"((a)[0]), "r"((a)[1]), "r"((a)[2]), "r"((a)[3]), \
                   "r"(b0), "r"(b1))

__device__ __forceinline__ float ex2f(float x) {
    float y;
    asm("ex2.approx.ftz.f32 %0, %1;" : "=f"(y) : "f"(x));
    return y;
}

__device__ __forceinline__ uint32_t pack_bf16(__nv_bfloat16 lo, __nv_bfloat16 hi) {
    __nv_bfloat162 t = __halves2bfloat162(lo, hi);
    return *(uint32_t*)&t;
}

// 64B-per-row tile (BK=32 GEMM): two rows per 128B line
__device__ __forceinline__ uint32_t tile_addr(uint32_t base, int row, int kc) {
    const int line = row >> 1;
    const int chunk = (kc + ((row & 1) << 2)) ^ (line & 7);
    return base + (uint32_t)(line * 128 + chunk * 16);
}
// 128B-per-row tile (attention, 64 bf16 per row): SW within line
__device__ __forceinline__ uint32_t addr128(uint32_t base, int row, int kc) {
    return base + (uint32_t)(row * 128 + ((kc ^ (row & 7)) * 16));
}

// ---------------------------------------------------------------------------
// Conversion kernels
// ---------------------------------------------------------------------------
__global__ void __launch_bounds__(256) split_input_kernel(
    const float4* __restrict__ in, __nv_bfloat162* __restrict__ hi,
    __nv_bfloat162* __restrict__ lo)
{
    const int i = blockIdx.x * 256 + threadIdx.x;
    const float4 v = in[i];
    const __nv_bfloat16 h0 = __float2bfloat16(v.x);
    const __nv_bfloat16 h1 = __float2bfloat16(v.y);
    const __nv_bfloat16 h2 = __float2bfloat16(v.z);
    const __nv_bfloat16 h3 = __float2bfloat16(v.w);
    hi[i * 2 + 0] = __halves2bfloat162(h0, h1);
    hi[i * 2 + 1] = __halves2bfloat162(h2, h3);
    lo[i * 2 + 0] = __halves2bfloat162(__float2bfloat16(v.x - __bfloat162float(h0)),
                                       __float2bfloat16(v.y - __bfloat162float(h1)));
    lo[i * 2 + 1] = __halves2bfloat162(__float2bfloat16(v.z - __bfloat162float(h2)),
                                       __float2bfloat16(v.w - __bfloat162float(h3)));
}

__global__ void __launch_bounds__(256) transpose_split_kernel(
    const float* __restrict__ W, int N,
    __nv_bfloat16* __restrict__ Thi, __nv_bfloat16* __restrict__ Tlo)
{
    __shared__ float t[32][33];
    const int n0 = blockIdx.x * 32;
    const int k0 = blockIdx.y * 32;
    const int tx = threadIdx.x & 31;
    const int ty = threadIdx.x >> 5;
#pragma unroll
    for (int i = 0; i < 32; i += 8)
        t[ty + i][tx] = W[(size_t)(k0 + ty + i) * N + n0 + tx];
    __syncthreads();
#pragma unroll
    for (int i = 0; i < 32; i += 8) {
        const float v = t[tx][ty + i];
        const __nv_bfloat16 h = __float2bfloat16(v);
        const size_t o = (size_t)(n0 + ty + i) * DM + k0 + tx;
        Thi[o] = h;
        Tlo[o] = __float2bfloat16(v - __bfloat162float(h));
    }
}

// prep: split Q(scaled)/K into bf16 hi/lo [bh][s][d]; V transposed [bh][d][s]
__global__ void __launch_bounds__(256) prep_kernel()
{
    __shared__ float vs[64][65];
    const int st = blockIdx.x;
    const int bh = (int)blockIdx.y;
    const int b = bh >> 4;
    const int h = bh & 15;
    const int tid = (int)threadIdx.x;

#pragma unroll
    for (int i = 0; i < 16; i++) {
        const int idx = tid + i * 256;
        const int s = idx >> 6;
        const int d = idx & 63;
        const float* src = g_qkv + (size_t)(b * SEQ + st * 64 + s) * TD + h * DH + d;
        const float q = src[0] * SCALE_L2E;
        const float k = src[DM];
        vs[s][d] = src[2 * DM];
        const size_t o = ((size_t)bh * SEQ + st * 64 + s) * DH + d;
        const __nv_bfloat16 qh = __float2bfloat16(q);
        const __nv_bfloat16 kh = __float2bfloat16(k);
        g_qh[o] = qh;
        g_ql[o] = __float2bfloat16(q - __bfloat162float(qh));
        g_kh[o] = kh;
        g_kl[o] = __float2bfloat16(k - __bfloat162float(kh));
    }
    __syncthreads();
#pragma unroll
    for (int i = 0; i < 16; i++) {
        const int idx = tid + i * 256;
        const int d = idx >> 6;
        const int s = idx & 63;
        const float v = vs[s][d];
        const __nv_bfloat16 vh = __float2bfloat16(v);
        const size_t o = ((size_t)bh * DH + d) * SEQ + st * 64 + s;
        g_vth[o] = vh;
        g_vtl[o] = __float2bfloat16(v - __bfloat162float(vh));
    }
}

// ---------------------------------------------------------------------------
// mma.sync GEMM: C = [Ahi|Ahi|Alo] x [Bhi;Blo;Bhi]^T + bias
// ---------------------------------------------------------------------------
#define NCHUNK 96

__device__ __forceinline__ void stage_tile(uint32_t sbase,
    const __nv_bfloat16* __restrict__ src, int row0, int k0, int tid)
{
#pragma unroll
    for (int it = 0; it < 2; ++it) {
        const int idx = tid + it * 256;
        const int r = idx >> 2;
        const int kc = idx & 3;
        CP_ASYNC16(tile_addr(sbase, r, kc), src + (size_t)(row0 + r) * DM + k0 + kc * 8);
    }
}

__global__ void __launch_bounds__(256) gemm_mma_kernel(
    const __nv_bfloat16* __restrict__ Ahi, const __nv_bfloat16* __restrict__ Alo,
    const __nv_bfloat16* __restrict__ Bhi, const __nv_bfloat16* __restrict__ Blo,
    const float* __restrict__ bias, float* __restrict__ C, int Ntot)
{
    __shared__ __align__(1024) uint8_t smem_raw[32768];
    const uint32_t sbase = smem_u32(smem_raw);

    const int tid = (int)threadIdx.x;
    const int wid = tid >> 5;
    const int lane = tid & 31;
    const int wm = wid & 1;
    const int wn = wid >> 1;

    const int m0g = blockIdx.x * 128;
    const int n0g = blockIdx.y * 128;

    float acc[4][4][4];
#pragma unroll
    for (int mt = 0; mt < 4; mt++)
#pragma unroll
        for (int nt = 0; nt < 4; nt++)
#pragma unroll
            for (int j = 0; j < 4; j++) acc[mt][nt][j] = 0.f;

    stage_tile(sbase,         Ahi, m0g, 0, tid);
    stage_tile(sbase + 16384, Bhi, n0g, 0, tid);
    CP_COMMIT();

    int buf = 0;
    for (int c = 0; c < NCHUNK; ++c) {
        if (c + 1 < NCHUNK) {
            const int cn = c + 1;
            const int g = cn >> 5;
            const int k0 = (cn & 31) * 32;
            const int nb = buf ^ 1;
            stage_tile(sbase + nb * 8192,         (g == 2) ? Alo : Ahi, m0g, k0, tid);
            stage_tile(sbase + 16384 + nb * 8192, (g == 1) ? Blo : Bhi, n0g, k0, tid);
            CP_COMMIT();
            CP_WAIT(1);
        } else {
            CP_WAIT(0);
        }
        __syncthreads();

        const uint32_t abase = sbase + buf * 8192;
        const uint32_t bbase = sbase + 16384 + buf * 8192;

#pragma unroll
        for (int ks = 0; ks < 2; ++ks) {
            uint32_t af[4][4];
#pragma unroll
            for (int mt = 0; mt < 4; mt++) {
                const int mat = lane >> 3;
                const int row = wm * 64 + mt * 16 + (lane & 7) + ((mat & 1) << 3);
                const int kc = ks * 2 + (mat >> 1);
                LDSM_X4(af[mt][0], af[mt][1], af[mt][2], af[mt][3],
                        tile_addr(abase, row, kc));
            }
            uint32_t bf[2][4];
#pragma unroll
            for (int ntp = 0; ntp < 2; ntp++) {
                const int mat = lane >> 3;
                const int row = wn * 32 + ntp * 16 + (lane & 7) + ((mat >> 1) << 3);
                const int kc = ks * 2 + (mat & 1);
                LDSM_X4(bf[ntp][0], bf[ntp][1], bf[ntp][2], bf[ntp][3],
                        tile_addr(bbase, row, kc));
            }
#pragma unroll
            for (int mt = 0; mt < 4; mt++)
#pragma unroll
                for (int nt = 0; nt < 4; nt++)
                    MMA_16816(acc[mt][nt], af[mt],
                              bf[nt >> 1][2 * (nt & 1)], bf[nt >> 1][2 * (nt & 1) + 1]);
        }
        __syncthreads();
        buf ^= 1;
    }

    const int qrow = lane >> 2;
    const int qcol = (lane & 3) << 1;
    float2 bv[4];
#pragma unroll
    for (int nt = 0; nt < 4; nt++) {
        const int n = n0g + wn * 32 + nt * 8 + qcol;
        bv[nt] = make_float2(bias[n], bias[n + 1]);
    }
#pragma unroll
    for (int mt = 0; mt < 4; mt++) {
        const int r0 = m0g + wm * 64 + mt * 16 + qrow;
#pragma unroll
        for (int nt = 0; nt < 4; nt++) {
            const int n = n0g + wn * 32 + nt * 8 + qcol;
            *(float2*)(C + (size_t)r0 * Ntot + n) =
                make_float2(acc[mt][nt][0] + bv[nt].x, acc[mt][nt][1] + bv[nt].y);
            *(float2*)(C + (size_t)(r0 + 8) * Ntot + n) =
                make_float2(acc[mt][nt][2] + bv[nt].x, acc[mt][nt][3] + bv[nt].y);
        }
    }
}

// ---------------------------------------------------------------------------
// HMMA flash attention. Block = 128 q-rows x one (b,h). 8 warps x 16 rows.
// ---------------------------------------------------------------------------
#define SM_QH 0
#define SM_QL 16384
#define SM_KH(b) (32768 + (b) * 16384)
#define SM_KL(b) (40960 + (b) * 16384)
#define SM_VH(b) (65536 + (b) * 16384)
#define SM_VL(b) (73728 + (b) * 16384)
#define ATTN_SMEM_BYTES 98304

__global__ void __launch_bounds__(256) attn_mma_kernel()
{
    extern __shared__ uint8_t dsm[];
    const uint32_t sb = smem_u32(dsm);
    const int tid = (int)threadIdx.x;
    const int wid = tid >> 5;
    const int lane = tid & 31;
    const int qti = 15 - (int)blockIdx.x;       // heavy tiles first
    const int bh = (int)blockIdx.y;
    const int b = bh >> 4;
    const int h = bh & 15;

    const size_t qkbase = (size_t)bh * SEQ * DH;
    const size_t vbase = (size_t)bh * DH * SEQ;

#pragma unroll
    for (int i = 0; i < 4; i++) {
        const int idx = tid + i * 256;
        const int r = idx >> 3;
        const int kc = idx & 7;
        CP_ASYNC16(addr128(sb + SM_QH, r, kc),
                   g_qh + qkbase + (size_t)(qti * 128 + r) * DH + kc * 8);
        CP_ASYNC16(addr128(sb + SM_QL, r, kc),
                   g_ql + qkbase + (size_t)(qti * 128 + r) * DH + kc * 8);
    }

    const int nkt = 2 * qti + 2;

    auto stage_kv = [&](int kt, int bb) {
#pragma unroll
        for (int i = 0; i < 2; i++) {
            const int idx = tid + i * 256;
            const int r = idx >> 3;
            const int kc = idx & 7;
            const size_t ko = qkbase + (size_t)(kt * 64 + r) * DH + kc * 8;
            CP_ASYNC16(addr128(sb + SM_KH(bb), r, kc), g_kh + ko);
            CP_ASYNC16(addr128(sb + SM_KL(bb), r, kc), g_kl + ko);
            const size_t vo = vbase + (size_t)r * SEQ + kt * 64 + kc * 8;
            CP_ASYNC16(addr128(sb + SM_VH(bb), r, kc), g_vth + vo);
            CP_ASYNC16(addr128(sb + SM_VL(bb), r, kc), g_vtl + vo);
        }
    };

    stage_kv(0, 0);
    CP_COMMIT();

    float o[8][4];
#pragma unroll
    for (int t = 0; t < 8; t++)
#pragma unroll
        for (int j = 0; j < 4; j++) o[t][j] = 0.f;
    float m_a = NEG_BIG, m_b = NEG_BIG, l_a = 0.f, l_b = 0.f;

    const int qrow_base = qti * 128 + wid * 16;
    const int ra = lane >> 2;
    const int c2 = (lane & 3) << 1;

    int buf = 0;
    for (int kt = 0; kt < nkt; kt++) {
        if (kt + 1 < nkt) {
            stage_kv(kt + 1, buf ^ 1);
            CP_COMMIT();
            CP_WAIT(1);
        } else {
            CP_WAIT(0);
        }
        __syncthreads();

        // ---- S = Q K^T (3 split terms) ----
        float s[8][4];
#pragma unroll
        for (int t = 0; t < 8; t++)
#pragma unroll
            for (int j = 0; j < 4; j++) s[t][j] = 0.f;

#pragma unroll
        for (int ks = 0; ks < 4; ks++) {
            const int mat = lane >> 3;
            const int arow = wid * 16 + (lane & 7) + ((mat & 1) << 3);
            const int akc = ks * 2 + (mat >> 1);
            uint32_t aqh[4], aql[4];
            LDSM_X4(aqh[0], aqh[1], aqh[2], aqh[3], addr128(sb + SM_QH, arow, akc));
            LDSM_X4(aql[0], aql[1], aql[2], aql[3], addr128(sb + SM_QL, arow, akc));

            const int brow7 = (lane & 7) + ((mat >> 1) << 3);
            const int bkc = ks * 2 + (mat & 1);
#pragma unroll
            for (int ntp = 0; ntp < 4; ntp++) {
                uint32_t bh4[4], bl4[4];
                LDSM_X4(bh4[0], bh4[1], bh4[2], bh4[3],
                        addr128(sb + SM_KH(buf), ntp * 16 + brow7, bkc));
                LDSM_X4(bl4[0], bl4[1], bl4[2], bl4[3],
                        addr128(sb + SM_KL(buf), ntp * 16 + brow7, bkc));
#pragma unroll
                for (int half = 0; half < 2; half++) {
                    const int nt = ntp * 2 + half;
                    MMA_16816(s[nt], aqh, bh4[2 * half], bh4[2 * half + 1]);
                    MMA_16816(s[nt], aql, bh4[2 * half], bh4[2 * half + 1]);
                    MMA_16816(s[nt], aqh, bl4[2 * half], bl4[2 * half + 1]);
                }
            }
        }

        // ---- causal mask: needed whenever max col of tile exceeds MIN row ----
        if (kt * 64 + 63 > qrow_base) {           // FIXED (was qrow_base + 15)
#pragma unroll
            for (int t = 0; t < 8; t++) {
                const int col = kt * 64 + t * 8 + c2;
                const int rowa = qrow_base + ra;
                const int rowb = rowa + 8;
                if (col > rowa)     s[t][0] = NEG_BIG;
                if (col + 1 > rowa) s[t][1] = NEG_BIG;
                if (col > rowb)     s[t][2] = NEG_BIG;
                if (col + 1 > rowb) s[t][3] = NEG_BIG;
            }
        }

        // ---- online softmax (scores in log2 domain) ----
        float pa = NEG_BIG, pb = NEG_BIG;
#pragma unroll
        for (int t = 0; t < 8; t++) {
            pa = fmaxf(pa, fmaxf(s[t][0], s[t][1]));
            pb = fmaxf(pb, fmaxf(s[t][2], s[t][3]));
        }
        pa = fmaxf(pa, __shfl_xor_sync(0xffffffffu, pa, 1));
        pa = fmaxf(pa, __shfl_xor_sync(0xffffffffu, pa, 2));
        pb = fmaxf(pb, __shfl_xor_sync(0xffffffffu, pb, 1));
        pb = fmaxf(pb, __shfl_xor_sync(0xffffffffu, pb, 2));
        const float nm_a = fmaxf(m_a, pa);
        const float nm_b = fmaxf(m_b, pb);
        const float al_a = ex2f(m_a - nm_a);
        const float al_b = ex2f(m_b - nm_b);
        m_a = nm_a;
        m_b = nm_b;

        float sum_a = 0.f, sum_b = 0.f;
#pragma unroll
        for (int t = 0; t < 8; t++) {
            s[t][0] = ex2f(s[t][0] - nm_a);
            s[t][1] = ex2f(s[t][1] - nm_a);
            s[t][2] = ex2f(s[t][2] - nm_b);
            s[t][3] = ex2f(s[t][3] - nm_b);
            sum_a += s[t][0] + s[t][1];
            sum_b += s[t][2] + s[t][3];
        }
        sum_a += __shfl_xor_sync(0xffffffffu, sum_a, 1);
        sum_a += __shfl_xor_sync(0xffffffffu, sum_a, 2);
        sum_b += __shfl_xor_sync(0xffffffffu, sum_b, 1);
        sum_b += __shfl_xor_sync(0xffffffffu, sum_b, 2);
        l_a = l_a * al_a + sum_a;
        l_b = l_b * al_b + sum_b;
#pragma unroll
        for (int t = 0; t < 8; t++) {
            o[t][0] *= al_a;
            o[t][1] *= al_a;
            o[t][2] *= al_b;
            o[t][3] *= al_b;
        }

        // ---- repack P into A fragments (hi + lo) ----
        uint32_t phi[4][4], plo[4][4];
#pragma unroll
        for (int ks = 0; ks < 4; ks++) {
#pragma unroll
            for (int half = 0; half < 2; half++) {
                const int t = 2 * ks + half;
                const __nv_bfloat16 h0 = __float2bfloat16(s[t][0]);
                const __nv_bfloat16 h1 = __float2bfloat16(s[t][1]);
                const __nv_bfloat16 h2 = __float2bfloat16(s[t][2]);
                const __nv_bfloat16 h3 = __float2bfloat16(s[t][3]);
                phi[ks][2 * half + 0] = pack_bf16(h0, h1);
                phi[ks][2 * half + 1] = pack_bf16(h2, h3);
                plo[ks][2 * half + 0] = pack_bf16(
                    __float2bfloat16(s[t][0] - __bfloat162float(h0)),
                    __float2bfloat16(s[t][1] - __bfloat162float(h1)));
                plo[ks][2 * half + 1] = pack_bf16(
                    __float2bfloat16(s[t][2] - __bfloat162float(h2)),
                    __float2bfloat16(s[t][3] - __bfloat162float(h3)));
            }
        }

        // ---- O += P V (3 split terms) ----
        const int mat = lane >> 3;
        const int vrow7 = (lane & 7) + ((mat >> 1) << 3);
#pragma unroll
        for (int ks = 0; ks < 4; ks++) {
            const int vkc = ks * 2 + (mat & 1);
#pragma unroll
            for (int ntp = 0; ntp < 4; ntp++) {
                uint32_t vh4[4], vl4[4];
                LDSM_X4(vh4[0], vh4[1], vh4[2], vh4[3],
                        addr128(sb + SM_VH(buf), ntp * 16 + vrow7, vkc));
                LDSM_X4(vl4[0], vl4[1], vl4[2], vl4[3],
                        addr128(sb + SM_VL(buf), ntp * 16 + vrow7, vkc));
#pragma unroll
                for (int half = 0; half < 2; half++) {
                    const int nt = ntp * 2 + half;
                    MMA_16816(o[nt], phi[ks], vh4[2 * half], vh4[2 * half + 1]);
                    MMA_16816(o[nt], plo[ks], vh4[2 * half], vh4[2 * half + 1]);
                    MMA_16816(o[nt], phi[ks], vl4[2 * half], vl4[2 * half + 1]);
                }
            }
        }

        __syncthreads();
        buf ^= 1;
    }

    // ---- epilogue: normalize, split to bf16 hi/lo for proj GEMM ----
    const float inv_a = 1.f / l_a;
    const float inv_b = 1.f / l_b;
#pragma unroll
    for (int t = 0; t < 8; t++) {
        const int col = h * DH + t * 8 + c2;
        const int rowa = qti * 128 + wid * 16 + ra;
        {
            const float v0 = o[t][0] * inv_a, v1 = o[t][1] * inv_a;
            const __nv_bfloat16 h0 = __float2bfloat16(v0);
            const __nv_bfloat16 h1 = __float2bfloat16(v1);
            const size_t base = (size_t)(b * SEQ + rowa) * DM + col;
            *(__nv_bfloat162*)(g_ahi + base) = __halves2bfloat162(h0, h1);
            *(__nv_bfloat162*)(g_alo + base) = __halves2bfloat162(
                __float2bfloat16(v0 - __bfloat162float(h0)),
                __float2bfloat16(v1 - __bfloat162float(h1)));
        }
        {
            const float v0 = o[t][2] * inv_b, v1 = o[t][3] * inv_b;
            const __nv_bfloat16 h0 = __float2bfloat16(v0);
            const __nv_bfloat16 h1 = __float2bfloat16(v1);
            const size_t base = (size_t)(b * SEQ + rowa + 8) * DM + col;
            *(__nv_bfloat162*)(g_ahi + base) = __halves2bfloat162(h0, h1);
            *(__nv_bfloat162*)(g_alo + base) = __halves2bfloat162(
                __float2bfloat16(v0 - __bfloat162float(h0)),
                __float2bfloat16(v1 - __bfloat162float(h1)));
        }
    }
}

// ---------------------------------------------------------------------------
extern "C" void kernel_launch(void* const* d_in, const int* in_sizes, int n_in,
                              void* d_out, int out_size)
{
    const float* input = (const float*)d_in[0];
    const float* W_qkv = (const float*)d_in[1];
    const float* b_qkv = (const float*)d_in[2];
    const float* W_out = (const float*)d_in[3];
    const float* b_out = (const float*)d_in[4];
    float* out = (float*)d_out;

    cudaFuncSetAttribute(attn_mma_kernel,
                         cudaFuncAttributeMaxDynamicSharedMemorySize, ATTN_SMEM_BYTES);

    __nv_bfloat16 *xhi, *xlo, *wqh, *wql, *woh, *wol, *ahi, *alo;
    float* qkv;
    cudaGetSymbolAddress((void**)&xhi, g_xhi);
    cudaGetSymbolAddress((void**)&xlo, g_xlo);
    cudaGetSymbolAddress((void**)&wqh, g_wqkvT_hi);
    cudaGetSymbolAddress((void**)&wql, g_wqkvT_lo);
    cudaGetSymbolAddress((void**)&woh, g_woutT_hi);
    cudaGetSymbolAddress((void**)&wol, g_woutT_lo);
    cudaGetSymbolAddress((void**)&ahi, g_ahi);
    cudaGetSymbolAddress((void**)&alo, g_alo);
    cudaGetSymbolAddress((void**)&qkv, g_qkv);

    split_input_kernel<<<(MROWS * DM / 4) / 256, 256>>>(
        (const float4*)input, (__nv_bfloat162*)xhi, (__nv_bfloat162*)xlo);
    transpose_split_kernel<<<dim3(TD / 32, DM / 32), 256>>>(W_qkv, TD, wqh, wql);
    transpose_split_kernel<<<dim3(DM / 32, DM / 32), 256>>>(W_out, DM, woh, wol);

    gemm_mma_kernel<<<dim3(MROWS / 128, TD / 128), 256>>>(
        xhi, xlo, wqh, wql, b_qkv, qkv, TD);

    prep_kernel<<<dim3(SEQ / 64, NBH), 256>>>();

    attn_mma_kernel<<<dim3(SEQ / 128, NBH), 256, ATTN_SMEM_BYTES>>>();

    gemm_mma_kernel<<<dim3(MROWS / 128, DM / 128), 256>>>(
        ahi, alo, woh, wol, b_out, out, DM);
}

// round 7
// speedup vs baseline: 2.8005x; 1.0003x over previous
#include <cuda_runtime.h>
#include <cuda_bf16.h>
#include <cstdint>

#define BSZ 4
#define SEQ 2048
#define NH 16
#define DH 64
#define DM 1024
#define TD 3072
#define MROWS (BSZ * SEQ)
#define NBH (BSZ * NH)

#define NEG_BIG (-1e30f)
#define SCALE_L2E 0.18033688011112042f   // 0.125 * log2(e)

// ---------------------------------------------------------------------------
// Scratch (__device__ globals; no allocation allowed)
// ---------------------------------------------------------------------------
__device__ float g_qkv[(size_t)MROWS * TD];                 // fp32 qkv (bias added)
__device__ __nv_bfloat16 g_xhi[(size_t)MROWS * DM];
__device__ __nv_bfloat16 g_xlo[(size_t)MROWS * DM];
__device__ __nv_bfloat16 g_wqkvT_hi[(size_t)TD * DM];
__device__ __nv_bfloat16 g_wqkvT_lo[(size_t)TD * DM];
__device__ __nv_bfloat16 g_woutT_hi[(size_t)DM * DM];
__device__ __nv_bfloat16 g_woutT_lo[(size_t)DM * DM];
__device__ __nv_bfloat16 g_ahi[(size_t)MROWS * DM];
__device__ __nv_bfloat16 g_alo[(size_t)MROWS * DM];
// per-head bf16 splits for attention (bh-major)
__device__ __nv_bfloat16 g_qh[(size_t)NBH * SEQ * DH];      // [bh][s][d], pre-scaled
__device__ __nv_bfloat16 g_ql[(size_t)NBH * SEQ * DH];
__device__ __nv_bfloat16 g_kh[(size_t)NBH * SEQ * DH];      // [bh][s][d]
__device__ __nv_bfloat16 g_kl[(size_t)NBH * SEQ * DH];
__device__ __nv_bfloat16 g_vth[(size_t)NBH * DH * SEQ];     // [bh][d][s] (transposed)
__device__ __nv_bfloat16 g_vtl[(size_t)NBH * DH * SEQ];

// ---------------------------------------------------------------------------
// PTX helpers (valid for target sm_100)
// ---------------------------------------------------------------------------
__device__ __forceinline__ uint32_t smem_u32(const void* p) {
    uint32_t a;
    asm("{ .reg .u64 t; cvta.to.shared.u64 t, %1; cvt.u32.u64 %0, t; }" : "=r"(a) : "l"(p));
    return a;
}

#define CP_ASYNC16(dst, src) \
    asm volatile("cp.async.cg.shared.global [%0], [%1], 16;" :: "r"(dst), "l"(src))
#define CP_COMMIT() asm volatile("cp.async.commit_group;" ::: "memory")
#define CP_WAIT(n)  asm volatile("cp.async.wait_group %0;" :: "n"(n) : "memory")

#define LDSM_X4(r0, r1, r2, r3, addr) \
    asm volatile("ldmatrix.sync.aligned.m8n8.x4.shared.b16 {%0,%1,%2,%3}, [%4];" \
                 : "=r"(r0), "=r"(r1), "=r"(r2), "=r"(r3) : "r"(addr))

#define MMA_16816(d, a, b0, b1) \
    asm volatile("mma.sync.aligned.m16n8k16.row.col.f32.bf16.bf16.f32 " \
                 "{%0,%1,%2,%3}, {%4,%5,%6,%7}, {%8,%9}, {%0,%1,%2,%3};" \
                 : "+f"((d)[0]), "+f"((d)[1]), "+f"((d)[2]), "+f"((d)[3]) \
                 : "r"((a)[0]), "r"((a)[1]), "r"((a)[2]), "r"((a)[3]), \
                   "r"(b0), "r"(b1))

__device__ __forceinline__ float ex2f(float x) {
    float y;
    asm("ex2.approx.ftz.f32 %0, %1;" : "=f"(y) : "f"(x));
    return y;
}

__device__ __forceinline__ uint32_t pack_bf16(__nv_bfloat16 lo, __nv_bfloat16 hi) {
    __nv_bfloat162 t = __halves2bfloat162(lo, hi);
    return *(uint32_t*)&t;
}

// 128B-per-row tile (64 bf16 per row): XOR-swizzled 16B chunks within line
__device__ __forceinline__ uint32_t addr128(uint32_t base, int row, int kc) {
    return base + (uint32_t)(row * 128 + ((kc ^ (row & 7)) * 16));
}

// ---------------------------------------------------------------------------
// Conversion kernels
// ---------------------------------------------------------------------------
__global__ void __launch_bounds__(256) split_input_kernel(
    const float4* __restrict__ in, __nv_bfloat162* __restrict__ hi,
    __nv_bfloat162* __restrict__ lo)
{
    const int i = blockIdx.x * 256 + threadIdx.x;
    const float4 v = in[i];
    const __nv_bfloat16 h0 = __float2bfloat16(v.x);
    const __nv_bfloat16 h1 = __float2bfloat16(v.y);
    const __nv_bfloat16 h2 = __float2bfloat16(v.z);
    const __nv_bfloat16 h3 = __float2bfloat16(v.w);
    hi[i * 2 + 0] = __halves2bfloat162(h0, h1);
    hi[i * 2 + 1] = __halves2bfloat162(h2, h3);
    lo[i * 2 + 0] = __halves2bfloat162(__float2bfloat16(v.x - __bfloat162float(h0)),
                                       __float2bfloat16(v.y - __bfloat162float(h1)));
    lo[i * 2 + 1] = __halves2bfloat162(__float2bfloat16(v.z - __bfloat162float(h2)),
                                       __float2bfloat16(v.w - __bfloat162float(h3)));
}

__global__ void __launch_bounds__(256) transpose_split_kernel(
    const float* __restrict__ W, int N,
    __nv_bfloat16* __restrict__ Thi, __nv_bfloat16* __restrict__ Tlo)
{
    __shared__ float t[32][33];
    const int n0 = blockIdx.x * 32;
    const int k0 = blockIdx.y * 32;
    const int tx = threadIdx.x & 31;
    const int ty = threadIdx.x >> 5;
#pragma unroll
    for (int i = 0; i < 32; i += 8)
        t[ty + i][tx] = W[(size_t)(k0 + ty + i) * N + n0 + tx];
    __syncthreads();
#pragma unroll
    for (int i = 0; i < 32; i += 8) {
        const float v = t[tx][ty + i];
        const __nv_bfloat16 h = __float2bfloat16(v);
        const size_t o = (size_t)(n0 + ty + i) * DM + k0 + tx;
        Thi[o] = h;
        Tlo[o] = __float2bfloat16(v - __bfloat162float(h));
    }
}

// prep: split Q(scaled)/K into bf16 hi/lo [bh][s][d]; V transposed [bh][d][s]
__global__ void __launch_bounds__(256) prep_kernel()
{
    __shared__ float vs[64][65];
    const int st = blockIdx.x;
    const int bh = (int)blockIdx.y;
    const int b = bh >> 4;
    const int h = bh & 15;
    const int tid = (int)threadIdx.x;

#pragma unroll
    for (int i = 0; i < 16; i++) {
        const int idx = tid + i * 256;
        const int s = idx >> 6;
        const int d = idx & 63;
        const float* src = g_qkv + (size_t)(b * SEQ + st * 64 + s) * TD + h * DH + d;
        const float q = src[0] * SCALE_L2E;
        const float k = src[DM];
        vs[s][d] = src[2 * DM];
        const size_t o = ((size_t)bh * SEQ + st * 64 + s) * DH + d;
        const __nv_bfloat16 qh = __float2bfloat16(q);
        const __nv_bfloat16 kh = __float2bfloat16(k);
        g_qh[o] = qh;
        g_ql[o] = __float2bfloat16(q - __bfloat162float(qh));
        g_kh[o] = kh;
        g_kl[o] = __float2bfloat16(k - __bfloat162float(kh));
    }
    __syncthreads();
#pragma unroll
    for (int i = 0; i < 16; i++) {
        const int idx = tid + i * 256;
        const int d = idx >> 6;
        const int s = idx & 63;
        const float v = vs[s][d];
        const __nv_bfloat16 vh = __float2bfloat16(v);
        const size_t o = ((size_t)bh * DH + d) * SEQ + st * 64 + s;
        g_vth[o] = vh;
        g_vtl[o] = __float2bfloat16(v - __bfloat162float(vh));
    }
}

// ---------------------------------------------------------------------------
// mma.sync GEMM v2: C = [Ahi|Ahi|Alo](K'=3072) x [Bhi;Blo;Bhi]^T + bias
// CTA tile 128x256, BK=64, 8 warps (2m x 4n), warp tile 64x64.
// smem: A 16KB x2 + B 32KB x2 = 96KB dynamic, double-buffered cp.async.
// ---------------------------------------------------------------------------
#define NCHUNK 48
#define GA(b) ((b) * 16384)             // A buffers at 0, 16KB
#define GB(b) (32768 + (b) * 32768)     // B buffers at 32KB, 64KB
#define GEMM_SMEM_BYTES 98304

__global__ void __launch_bounds__(256, 1) gemm_mma_kernel(
    const __nv_bfloat16* __restrict__ Ahi, const __nv_bfloat16* __restrict__ Alo,
    const __nv_bfloat16* __restrict__ Bhi, const __nv_bfloat16* __restrict__ Blo,
    const float* __restrict__ bias, float* __restrict__ C, int Ntot)
{
    extern __shared__ uint8_t gsm[];
    const uint32_t sbase = smem_u32(gsm);

    const int tid = (int)threadIdx.x;
    const int wid = tid >> 5;
    const int lane = tid & 31;
    const int wm = wid & 1;          // 64-row half
    const int wn = wid >> 1;         // 64-col slice

    const int m0g = blockIdx.x * 128;
    const int n0g = blockIdx.y * 256;

    float acc[4][8][4];
#pragma unroll
    for (int mt = 0; mt < 4; mt++)
#pragma unroll
        for (int nt = 0; nt < 8; nt++)
#pragma unroll
            for (int j = 0; j < 4; j++) acc[mt][nt][j] = 0.f;

    // stage chunk: A 128 rows, B 256 rows, 64 k each (8 x 16B chunks per row)
    auto stage = [&](const __nv_bfloat16* __restrict__ As,
                     const __nv_bfloat16* __restrict__ Bs, int k0, int bb) {
#pragma unroll
        for (int it = 0; it < 4; ++it) {
            const int idx = tid + it * 256;      // 0..1023
            const int r = idx >> 3;
            const int kc = idx & 7;
            CP_ASYNC16(addr128(sbase + GA(bb), r, kc),
                       As + (size_t)(m0g + r) * DM + k0 + kc * 8);
        }
#pragma unroll
        for (int it = 0; it < 8; ++it) {
            const int idx = tid + it * 256;      // 0..2047
            const int r = idx >> 3;
            const int kc = idx & 7;
            CP_ASYNC16(addr128(sbase + GB(bb), r, kc),
                       Bs + (size_t)(n0g + r) * DM + k0 + kc * 8);
        }
    };

    // chunk c: g=c>>4 (0,1,2), k0=(c&15)*64. A: g==2 -> Alo else Ahi.
    //                                        B: g==1 -> Blo else Bhi.
    stage(Ahi, Bhi, 0, 0);
    CP_COMMIT();

    const int mat = lane >> 3;
    const int arow7 = (lane & 7) + ((mat & 1) << 3);
    const int brow7 = (lane & 7) + ((mat >> 1) << 3);

    int buf = 0;
    for (int c = 0; c < NCHUNK; ++c) {
        if (c + 1 < NCHUNK) {
            const int cn = c + 1;
            const int g = cn >> 4;
            const int k0 = (cn & 15) * 64;
            stage((g == 2) ? Alo : Ahi, (g == 1) ? Blo : Bhi, k0, buf ^ 1);
            CP_COMMIT();
            CP_WAIT(1);
        } else {
            CP_WAIT(0);
        }
        __syncthreads();

        const uint32_t abase = sbase + GA(buf);
        const uint32_t bbase = sbase + GB(buf);

#pragma unroll
        for (int ks = 0; ks < 4; ++ks) {
            uint32_t af[4][4];
#pragma unroll
            for (int mt = 0; mt < 4; mt++) {
                const int row = wm * 64 + mt * 16 + arow7;
                const int kc = ks * 2 + (mat >> 1);
                LDSM_X4(af[mt][0], af[mt][1], af[mt][2], af[mt][3],
                        addr128(abase, row, kc));
            }
            uint32_t bf[4][4];
#pragma unroll
            for (int ntp = 0; ntp < 4; ntp++) {
                const int row = wn * 64 + ntp * 16 + brow7;
                const int kc = ks * 2 + (mat & 1);
                LDSM_X4(bf[ntp][0], bf[ntp][1], bf[ntp][2], bf[ntp][3],
                        addr128(bbase, row, kc));
            }
#pragma unroll
            for (int mt = 0; mt < 4; mt++)
#pragma unroll
                for (int nt = 0; nt < 8; nt++)
                    MMA_16816(acc[mt][nt], af[mt],
                              bf[nt >> 1][2 * (nt & 1)], bf[nt >> 1][2 * (nt & 1) + 1]);
        }
        __syncthreads();
        buf ^= 1;
    }

    // Epilogue: add bias, store fp32
    const int qrow = lane >> 2;
    const int qcol = (lane & 3) << 1;
    float2 bv[8];
#pragma unroll
    for (int nt = 0; nt < 8; nt++) {
        const int n = n0g + wn * 64 + nt * 8 + qcol;
        bv[nt] = make_float2(bias[n], bias[n + 1]);
    }
#pragma unroll
    for (int mt = 0; mt < 4; mt++) {
        const int r0 = m0g + wm * 64 + mt * 16 + qrow;
#pragma unroll
        for (int nt = 0; nt < 8; nt++) {
            const int n = n0g + wn * 64 + nt * 8 + qcol;
            *(float2*)(C + (size_t)r0 * Ntot + n) =
                make_float2(acc[mt][nt][0] + bv[nt].x, acc[mt][nt][1] + bv[nt].y);
            *(float2*)(C + (size_t)(r0 + 8) * Ntot + n) =
                make_float2(acc[mt][nt][2] + bv[nt].x, acc[mt][nt][3] + bv[nt].y);
        }
    }
}

// ---------------------------------------------------------------------------
// HMMA flash attention (unchanged from R5). Block = 128 q-rows x one (b,h).
// ---------------------------------------------------------------------------
#define SM_QH 0
#define SM_QL 16384
#define SM_KH(b) (32768 + (b) * 16384)
#define SM_KL(b) (40960 + (b) * 16384)
#define SM_VH(b) (65536 + (b) * 16384)
#define SM_VL(b) (73728 + (b) * 16384)
#define ATTN_SMEM_BYTES 98304

__global__ void __launch_bounds__(256) attn_mma_kernel()
{
    extern __shared__ uint8_t dsm[];
    const uint32_t sb = smem_u32(dsm);
    const int tid = (int)threadIdx.x;
    const int wid = tid >> 5;
    const int lane = tid & 31;
    const int qti = 15 - (int)blockIdx.x;       // heavy tiles first
    const int bh = (int)blockIdx.y;
    const int b = bh >> 4;
    const int h = bh & 15;

    const size_t qkbase = (size_t)bh * SEQ * DH;
    const size_t vbase = (size_t)bh * DH * SEQ;

#pragma unroll
    for (int i = 0; i < 4; i++) {
        const int idx = tid + i * 256;
        const int r = idx >> 3;
        const int kc = idx & 7;
        CP_ASYNC16(addr128(sb + SM_QH, r, kc),
                   g_qh + qkbase + (size_t)(qti * 128 + r) * DH + kc * 8);
        CP_ASYNC16(addr128(sb + SM_QL, r, kc),
                   g_ql + qkbase + (size_t)(qti * 128 + r) * DH + kc * 8);
    }

    const int nkt = 2 * qti + 2;

    auto stage_kv = [&](int kt, int bb) {
#pragma unroll
        for (int i = 0; i < 2; i++) {
            const int idx = tid + i * 256;
            const int r = idx >> 3;
            const int kc = idx & 7;
            const size_t ko = qkbase + (size_t)(kt * 64 + r) * DH + kc * 8;
            CP_ASYNC16(addr128(sb + SM_KH(bb), r, kc), g_kh + ko);
            CP_ASYNC16(addr128(sb + SM_KL(bb), r, kc), g_kl + ko);
            const size_t vo = vbase + (size_t)r * SEQ + kt * 64 + kc * 8;
            CP_ASYNC16(addr128(sb + SM_VH(bb), r, kc), g_vth + vo);
            CP_ASYNC16(addr128(sb + SM_VL(bb), r, kc), g_vtl + vo);
        }
    };

    stage_kv(0, 0);
    CP_COMMIT();

    float o[8][4];
#pragma unroll
    for (int t = 0; t < 8; t++)
#pragma unroll
        for (int j = 0; j < 4; j++) o[t][j] = 0.f;
    float m_a = NEG_BIG, m_b = NEG_BIG, l_a = 0.f, l_b = 0.f;

    const int qrow_base = qti * 128 + wid * 16;
    const int ra = lane >> 2;
    const int c2 = (lane & 3) << 1;

    int buf = 0;
    for (int kt = 0; kt < nkt; kt++) {
        if (kt + 1 < nkt) {
            stage_kv(kt + 1, buf ^ 1);
            CP_COMMIT();
            CP_WAIT(1);
        } else {
            CP_WAIT(0);
        }
        __syncthreads();

        // ---- S = Q K^T (3 split terms) ----
        float s[8][4];
#pragma unroll
        for (int t = 0; t < 8; t++)
#pragma unroll
            for (int j = 0; j < 4; j++) s[t][j] = 0.f;

#pragma unroll
        for (int ks = 0; ks < 4; ks++) {
            const int mat = lane >> 3;
            const int arow = wid * 16 + (lane & 7) + ((mat & 1) << 3);
            const int akc = ks * 2 + (mat >> 1);
            uint32_t aqh[4], aql[4];
            LDSM_X4(aqh[0], aqh[1], aqh[2], aqh[3], addr128(sb + SM_QH, arow, akc));
            LDSM_X4(aql[0], aql[1], aql[2], aql[3], addr128(sb + SM_QL, arow, akc));

            const int brow7 = (lane & 7) + ((mat >> 1) << 3);
            const int bkc = ks * 2 + (mat & 1);
#pragma unroll
            for (int ntp = 0; ntp < 4; ntp++) {
                uint32_t bh4[4], bl4[4];
                LDSM_X4(bh4[0], bh4[1], bh4[2], bh4[3],
                        addr128(sb + SM_KH(buf), ntp * 16 + brow7, bkc));
                LDSM_X4(bl4[0], bl4[1], bl4[2], bl4[3],
                        addr128(sb + SM_KL(buf), ntp * 16 + brow7, bkc));
#pragma unroll
                for (int half = 0; half < 2; half++) {
                    const int nt = ntp * 2 + half;
                    MMA_16816(s[nt], aqh, bh4[2 * half], bh4[2 * half + 1]);
                    MMA_16816(s[nt], aql, bh4[2 * half], bh4[2 * half + 1]);
                    MMA_16816(s[nt], aqh, bl4[2 * half], bl4[2 * half + 1]);
                }
            }
        }

        // ---- causal mask ----
        if (kt * 64 + 63 > qrow_base) {
#pragma unroll
            for (int t = 0; t < 8; t++) {
                const int col = kt * 64 + t * 8 + c2;
                const int rowa = qrow_base + ra;
                const int rowb = rowa + 8;
                if (col > rowa)     s[t][0] = NEG_BIG;
                if (col + 1 > rowa) s[t][1] = NEG_BIG;
                if (col > rowb)     s[t][2] = NEG_BIG;
                if (col + 1 > rowb) s[t][3] = NEG_BIG;
            }
        }

        // ---- online softmax (log2 domain) ----
        float pa = NEG_BIG, pb = NEG_BIG;
#pragma unroll
        for (int t = 0; t < 8; t++) {
            pa = fmaxf(pa, fmaxf(s[t][0], s[t][1]));
            pb = fmaxf(pb, fmaxf(s[t][2], s[t][3]));
        }
        pa = fmaxf(pa, __shfl_xor_sync(0xffffffffu, pa, 1));
        pa = fmaxf(pa, __shfl_xor_sync(0xffffffffu, pa, 2));
        pb = fmaxf(pb, __shfl_xor_sync(0xffffffffu, pb, 1));
        pb = fmaxf(pb, __shfl_xor_sync(0xffffffffu, pb, 2));
        const float nm_a = fmaxf(m_a, pa);
        const float nm_b = fmaxf(m_b, pb);
        const float al_a = ex2f(m_a - nm_a);
        const float al_b = ex2f(m_b - nm_b);
        m_a = nm_a;
        m_b = nm_b;

        float sum_a = 0.f, sum_b = 0.f;
#pragma unroll
        for (int t = 0; t < 8; t++) {
            s[t][0] = ex2f(s[t][0] - nm_a);
            s[t][1] = ex2f(s[t][1] - nm_a);
            s[t][2] = ex2f(s[t][2] - nm_b);
            s[t][3] = ex2f(s[t][3] - nm_b);
            sum_a += s[t][0] + s[t][1];
            sum_b += s[t][2] + s[t][3];
        }
        sum_a += __shfl_xor_sync(0xffffffffu, sum_a, 1);
        sum_a += __shfl_xor_sync(0xffffffffu, sum_a, 2);
        sum_b += __shfl_xor_sync(0xffffffffu, sum_b, 1);
        sum_b += __shfl_xor_sync(0xffffffffu, sum_b, 2);
        l_a = l_a * al_a + sum_a;
        l_b = l_b * al_b + sum_b;
#pragma unroll
        for (int t = 0; t < 8; t++) {
            o[t][0] *= al_a;
            o[t][1] *= al_a;
            o[t][2] *= al_b;
            o[t][3] *= al_b;
        }

        // ---- repack P into A fragments (hi + lo) ----
        uint32_t phi[4][4], plo[4][4];
#pragma unroll
        for (int ks = 0; ks < 4; ks++) {
#pragma unroll
            for (int half = 0; half < 2; half++) {
                const int t = 2 * ks + half;
                const __nv_bfloat16 h0 = __float2bfloat16(s[t][0]);
                const __nv_bfloat16 h1 = __float2bfloat16(s[t][1]);
                const __nv_bfloat16 h2 = __float2bfloat16(s[t][2]);
                const __nv_bfloat16 h3 = __float2bfloat16(s[t][3]);
                phi[ks][2 * half + 0] = pack_bf16(h0, h1);
                phi[ks][2 * half + 1] = pack_bf16(h2, h3);
                plo[ks][2 * half + 0] = pack_bf16(
                    __float2bfloat16(s[t][0] - __bfloat162float(h0)),
                    __float2bfloat16(s[t][1] - __bfloat162float(h1)));
                plo[ks][2 * half + 1] = pack_bf16(
                    __float2bfloat16(s[t][2] - __bfloat162float(h2)),
                    __float2bfloat16(s[t][3] - __bfloat162float(h3)));
            }
        }

        // ---- O += P V (3 split terms) ----
        const int mat = lane >> 3;
        const int vrow7 = (lane & 7) + ((mat >> 1) << 3);
#pragma unroll
        for (int ks = 0; ks < 4; ks++) {
            const int vkc = ks * 2 + (mat & 1);
#pragma unroll
            for (int ntp = 0; ntp < 4; ntp++) {
                uint32_t vh4[4], vl4[4];
                LDSM_X4(vh4[0], vh4[1], vh4[2], vh4[3],
                        addr128(sb + SM_VH(buf), ntp * 16 + vrow7, vkc));
                LDSM_X4(vl4[0], vl4[1], vl4[2], vl4[3],
                        addr128(sb + SM_VL(buf), ntp * 16 + vrow7, vkc));
#pragma unroll
                for (int half = 0; half < 2; half++) {
                    const int nt = ntp * 2 + half;
                    MMA_16816(o[nt], phi[ks], vh4[2 * half], vh4[2 * half + 1]);
                    MMA_16816(o[nt], plo[ks], vh4[2 * half], vh4[2 * half + 1]);
                    MMA_16816(o[nt], phi[ks], vl4[2 * half], vl4[2 * half + 1]);
                }
            }
        }

        __syncthreads();
        buf ^= 1;
    }

    // ---- epilogue: normalize, split to bf16 hi/lo for proj GEMM ----
    const float inv_a = 1.f / l_a;
    const float inv_b = 1.f / l_b;
#pragma unroll
    for (int t = 0; t < 8; t++) {
        const int col = h * DH + t * 8 + c2;
        const int rowa = qti * 128 + wid * 16 + ra;
        {
            const float v0 = o[t][0] * inv_a, v1 = o[t][1] * inv_a;
            const __nv_bfloat16 h0 = __float2bfloat16(v0);
            const __nv_bfloat16 h1 = __float2bfloat16(v1);
            const size_t base = (size_t)(b * SEQ + rowa) * DM + col;
            *(__nv_bfloat162*)(g_ahi + base) = __halves2bfloat162(h0, h1);
            *(__nv_bfloat162*)(g_alo + base) = __halves2bfloat162(
                __float2bfloat16(v0 - __bfloat162float(h0)),
                __float2bfloat16(v1 - __bfloat162float(h1)));
        }
        {
            const float v0 = o[t][2] * inv_b, v1 = o[t][3] * inv_b;
            const __nv_bfloat16 h0 = __float2bfloat16(v0);
            const __nv_bfloat16 h1 = __float2bfloat16(v1);
            const size_t base = (size_t)(b * SEQ + rowa + 8) * DM + col;
            *(__nv_bfloat162*)(g_ahi + base) = __halves2bfloat162(h0, h1);
            *(__nv_bfloat162*)(g_alo + base) = __halves2bfloat162(
                __float2bfloat16(v0 - __bfloat162float(h0)),
                __float2bfloat16(v1 - __bfloat162float(h1)));
        }
    }
}

// ---------------------------------------------------------------------------
extern "C" void kernel_launch(void* const* d_in, const int* in_sizes, int n_in,
                              void* d_out, int out_size)
{
    const float* input = (const float*)d_in[0];
    const float* W_qkv = (const float*)d_in[1];
    const float* b_qkv = (const float*)d_in[2];
    const float* W_out = (const float*)d_in[3];
    const float* b_out = (const float*)d_in[4];
    float* out = (float*)d_out;

    cudaFuncSetAttribute(attn_mma_kernel,
                         cudaFuncAttributeMaxDynamicSharedMemorySize, ATTN_SMEM_BYTES);
    cudaFuncSetAttribute(gemm_mma_kernel,
                         cudaFuncAttributeMaxDynamicSharedMemorySize, GEMM_SMEM_BYTES);

    __nv_bfloat16 *xhi, *xlo, *wqh, *wql, *woh, *wol, *ahi, *alo;
    float* qkv;
    cudaGetSymbolAddress((void**)&xhi, g_xhi);
    cudaGetSymbolAddress((void**)&xlo, g_xlo);
    cudaGetSymbolAddress((void**)&wqh, g_wqkvT_hi);
    cudaGetSymbolAddress((void**)&wql, g_wqkvT_lo);
    cudaGetSymbolAddress((void**)&woh, g_woutT_hi);
    cudaGetSymbolAddress((void**)&wol, g_woutT_lo);
    cudaGetSymbolAddress((void**)&ahi, g_ahi);
    cudaGetSymbolAddress((void**)&alo, g_alo);
    cudaGetSymbolAddress((void**)&qkv, g_qkv);

    split_input_kernel<<<(MROWS * DM / 4) / 256, 256>>>(
        (const float4*)input, (__nv_bfloat162*)xhi, (__nv_bfloat162*)xlo);
    transpose_split_kernel<<<dim3(TD / 32, DM / 32), 256>>>(W_qkv, TD, wqh, wql);
    transpose_split_kernel<<<dim3(DM / 32, DM / 32), 256>>>(W_out, DM, woh, wol);

    gemm_mma_kernel<<<dim3(MROWS / 128, TD / 256), 256, GEMM_SMEM_BYTES>>>(
        xhi, xlo, wqh, wql, b_qkv, qkv, TD);

    prep_kernel<<<dim3(SEQ / 64, NBH), 256>>>();

    attn_mma_kernel<<<dim3(SEQ / 128, NBH), 256, ATTN_SMEM_BYTES>>>();

    gemm_mma_kernel<<<dim3(MROWS / 128, DM / 256), 256, GEMM_SMEM_BYTES>>>(
        ahi, alo, woh, wol, b_out, out, DM);
}

// round 8
// speedup vs baseline: 2.8571x; 1.0202x over previous
#include <cuda_runtime.h>
#include <cuda_bf16.h>
#include <cstdint>

#define BSZ 4
#define SEQ 2048
#define NH 16
#define DH 64
#define DM 1024
#define TD 3072
#define MROWS (BSZ * SEQ)
#define NBH (BSZ * NH)

#define NEG_BIG (-1e30f)
#define SCALE_L2E 0.18033688011112042f   // 0.125 * log2(e)

// ---------------------------------------------------------------------------
// Scratch (__device__ globals; no allocation allowed)
// ---------------------------------------------------------------------------
__device__ float g_qkv[(size_t)MROWS * TD];                 // fp32 qkv (bias added)
__device__ __nv_bfloat16 g_xhi[(size_t)MROWS * DM];
__device__ __nv_bfloat16 g_xlo[(size_t)MROWS * DM];
__device__ __nv_bfloat16 g_wqkvT_hi[(size_t)TD * DM];
__device__ __nv_bfloat16 g_wqkvT_lo[(size_t)TD * DM];
__device__ __nv_bfloat16 g_woutT_hi[(size_t)DM * DM];
__device__ __nv_bfloat16 g_woutT_lo[(size_t)DM * DM];
__device__ __nv_bfloat16 g_ahi[(size_t)MROWS * DM];
__device__ __nv_bfloat16 g_alo[(size_t)MROWS * DM];
// per-head bf16 splits for attention (bh-major)
__device__ __nv_bfloat16 g_qh[(size_t)NBH * SEQ * DH];      // [bh][s][d], pre-scaled
__device__ __nv_bfloat16 g_ql[(size_t)NBH * SEQ * DH];
__device__ __nv_bfloat16 g_kh[(size_t)NBH * SEQ * DH];      // [bh][s][d]
__device__ __nv_bfloat16 g_kl[(size_t)NBH * SEQ * DH];
__device__ __nv_bfloat16 g_vth[(size_t)NBH * DH * SEQ];     // [bh][d][s] (transposed)
__device__ __nv_bfloat16 g_vtl[(size_t)NBH * DH * SEQ];

// ---------------------------------------------------------------------------
// PTX helpers (valid for target sm_100)
// ---------------------------------------------------------------------------
__device__ __forceinline__ uint32_t smem_u32(const void* p) {
    uint32_t a;
    asm("{ .reg .u64 t; cvta.to.shared.u64 t, %1; cvt.u32.u64 %0, t; }" : "=r"(a) : "l"(p));
    return a;
}

#define CP_ASYNC16(dst, src) \
    asm volatile("cp.async.cg.shared.global [%0], [%1], 16;" :: "r"(dst), "l"(src))
#define CP_COMMIT() asm volatile("cp.async.commit_group;" ::: "memory")
#define CP_WAIT(n)  asm volatile("cp.async.wait_group %0;" :: "n"(n) : "memory")

#define LDSM_X4(r0, r1, r2, r3, addr) \
    asm volatile("ldmatrix.sync.aligned.m8n8.x4.shared.b16 {%0,%1,%2,%3}, [%4];" \
                 : "=r"(r0), "=r"(r1), "=r"(r2), "=r"(r3) : "r"(addr))

#define MMA_16816(d, a, b0, b1) \
    asm volatile("mma.sync.aligned.m16n8k16.row.col.f32.bf16.bf16.f32 " \
                 "{%0,%1,%2,%3}, {%4,%5,%6,%7}, {%8,%9}, {%0,%1,%2,%3};" \
                 : "+f"((d)[0]), "+f"((d)[1]), "+f"((d)[2]), "+f"((d)[3]) \
                 : "r"((a)[0]), "r"((a)[1]), "r"((a)[2]), "r"((a)[3]), \
                   "r"(b0), "r"(b1))

__device__ __forceinline__ float ex2f(float x) {
    float y;
    asm("ex2.approx.ftz.f32 %0, %1;" : "=f"(y) : "f"(x));
    return y;
}

__device__ __forceinline__ uint32_t pack_bf16(__nv_bfloat16 lo, __nv_bfloat16 hi) {
    __nv_bfloat162 t = __halves2bfloat162(lo, hi);
    return *(uint32_t*)&t;
}

// 128B-per-row tile (64 bf16 per row): XOR-swizzled 16B chunks within line
__device__ __forceinline__ uint32_t addr128(uint32_t base, int row, int kc) {
    return base + (uint32_t)(row * 128 + ((kc ^ (row & 7)) * 16));
}

// ---------------------------------------------------------------------------
// Conversion kernels
// ---------------------------------------------------------------------------
__global__ void __launch_bounds__(256) split_input_kernel(
    const float4* __restrict__ in, __nv_bfloat162* __restrict__ hi,
    __nv_bfloat162* __restrict__ lo)
{
    const int i = blockIdx.x * 256 + threadIdx.x;
    const float4 v = in[i];
    const __nv_bfloat16 h0 = __float2bfloat16(v.x);
    const __nv_bfloat16 h1 = __float2bfloat16(v.y);
    const __nv_bfloat16 h2 = __float2bfloat16(v.z);
    const __nv_bfloat16 h3 = __float2bfloat16(v.w);
    hi[i * 2 + 0] = __halves2bfloat162(h0, h1);
    hi[i * 2 + 1] = __halves2bfloat162(h2, h3);
    lo[i * 2 + 0] = __halves2bfloat162(__float2bfloat16(v.x - __bfloat162float(h0)),
                                       __float2bfloat16(v.y - __bfloat162float(h1)));
    lo[i * 2 + 1] = __halves2bfloat162(__float2bfloat16(v.z - __bfloat162float(h2)),
                                       __float2bfloat16(v.w - __bfloat162float(h3)));
}

__global__ void __launch_bounds__(256) transpose_split_kernel(
    const float* __restrict__ W, int N,
    __nv_bfloat16* __restrict__ Thi, __nv_bfloat16* __restrict__ Tlo)
{
    __shared__ float t[32][33];
    const int n0 = blockIdx.x * 32;
    const int k0 = blockIdx.y * 32;
    const int tx = threadIdx.x & 31;
    const int ty = threadIdx.x >> 5;
#pragma unroll
    for (int i = 0; i < 32; i += 8)
        t[ty + i][tx] = W[(size_t)(k0 + ty + i) * N + n0 + tx];
    __syncthreads();
#pragma unroll
    for (int i = 0; i < 32; i += 8) {
        const float v = t[tx][ty + i];
        const __nv_bfloat16 h = __float2bfloat16(v);
        const size_t o = (size_t)(n0 + ty + i) * DM + k0 + tx;
        Thi[o] = h;
        Tlo[o] = __float2bfloat16(v - __bfloat162float(h));
    }
}

// prep: split Q(scaled)/K into bf16 hi/lo [bh][s][d]; V transposed [bh][d][s]
__global__ void __launch_bounds__(256) prep_kernel()
{
    __shared__ float vs[64][65];
    const int st = blockIdx.x;
    const int bh = (int)blockIdx.y;
    const int b = bh >> 4;
    const int h = bh & 15;
    const int tid = (int)threadIdx.x;

#pragma unroll
    for (int i = 0; i < 16; i++) {
        const int idx = tid + i * 256;
        const int s = idx >> 6;
        const int d = idx & 63;
        const float* src = g_qkv + (size_t)(b * SEQ + st * 64 + s) * TD + h * DH + d;
        const float q = src[0] * SCALE_L2E;
        const float k = src[DM];
        vs[s][d] = src[2 * DM];
        const size_t o = ((size_t)bh * SEQ + st * 64 + s) * DH + d;
        const __nv_bfloat16 qh = __float2bfloat16(q);
        const __nv_bfloat16 kh = __float2bfloat16(k);
        g_qh[o] = qh;
        g_ql[o] = __float2bfloat16(q - __bfloat162float(qh));
        g_kh[o] = kh;
        g_kl[o] = __float2bfloat16(k - __bfloat162float(kh));
    }
    __syncthreads();
#pragma unroll
    for (int i = 0; i < 16; i++) {
        const int idx = tid + i * 256;
        const int d = idx >> 6;
        const int s = idx & 63;
        const float v = vs[s][d];
        const __nv_bfloat16 vh = __float2bfloat16(v);
        const size_t o = ((size_t)bh * DH + d) * SEQ + st * 64 + s;
        g_vth[o] = vh;
        g_vtl[o] = __float2bfloat16(v - __bfloat162float(vh));
    }
}

// ---------------------------------------------------------------------------
// mma.sync GEMM v3: C = [Ahi|Ahi|Alo](K'=3072) x [Bhi;Blo;Bhi]^T + bias
// CTA tile 128x256, BK=64, 8 warps (2m x 4n), warp tile 64x64.
// 3-stage cp.async pipeline (prefetch depth 2), ONE barrier per chunk.
// smem: 3 x (A 16KB + B 32KB) = 144KB dynamic.
// ---------------------------------------------------------------------------
#define NCHUNK 48
#define GA(s) ((s) * 16384)              // A stages at 0, 16K, 32K
#define GB(s) (49152 + (s) * 32768)      // B stages at 48K, 80K, 112K
#define GEMM_SMEM_BYTES 147456

__global__ void __launch_bounds__(256, 1) gemm_mma_kernel(
    const __nv_bfloat16* __restrict__ Ahi, const __nv_bfloat16* __restrict__ Alo,
    const __nv_bfloat16* __restrict__ Bhi, const __nv_bfloat16* __restrict__ Blo,
    const float* __restrict__ bias, float* __restrict__ C, int Ntot)
{
    extern __shared__ uint8_t gsm[];
    const uint32_t sbase = smem_u32(gsm);

    const int tid = (int)threadIdx.x;
    const int wid = tid >> 5;
    const int lane = tid & 31;
    const int wm = wid & 1;          // 64-row half
    const int wn = wid >> 1;         // 64-col slice

    const int m0g = blockIdx.x * 128;
    const int n0g = blockIdx.y * 256;

    float acc[4][8][4];
#pragma unroll
    for (int mt = 0; mt < 4; mt++)
#pragma unroll
        for (int nt = 0; nt < 8; nt++)
#pragma unroll
            for (int j = 0; j < 4; j++) acc[mt][nt][j] = 0.f;

    // stage chunk c into stage slot ss.
    // chunk c: g=c>>4 (0,1,2), k0=(c&15)*64. A: g==2 -> Alo else Ahi.
    //                                        B: g==1 -> Blo else Bhi.
    auto stage = [&](int c, int ss) {
        const int g = c >> 4;
        const int k0 = (c & 15) * 64;
        const __nv_bfloat16* __restrict__ As = (g == 2) ? Alo : Ahi;
        const __nv_bfloat16* __restrict__ Bs = (g == 1) ? Blo : Bhi;
#pragma unroll
        for (int it = 0; it < 4; ++it) {
            const int idx = tid + it * 256;      // 0..1023
            const int r = idx >> 3;
            const int kc = idx & 7;
            CP_ASYNC16(addr128(sbase + GA(ss), r, kc),
                       As + (size_t)(m0g + r) * DM + k0 + kc * 8);
        }
#pragma unroll
        for (int it = 0; it < 8; ++it) {
            const int idx = tid + it * 256;      // 0..2047
            const int r = idx >> 3;
            const int kc = idx & 7;
            CP_ASYNC16(addr128(sbase + GB(ss), r, kc),
                       Bs + (size_t)(n0g + r) * DM + k0 + kc * 8);
        }
    };

    stage(0, 0);
    CP_COMMIT();
    stage(1, 1);
    CP_COMMIT();

    const int mat = lane >> 3;
    const int arow7 = (lane & 7) + ((mat & 1) << 3);
    const int brow7 = (lane & 7) + ((mat >> 1) << 3);

    for (int c = 0; c < NCHUNK; ++c) {
        // wait for chunk c's data (groups complete in commit order)
        if (c + 1 < NCHUNK) {
            CP_WAIT(1);
        } else {
            CP_WAIT(0);
        }
        // single barrier: data of chunk c visible to all; all warps have
        // finished compute of chunk c-1, so slot (c+2)%3 (== (c-1)%3) is free.
        __syncthreads();

        if (c + 2 < NCHUNK) {
            stage(c + 2, (c + 2) % 3);
            CP_COMMIT();
        }

        const int ss = c % 3;
        const uint32_t abase = sbase + GA(ss);
        const uint32_t bbase = sbase + GB(ss);

#pragma unroll
        for (int ks = 0; ks < 4; ++ks) {
            uint32_t af[4][4];
#pragma unroll
            for (int mt = 0; mt < 4; mt++) {
                const int row = wm * 64 + mt * 16 + arow7;
                const int kc = ks * 2 + (mat >> 1);
                LDSM_X4(af[mt][0], af[mt][1], af[mt][2], af[mt][3],
                        addr128(abase, row, kc));
            }
            uint32_t bf[4][4];
#pragma unroll
            for (int ntp = 0; ntp < 4; ntp++) {
                const int row = wn * 64 + ntp * 16 + brow7;
                const int kc = ks * 2 + (mat & 1);
                LDSM_X4(bf[ntp][0], bf[ntp][1], bf[ntp][2], bf[ntp][3],
                        addr128(bbase, row, kc));
            }
#pragma unroll
            for (int mt = 0; mt < 4; mt++)
#pragma unroll
                for (int nt = 0; nt < 8; nt++)
                    MMA_16816(acc[mt][nt], af[mt],
                              bf[nt >> 1][2 * (nt & 1)], bf[nt >> 1][2 * (nt & 1) + 1]);
        }
    }

    // Epilogue: add bias, store fp32
    const int qrow = lane >> 2;
    const int qcol = (lane & 3) << 1;
    float2 bv[8];
#pragma unroll
    for (int nt = 0; nt < 8; nt++) {
        const int n = n0g + wn * 64 + nt * 8 + qcol;
        bv[nt] = make_float2(bias[n], bias[n + 1]);
    }
#pragma unroll
    for (int mt = 0; mt < 4; mt++) {
        const int r0 = m0g + wm * 64 + mt * 16 + qrow;
#pragma unroll
        for (int nt = 0; nt < 8; nt++) {
            const int n = n0g + wn * 64 + nt * 8 + qcol;
            *(float2*)(C + (size_t)r0 * Ntot + n) =
                make_float2(acc[mt][nt][0] + bv[nt].x, acc[mt][nt][1] + bv[nt].y);
            *(float2*)(C + (size_t)(r0 + 8) * Ntot + n) =
                make_float2(acc[mt][nt][2] + bv[nt].x, acc[mt][nt][3] + bv[nt].y);
        }
    }
}

// ---------------------------------------------------------------------------
// HMMA flash attention (unchanged from R5/R7). Block = 128 q-rows x one (b,h).
// ---------------------------------------------------------------------------
#define SM_QH 0
#define SM_QL 16384
#define SM_KH(b) (32768 + (b) * 16384)
#define SM_KL(b) (40960 + (b) * 16384)
#define SM_VH(b) (65536 + (b) * 16384)
#define SM_VL(b) (73728 + (b) * 16384)
#define ATTN_SMEM_BYTES 98304

__global__ void __launch_bounds__(256) attn_mma_kernel()
{
    extern __shared__ uint8_t dsm[];
    const uint32_t sb = smem_u32(dsm);
    const int tid = (int)threadIdx.x;
    const int wid = tid >> 5;
    const int lane = tid & 31;
    const int qti = 15 - (int)blockIdx.x;       // heavy tiles first
    const int bh = (int)blockIdx.y;
    const int b = bh >> 4;
    const int h = bh & 15;

    const size_t qkbase = (size_t)bh * SEQ * DH;
    const size_t vbase = (size_t)bh * DH * SEQ;

#pragma unroll
    for (int i = 0; i < 4; i++) {
        const int idx = tid + i * 256;
        const int r = idx >> 3;
        const int kc = idx & 7;
        CP_ASYNC16(addr128(sb + SM_QH, r, kc),
                   g_qh + qkbase + (size_t)(qti * 128 + r) * DH + kc * 8);
        CP_ASYNC16(addr128(sb + SM_QL, r, kc),
                   g_ql + qkbase + (size_t)(qti * 128 + r) * DH + kc * 8);
    }

    const int nkt = 2 * qti + 2;

    auto stage_kv = [&](int kt, int bb) {
#pragma unroll
        for (int i = 0; i < 2; i++) {
            const int idx = tid + i * 256;
            const int r = idx >> 3;
            const int kc = idx & 7;
            const size_t ko = qkbase + (size_t)(kt * 64 + r) * DH + kc * 8;
            CP_ASYNC16(addr128(sb + SM_KH(bb), r, kc), g_kh + ko);
            CP_ASYNC16(addr128(sb + SM_KL(bb), r, kc), g_kl + ko);
            const size_t vo = vbase + (size_t)r * SEQ + kt * 64 + kc * 8;
            CP_ASYNC16(addr128(sb + SM_VH(bb), r, kc), g_vth + vo);
            CP_ASYNC16(addr128(sb + SM_VL(bb), r, kc), g_vtl + vo);
        }
    };

    stage_kv(0, 0);
    CP_COMMIT();

    float o[8][4];
#pragma unroll
    for (int t = 0; t < 8; t++)
#pragma unroll
        for (int j = 0; j < 4; j++) o[t][j] = 0.f;
    float m_a = NEG_BIG, m_b = NEG_BIG, l_a = 0.f, l_b = 0.f;

    const int qrow_base = qti * 128 + wid * 16;
    const int ra = lane >> 2;
    const int c2 = (lane & 3) << 1;

    int buf = 0;
    for (int kt = 0; kt < nkt; kt++) {
        if (kt + 1 < nkt) {
            stage_kv(kt + 1, buf ^ 1);
            CP_COMMIT();
            CP_WAIT(1);
        } else {
            CP_WAIT(0);
        }
        __syncthreads();

        // ---- S = Q K^T (3 split terms) ----
        float s[8][4];
#pragma unroll
        for (int t = 0; t < 8; t++)
#pragma unroll
            for (int j = 0; j < 4; j++) s[t][j] = 0.f;

#pragma unroll
        for (int ks = 0; ks < 4; ks++) {
            const int mat = lane >> 3;
            const int arow = wid * 16 + (lane & 7) + ((mat & 1) << 3);
            const int akc = ks * 2 + (mat >> 1);
            uint32_t aqh[4], aql[4];
            LDSM_X4(aqh[0], aqh[1], aqh[2], aqh[3], addr128(sb + SM_QH, arow, akc));
            LDSM_X4(aql[0], aql[1], aql[2], aql[3], addr128(sb + SM_QL, arow, akc));

            const int brow7 = (lane & 7) + ((mat >> 1) << 3);
            const int bkc = ks * 2 + (mat & 1);
#pragma unroll
            for (int ntp = 0; ntp < 4; ntp++) {
                uint32_t bh4[4], bl4[4];
                LDSM_X4(bh4[0], bh4[1], bh4[2], bh4[3],
                        addr128(sb + SM_KH(buf), ntp * 16 + brow7, bkc));
                LDSM_X4(bl4[0], bl4[1], bl4[2], bl4[3],
                        addr128(sb + SM_KL(buf), ntp * 16 + brow7, bkc));
#pragma unroll
                for (int half = 0; half < 2; half++) {
                    const int nt = ntp * 2 + half;
                    MMA_16816(s[nt], aqh, bh4[2 * half], bh4[2 * half + 1]);
                    MMA_16816(s[nt], aql, bh4[2 * half], bh4[2 * half + 1]);
                    MMA_16816(s[nt], aqh, bl4[2 * half], bl4[2 * half + 1]);
                }
            }
        }

        // ---- causal mask ----
        if (kt * 64 + 63 > qrow_base) {
#pragma unroll
            for (int t = 0; t < 8; t++) {
                const int col = kt * 64 + t * 8 + c2;
                const int rowa = qrow_base + ra;
                const int rowb = rowa + 8;
                if (col > rowa)     s[t][0] = NEG_BIG;
                if (col + 1 > rowa) s[t][1] = NEG_BIG;
                if (col > rowb)     s[t][2] = NEG_BIG;
                if (col + 1 > rowb) s[t][3] = NEG_BIG;
            }
        }

        // ---- online softmax (log2 domain) ----
        float pa = NEG_BIG, pb = NEG_BIG;
#pragma unroll
        for (int t = 0; t < 8; t++) {
            pa = fmaxf(pa, fmaxf(s[t][0], s[t][1]));
            pb = fmaxf(pb, fmaxf(s[t][2], s[t][3]));
        }
        pa = fmaxf(pa, __shfl_xor_sync(0xffffffffu, pa, 1));
        pa = fmaxf(pa, __shfl_xor_sync(0xffffffffu, pa, 2));
        pb = fmaxf(pb, __shfl_xor_sync(0xffffffffu, pb, 1));
        pb = fmaxf(pb, __shfl_xor_sync(0xffffffffu, pb, 2));
        const float nm_a = fmaxf(m_a, pa);
        const float nm_b = fmaxf(m_b, pb);
        const float al_a = ex2f(m_a - nm_a);
        const float al_b = ex2f(m_b - nm_b);
        m_a = nm_a;
        m_b = nm_b;

        float sum_a = 0.f, sum_b = 0.f;
#pragma unroll
        for (int t = 0; t < 8; t++) {
            s[t][0] = ex2f(s[t][0] - nm_a);
            s[t][1] = ex2f(s[t][1] - nm_a);
            s[t][2] = ex2f(s[t][2] - nm_b);
            s[t][3] = ex2f(s[t][3] - nm_b);
            sum_a += s[t][0] + s[t][1];
            sum_b += s[t][2] + s[t][3];
        }
        sum_a += __shfl_xor_sync(0xffffffffu, sum_a, 1);
        sum_a += __shfl_xor_sync(0xffffffffu, sum_a, 2);
        sum_b += __shfl_xor_sync(0xffffffffu, sum_b, 1);
        sum_b += __shfl_xor_sync(0xffffffffu, sum_b, 2);
        l_a = l_a * al_a + sum_a;
        l_b = l_b * al_b + sum_b;
#pragma unroll
        for (int t = 0; t < 8; t++) {
            o[t][0] *= al_a;
            o[t][1] *= al_a;
            o[t][2] *= al_b;
            o[t][3] *= al_b;
        }

        // ---- repack P into A fragments (hi + lo) ----
        uint32_t phi[4][4], plo[4][4];
#pragma unroll
        for (int ks = 0; ks < 4; ks++) {
#pragma unroll
            for (int half = 0; half < 2; half++) {
                const int t = 2 * ks + half;
                const __nv_bfloat16 h0 = __float2bfloat16(s[t][0]);
                const __nv_bfloat16 h1 = __float2bfloat16(s[t][1]);
                const __nv_bfloat16 h2 = __float2bfloat16(s[t][2]);
                const __nv_bfloat16 h3 = __float2bfloat16(s[t][3]);
                phi[ks][2 * half + 0] = pack_bf16(h0, h1);
                phi[ks][2 * half + 1] = pack_bf16(h2, h3);
                plo[ks][2 * half + 0] = pack_bf16(
                    __float2bfloat16(s[t][0] - __bfloat162float(h0)),
                    __float2bfloat16(s[t][1] - __bfloat162float(h1)));
                plo[ks][2 * half + 1] = pack_bf16(
                    __float2bfloat16(s[t][2] - __bfloat162float(h2)),
                    __float2bfloat16(s[t][3] - __bfloat162float(h3)));
            }
        }

        // ---- O += P V (3 split terms) ----
        const int mat = lane >> 3;
        const int vrow7 = (lane & 7) + ((mat >> 1) << 3);
#pragma unroll
        for (int ks = 0; ks < 4; ks++) {
            const int vkc = ks * 2 + (mat & 1);
#pragma unroll
            for (int ntp = 0; ntp < 4; ntp++) {
                uint32_t vh4[4], vl4[4];
                LDSM_X4(vh4[0], vh4[1], vh4[2], vh4[3],
                        addr128(sb + SM_VH(buf), ntp * 16 + vrow7, vkc));
                LDSM_X4(vl4[0], vl4[1], vl4[2], vl4[3],
                        addr128(sb + SM_VL(buf), ntp * 16 + vrow7, vkc));
#pragma unroll
                for (int half = 0; half < 2; half++) {
                    const int nt = ntp * 2 + half;
                    MMA_16816(o[nt], phi[ks], vh4[2 * half], vh4[2 * half + 1]);
                    MMA_16816(o[nt], plo[ks], vh4[2 * half], vh4[2 * half + 1]);
                    MMA_16816(o[nt], phi[ks], vl4[2 * half], vl4[2 * half + 1]);
                }
            }
        }

        __syncthreads();
        buf ^= 1;
    }

    // ---- epilogue: normalize, split to bf16 hi/lo for proj GEMM ----
    const float inv_a = 1.f / l_a;
    const float inv_b = 1.f / l_b;
#pragma unroll
    for (int t = 0; t < 8; t++) {
        const int col = h * DH + t * 8 + c2;
        const int rowa = qti * 128 + wid * 16 + ra;
        {
            const float v0 = o[t][0] * inv_a, v1 = o[t][1] * inv_a;
            const __nv_bfloat16 h0 = __float2bfloat16(v0);
            const __nv_bfloat16 h1 = __float2bfloat16(v1);
            const size_t base = (size_t)(b * SEQ + rowa) * DM + col;
            *(__nv_bfloat162*)(g_ahi + base) = __halves2bfloat162(h0, h1);
            *(__nv_bfloat162*)(g_alo + base) = __halves2bfloat162(
                __float2bfloat16(v0 - __bfloat162float(h0)),
                __float2bfloat16(v1 - __bfloat162float(h1)));
        }
        {
            const float v0 = o[t][2] * inv_b, v1 = o[t][3] * inv_b;
            const __nv_bfloat16 h0 = __float2bfloat16(v0);
            const __nv_bfloat16 h1 = __float2bfloat16(v1);
            const size_t base = (size_t)(b * SEQ + rowa + 8) * DM + col;
            *(__nv_bfloat162*)(g_ahi + base) = __halves2bfloat162(h0, h1);
            *(__nv_bfloat162*)(g_alo + base) = __halves2bfloat162(
                __float2bfloat16(v0 - __bfloat162float(h0)),
                __float2bfloat16(v1 - __bfloat162float(h1)));
        }
    }
}

// ---------------------------------------------------------------------------
extern "C" void kernel_launch(void* const* d_in, const int* in_sizes, int n_in,
                              void* d_out, int out_size)
{
    const float* input = (const float*)d_in[0];
    const float* W_qkv = (const float*)d_in[1];
    const float* b_qkv = (const float*)d_in[2];
    const float* W_out = (const float*)d_in[3];
    const float* b_out = (const float*)d_in[4];
    float* out = (float*)d_out;

    cudaFuncSetAttribute(attn_mma_kernel,
                         cudaFuncAttributeMaxDynamicSharedMemorySize, ATTN_SMEM_BYTES);
    cudaFuncSetAttribute(gemm_mma_kernel,
                         cudaFuncAttributeMaxDynamicSharedMemorySize, GEMM_SMEM_BYTES);

    __nv_bfloat16 *xhi, *xlo, *wqh, *wql, *woh, *wol, *ahi, *alo;
    float* qkv;
    cudaGetSymbolAddress((void**)&xhi, g_xhi);
    cudaGetSymbolAddress((void**)&xlo, g_xlo);
    cudaGetSymbolAddress((void**)&wqh, g_wqkvT_hi);
    cudaGetSymbolAddress((void**)&wql, g_wqkvT_lo);
    cudaGetSymbolAddress((void**)&woh, g_woutT_hi);
    cudaGetSymbolAddress((void**)&wol, g_woutT_lo);
    cudaGetSymbolAddress((void**)&ahi, g_ahi);
    cudaGetSymbolAddress((void**)&alo, g_alo);
    cudaGetSymbolAddress((void**)&qkv, g_qkv);

    split_input_kernel<<<(MROWS * DM / 4) / 256, 256>>>(
        (const float4*)input, (__nv_bfloat162*)xhi, (__nv_bfloat162*)xlo);
    transpose_split_kernel<<<dim3(TD / 32, DM / 32), 256>>>(W_qkv, TD, wqh, wql);
    transpose_split_kernel<<<dim3(DM / 32, DM / 32), 256>>>(W_out, DM, woh, wol);

    gemm_mma_kernel<<<dim3(MROWS / 128, TD / 256), 256, GEMM_SMEM_BYTES>>>(
        xhi, xlo, wqh, wql, b_qkv, qkv, TD);

    prep_kernel<<<dim3(SEQ / 64, NBH), 256>>>();

    attn_mma_kernel<<<dim3(SEQ / 128, NBH), 256, ATTN_SMEM_BYTES>>>();

    gemm_mma_kernel<<<dim3(MROWS / 128, DM / 256), 256, GEMM_SMEM_BYTES>>>(
        ahi, alo, woh, wol, b_out, out, DM);
}

// round 9
// speedup vs baseline: 3.8640x; 1.3524x over previous
#include <cuda_runtime.h>
#include <cuda_fp16.h>
#include <cstdint>

#define BSZ 4
#define SEQ 2048
#define NH 16
#define DH 64
#define DM 1024
#define TD 3072
#define MROWS (BSZ * SEQ)
#define NBH (BSZ * NH)

#define NEG_BIG (-1e30f)
#define SCALE_L2E 0.18033688011112042f   // 0.125 * log2(e)

// ---------------------------------------------------------------------------
// Scratch (__device__ globals; no allocation allowed)
// ---------------------------------------------------------------------------
__device__ float g_qkv[(size_t)MROWS * TD];            // fp32 qkv (bias added)
__device__ __half g_xhi[(size_t)MROWS * DM];           // input split hi
__device__ __half g_xlo[(size_t)MROWS * DM];           // input split lo
__device__ __half g_wqkvT[(size_t)TD * DM];            // W_qkv^T fp16 [3072][1024]
__device__ __half g_woutT[(size_t)DM * DM];            // W_out^T fp16 [1024][1024]
__device__ __half g_ahi[(size_t)MROWS * DM];           // attention out split hi
__device__ __half g_alo[(size_t)MROWS * DM];           // attention out split lo
// per-head fp16 for attention (bh-major)
__device__ __half g_qh[(size_t)NBH * SEQ * DH];        // [bh][s][d], pre-scaled
__device__ __half g_ql[(size_t)NBH * SEQ * DH];
__device__ __half g_kh[(size_t)NBH * SEQ * DH];        // [bh][s][d]
__device__ __half g_vth[(size_t)NBH * DH * SEQ];       // [bh][d][s] (transposed)

// ---------------------------------------------------------------------------
// PTX helpers (valid for target sm_100)
// ---------------------------------------------------------------------------
__device__ __forceinline__ uint32_t smem_u32(const void* p) {
    uint32_t a;
    asm("{ .reg .u64 t; cvta.to.shared.u64 t, %1; cvt.u32.u64 %0, t; }" : "=r"(a) : "l"(p));
    return a;
}

#define CP_ASYNC16(dst, src) \
    asm volatile("cp.async.cg.shared.global [%0], [%1], 16;" :: "r"(dst), "l"(src))
#define CP_COMMIT() asm volatile("cp.async.commit_group;" ::: "memory")
#define CP_WAIT(n)  asm volatile("cp.async.wait_group %0;" :: "n"(n) : "memory")

#define LDSM_X4(r0, r1, r2, r3, addr) \
    asm volatile("ldmatrix.sync.aligned.m8n8.x4.shared.b16 {%0,%1,%2,%3}, [%4];" \
                 : "=r"(r0), "=r"(r1), "=r"(r2), "=r"(r3) : "r"(addr))

#define MMA_16816(d, a, b0, b1) \
    asm volatile("mma.sync.aligned.m16n8k16.row.col.f32.f16.f16.f32 " \
                 "{%0,%1,%2,%3}, {%4,%5,%6,%7}, {%8,%9}, {%0,%1,%2,%3};" \
                 : "+f"((d)[0]), "+f"((d)[1]), "+f"((d)[2]), "+f"((d)[3]) \
                 : "r"((a)[0]), "r"((a)[1]), "r"((a)[2]), "r"((a)[3]), \
                   "r"(b0), "r"(b1))

__device__ __forceinline__ float ex2f(float x) {
    float y;
    asm("ex2.approx.ftz.f32 %0, %1;" : "=f"(y) : "f"(x));
    return y;
}

__device__ __forceinline__ uint32_t pack_half(__half a, __half b) {
    __half2 t = __halves2half2(a, b);
    return *(uint32_t*)&t;
}

// 128B-per-row tile (64 fp16 per row): XOR-swizzled 16B chunks within line
__device__ __forceinline__ uint32_t addr128(uint32_t base, int row, int kc) {
    return base + (uint32_t)(row * 128 + ((kc ^ (row & 7)) * 16));
}

// ---------------------------------------------------------------------------
// Conversion kernels
// ---------------------------------------------------------------------------
__global__ void __launch_bounds__(256) split_input_kernel(
    const float4* __restrict__ in, __half2* __restrict__ hi,
    __half2* __restrict__ lo)
{
    const int i = blockIdx.x * 256 + threadIdx.x;
    const float4 v = in[i];
    const __half h0 = __float2half(v.x);
    const __half h1 = __float2half(v.y);
    const __half h2 = __float2half(v.z);
    const __half h3 = __float2half(v.w);
    hi[i * 2 + 0] = __halves2half2(h0, h1);
    hi[i * 2 + 1] = __halves2half2(h2, h3);
    lo[i * 2 + 0] = __halves2half2(__float2half(v.x - __half2float(h0)),
                                   __float2half(v.y - __half2float(h1)));
    lo[i * 2 + 1] = __halves2half2(__float2half(v.z - __half2float(h2)),
                                   __float2half(v.w - __half2float(h3)));
}

// W [1024][N] fp32 -> Wt fp16 [N][1024] (tiled transpose)
__global__ void __launch_bounds__(256) transpose_half_kernel(
    const float* __restrict__ W, int N, __half* __restrict__ T)
{
    __shared__ float t[32][33];
    const int n0 = blockIdx.x * 32;
    const int k0 = blockIdx.y * 32;
    const int tx = threadIdx.x & 31;
    const int ty = threadIdx.x >> 5;
#pragma unroll
    for (int i = 0; i < 32; i += 8)
        t[ty + i][tx] = W[(size_t)(k0 + ty + i) * N + n0 + tx];
    __syncthreads();
#pragma unroll
    for (int i = 0; i < 32; i += 8)
        T[(size_t)(n0 + ty + i) * DM + k0 + tx] = __float2half(t[tx][ty + i]);
}

// prep: Q(scaled) hi/lo, K hi fp16 [bh][s][d]; V hi transposed [bh][d][s]
__global__ void __launch_bounds__(256) prep_kernel()
{
    __shared__ float vs[64][65];
    const int st = blockIdx.x;
    const int bh = (int)blockIdx.y;
    const int b = bh >> 4;
    const int h = bh & 15;
    const int tid = (int)threadIdx.x;

#pragma unroll
    for (int i = 0; i < 16; i++) {
        const int idx = tid + i * 256;
        const int s = idx >> 6;
        const int d = idx & 63;
        const float* src = g_qkv + (size_t)(b * SEQ + st * 64 + s) * TD + h * DH + d;
        const float q = src[0] * SCALE_L2E;
        vs[s][d] = src[2 * DM];
        const size_t o = ((size_t)bh * SEQ + st * 64 + s) * DH + d;
        const __half qh = __float2half(q);
        g_qh[o] = qh;
        g_ql[o] = __float2half(q - __half2float(qh));
        g_kh[o] = __float2half(src[DM]);
    }
    __syncthreads();
#pragma unroll
    for (int i = 0; i < 16; i++) {
        const int idx = tid + i * 256;
        const int d = idx >> 6;
        const int s = idx & 63;
        g_vth[((size_t)bh * DH + d) * SEQ + st * 64 + s] = __float2half(vs[s][d]);
    }
}

// ---------------------------------------------------------------------------
// mma.sync GEMM (fp16, 2-term): C = [Ahi|Alo](K'=2048) x [B;B]^T + bias
// CTA tile 128x256, BK=64, 8 warps (2m x 4n), warp tile 64x64.
// 3-stage cp.async pipeline (prefetch depth 2), one barrier per chunk.
// ---------------------------------------------------------------------------
#define NCHUNK 32
#define GA(s) ((s) * 16384)              // A stages at 0, 16K, 32K
#define GB(s) (49152 + (s) * 32768)      // B stages at 48K, 80K, 112K
#define GEMM_SMEM_BYTES 147456

__global__ void __launch_bounds__(256, 1) gemm_mma_kernel(
    const __half* __restrict__ Ahi, const __half* __restrict__ Alo,
    const __half* __restrict__ Bh,
    const float* __restrict__ bias, float* __restrict__ C, int Ntot)
{
    extern __shared__ uint8_t gsm[];
    const uint32_t sbase = smem_u32(gsm);

    const int tid = (int)threadIdx.x;
    const int wid = tid >> 5;
    const int lane = tid & 31;
    const int wm = wid & 1;          // 64-row half
    const int wn = wid >> 1;         // 64-col slice

    const int m0g = blockIdx.x * 128;
    const int n0g = blockIdx.y * 256;

    float acc[4][8][4];
#pragma unroll
    for (int mt = 0; mt < 4; mt++)
#pragma unroll
        for (int nt = 0; nt < 8; nt++)
#pragma unroll
            for (int j = 0; j < 4; j++) acc[mt][nt][j] = 0.f;

    // chunk c (0..31): group g=c>>4 (0: Ahi, 1: Alo); k0=(c&15)*64; B always Bh.
    auto stage = [&](int c, int ss) {
        const int k0 = (c & 15) * 64;
        const __half* __restrict__ As = (c >= 16) ? Alo : Ahi;
#pragma unroll
        for (int it = 0; it < 4; ++it) {
            const int idx = tid + it * 256;      // 0..1023
            const int r = idx >> 3;
            const int kc = idx & 7;
            CP_ASYNC16(addr128(sbase + GA(ss), r, kc),
                       As + (size_t)(m0g + r) * DM + k0 + kc * 8);
        }
#pragma unroll
        for (int it = 0; it < 8; ++it) {
            const int idx = tid + it * 256;      // 0..2047
            const int r = idx >> 3;
            const int kc = idx & 7;
            CP_ASYNC16(addr128(sbase + GB(ss), r, kc),
                       Bh + (size_t)(n0g + r) * DM + k0 + kc * 8);
        }
    };

    stage(0, 0);
    CP_COMMIT();
    stage(1, 1);
    CP_COMMIT();

    const int mat = lane >> 3;
    const int arow7 = (lane & 7) + ((mat & 1) << 3);
    const int brow7 = (lane & 7) + ((mat >> 1) << 3);

    for (int c = 0; c < NCHUNK; ++c) {
        if (c + 1 < NCHUNK) {
            CP_WAIT(1);
        } else {
            CP_WAIT(0);
        }
        __syncthreads();

        if (c + 2 < NCHUNK) {
            stage(c + 2, (c + 2) % 3);
            CP_COMMIT();
        }

        const int ss = c % 3;
        const uint32_t abase = sbase + GA(ss);
        const uint32_t bbase = sbase + GB(ss);

#pragma unroll
        for (int ks = 0; ks < 4; ++ks) {
            uint32_t af[4][4];
#pragma unroll
            for (int mt = 0; mt < 4; mt++) {
                const int row = wm * 64 + mt * 16 + arow7;
                const int kc = ks * 2 + (mat >> 1);
                LDSM_X4(af[mt][0], af[mt][1], af[mt][2], af[mt][3],
                        addr128(abase, row, kc));
            }
            uint32_t bf[4][4];
#pragma unroll
            for (int ntp = 0; ntp < 4; ntp++) {
                const int row = wn * 64 + ntp * 16 + brow7;
                const int kc = ks * 2 + (mat & 1);
                LDSM_X4(bf[ntp][0], bf[ntp][1], bf[ntp][2], bf[ntp][3],
                        addr128(bbase, row, kc));
            }
#pragma unroll
            for (int mt = 0; mt < 4; mt++)
#pragma unroll
                for (int nt = 0; nt < 8; nt++)
                    MMA_16816(acc[mt][nt], af[mt],
                              bf[nt >> 1][2 * (nt & 1)], bf[nt >> 1][2 * (nt & 1) + 1]);
        }
    }

    // Epilogue: add bias, store fp32
    const int qrow = lane >> 2;
    const int qcol = (lane & 3) << 1;
    float2 bv[8];
#pragma unroll
    for (int nt = 0; nt < 8; nt++) {
        const int n = n0g + wn * 64 + nt * 8 + qcol;
        bv[nt] = make_float2(bias[n], bias[n + 1]);
    }
#pragma unroll
    for (int mt = 0; mt < 4; mt++) {
        const int r0 = m0g + wm * 64 + mt * 16 + qrow;
#pragma unroll
        for (int nt = 0; nt < 8; nt++) {
            const int n = n0g + wn * 64 + nt * 8 + qcol;
            *(float2*)(C + (size_t)r0 * Ntot + n) =
                make_float2(acc[mt][nt][0] + bv[nt].x, acc[mt][nt][1] + bv[nt].y);
            *(float2*)(C + (size_t)(r0 + 8) * Ntot + n) =
                make_float2(acc[mt][nt][2] + bv[nt].x, acc[mt][nt][3] + bv[nt].y);
        }
    }
}

// ---------------------------------------------------------------------------
// HMMA flash attention (fp16, 2-term). Block = 128 q-rows x one (b,h).
// S = Qh K^T + Ql K^T.  PV = Ph V + Pl V.
// smem: QH 16K + QL 16K + KH dbuf 16K + VH dbuf 16K = 64KB dynamic.
// ---------------------------------------------------------------------------
#define SM_QH 0
#define SM_QL 16384
#define SM_KH(b) (32768 + (b) * 8192)
#define SM_VH(b) (49152 + (b) * 8192)
#define ATTN_SMEM_BYTES 65536

__global__ void __launch_bounds__(256) attn_mma_kernel()
{
    extern __shared__ uint8_t dsm[];
    const uint32_t sb = smem_u32(dsm);
    const int tid = (int)threadIdx.x;
    const int wid = tid >> 5;
    const int lane = tid & 31;
    const int qti = 15 - (int)blockIdx.x;       // heavy tiles first
    const int bh = (int)blockIdx.y;
    const int b = bh >> 4;
    const int h = bh & 15;

    const size_t qkbase = (size_t)bh * SEQ * DH;
    const size_t vbase = (size_t)bh * DH * SEQ;

#pragma unroll
    for (int i = 0; i < 4; i++) {
        const int idx = tid + i * 256;
        const int r = idx >> 3;
        const int kc = idx & 7;
        CP_ASYNC16(addr128(sb + SM_QH, r, kc),
                   g_qh + qkbase + (size_t)(qti * 128 + r) * DH + kc * 8);
        CP_ASYNC16(addr128(sb + SM_QL, r, kc),
                   g_ql + qkbase + (size_t)(qti * 128 + r) * DH + kc * 8);
    }

    const int nkt = 2 * qti + 2;

    auto stage_kv = [&](int kt, int bb) {
#pragma unroll
        for (int i = 0; i < 2; i++) {
            const int idx = tid + i * 256;
            const int r = idx >> 3;
            const int kc = idx & 7;
            CP_ASYNC16(addr128(sb + SM_KH(bb), r, kc),
                       g_kh + qkbase + (size_t)(kt * 64 + r) * DH + kc * 8);
            CP_ASYNC16(addr128(sb + SM_VH(bb), r, kc),
                       g_vth + vbase + (size_t)r * SEQ + kt * 64 + kc * 8);
        }
    };

    stage_kv(0, 0);
    CP_COMMIT();

    float o[8][4];
#pragma unroll
    for (int t = 0; t < 8; t++)
#pragma unroll
        for (int j = 0; j < 4; j++) o[t][j] = 0.f;
    float m_a = NEG_BIG, m_b = NEG_BIG, l_a = 0.f, l_b = 0.f;

    const int qrow_base = qti * 128 + wid * 16;
    const int ra = lane >> 2;
    const int c2 = (lane & 3) << 1;

    int buf = 0;
    for (int kt = 0; kt < nkt; kt++) {
        if (kt + 1 < nkt) {
            stage_kv(kt + 1, buf ^ 1);
            CP_COMMIT();
            CP_WAIT(1);
        } else {
            CP_WAIT(0);
        }
        __syncthreads();

        // ---- S = Q K^T (hi + lo terms) ----
        float s[8][4];
#pragma unroll
        for (int t = 0; t < 8; t++)
#pragma unroll
            for (int j = 0; j < 4; j++) s[t][j] = 0.f;

#pragma unroll
        for (int ks = 0; ks < 4; ks++) {
            const int mat = lane >> 3;
            const int arow = wid * 16 + (lane & 7) + ((mat & 1) << 3);
            const int akc = ks * 2 + (mat >> 1);
            uint32_t aqh[4], aql[4];
            LDSM_X4(aqh[0], aqh[1], aqh[2], aqh[3], addr128(sb + SM_QH, arow, akc));
            LDSM_X4(aql[0], aql[1], aql[2], aql[3], addr128(sb + SM_QL, arow, akc));

            const int brow7 = (lane & 7) + ((mat >> 1) << 3);
            const int bkc = ks * 2 + (mat & 1);
#pragma unroll
            for (int ntp = 0; ntp < 4; ntp++) {
                uint32_t bh4[4];
                LDSM_X4(bh4[0], bh4[1], bh4[2], bh4[3],
                        addr128(sb + SM_KH(buf), ntp * 16 + brow7, bkc));
#pragma unroll
                for (int half = 0; half < 2; half++) {
                    const int nt = ntp * 2 + half;
                    MMA_16816(s[nt], aqh, bh4[2 * half], bh4[2 * half + 1]);
                    MMA_16816(s[nt], aql, bh4[2 * half], bh4[2 * half + 1]);
                }
            }
        }

        // ---- causal mask (max col of tile vs MIN warp row) ----
        if (kt * 64 + 63 > qrow_base) {
#pragma unroll
            for (int t = 0; t < 8; t++) {
                const int col = kt * 64 + t * 8 + c2;
                const int rowa = qrow_base + ra;
                const int rowb = rowa + 8;
                if (col > rowa)     s[t][0] = NEG_BIG;
                if (col + 1 > rowa) s[t][1] = NEG_BIG;
                if (col > rowb)     s[t][2] = NEG_BIG;
                if (col + 1 > rowb) s[t][3] = NEG_BIG;
            }
        }

        // ---- online softmax (log2 domain) ----
        float pa = NEG_BIG, pb = NEG_BIG;
#pragma unroll
        for (int t = 0; t < 8; t++) {
            pa = fmaxf(pa, fmaxf(s[t][0], s[t][1]));
            pb = fmaxf(pb, fmaxf(s[t][2], s[t][3]));
        }
        pa = fmaxf(pa, __shfl_xor_sync(0xffffffffu, pa, 1));
        pa = fmaxf(pa, __shfl_xor_sync(0xffffffffu, pa, 2));
        pb = fmaxf(pb, __shfl_xor_sync(0xffffffffu, pb, 1));
        pb = fmaxf(pb, __shfl_xor_sync(0xffffffffu, pb, 2));
        const float nm_a = fmaxf(m_a, pa);
        const float nm_b = fmaxf(m_b, pb);
        const float al_a = ex2f(m_a - nm_a);
        const float al_b = ex2f(m_b - nm_b);
        m_a = nm_a;
        m_b = nm_b;

        float sum_a = 0.f, sum_b = 0.f;
#pragma unroll
        for (int t = 0; t < 8; t++) {
            s[t][0] = ex2f(s[t][0] - nm_a);
            s[t][1] = ex2f(s[t][1] - nm_a);
            s[t][2] = ex2f(s[t][2] - nm_b);
            s[t][3] = ex2f(s[t][3] - nm_b);
            sum_a += s[t][0] + s[t][1];
            sum_b += s[t][2] + s[t][3];
        }
        sum_a += __shfl_xor_sync(0xffffffffu, sum_a, 1);
        sum_a += __shfl_xor_sync(0xffffffffu, sum_a, 2);
        sum_b += __shfl_xor_sync(0xffffffffu, sum_b, 1);
        sum_b += __shfl_xor_sync(0xffffffffu, sum_b, 2);
        l_a = l_a * al_a + sum_a;
        l_b = l_b * al_b + sum_b;
#pragma unroll
        for (int t = 0; t < 8; t++) {
            o[t][0] *= al_a;
            o[t][1] *= al_a;
            o[t][2] *= al_b;
            o[t][3] *= al_b;
        }

        // ---- repack P into A fragments (hi + lo, fp16) ----
        uint32_t phi[4][4], plo[4][4];
#pragma unroll
        for (int ks = 0; ks < 4; ks++) {
#pragma unroll
            for (int half = 0; half < 2; half++) {
                const int t = 2 * ks + half;
                const __half h0 = __float2half(s[t][0]);
                const __half h1 = __float2half(s[t][1]);
                const __half h2 = __float2half(s[t][2]);
                const __half h3 = __float2half(s[t][3]);
                phi[ks][2 * half + 0] = pack_half(h0, h1);
                phi[ks][2 * half + 1] = pack_half(h2, h3);
                plo[ks][2 * half + 0] = pack_half(
                    __float2half(s[t][0] - __half2float(h0)),
                    __float2half(s[t][1] - __half2float(h1)));
                plo[ks][2 * half + 1] = pack_half(
                    __float2half(s[t][2] - __half2float(h2)),
                    __float2half(s[t][3] - __half2float(h3)));
            }
        }

        // ---- O += P V (hi + lo terms) ----
        const int mat = lane >> 3;
        const int vrow7 = (lane & 7) + ((mat >> 1) << 3);
#pragma unroll
        for (int ks = 0; ks < 4; ks++) {
            const int vkc = ks * 2 + (mat & 1);
#pragma unroll
            for (int ntp = 0; ntp < 4; ntp++) {
                uint32_t vh4[4];
                LDSM_X4(vh4[0], vh4[1], vh4[2], vh4[3],
                        addr128(sb + SM_VH(buf), ntp * 16 + vrow7, vkc));
#pragma unroll
                for (int half = 0; half < 2; half++) {
                    const int nt = ntp * 2 + half;
                    MMA_16816(o[nt], phi[ks], vh4[2 * half], vh4[2 * half + 1]);
                    MMA_16816(o[nt], plo[ks], vh4[2 * half], vh4[2 * half + 1]);
                }
            }
        }

        __syncthreads();
        buf ^= 1;
    }

    // ---- epilogue: normalize, split to fp16 hi/lo for proj GEMM ----
    const float inv_a = 1.f / l_a;
    const float inv_b = 1.f / l_b;
#pragma unroll
    for (int t = 0; t < 8; t++) {
        const int col = h * DH + t * 8 + c2;
        const int rowa = qti * 128 + wid * 16 + ra;
        {
            const float v0 = o[t][0] * inv_a, v1 = o[t][1] * inv_a;
            const __half h0 = __float2half(v0);
            const __half h1 = __float2half(v1);
            const size_t base = (size_t)(b * SEQ + rowa) * DM + col;
            *(__half2*)(g_ahi + base) = __halves2half2(h0, h1);
            *(__half2*)(g_alo + base) = __halves2half2(
                __float2half(v0 - __half2float(h0)),
                __float2half(v1 - __half2float(h1)));
        }
        {
            const float v0 = o[t][2] * inv_b, v1 = o[t][3] * inv_b;
            const __half h0 = __float2half(v0);
            const __half h1 = __float2half(v1);
            const size_t base = (size_t)(b * SEQ + rowa + 8) * DM + col;
            *(__half2*)(g_ahi + base) = __halves2half2(h0, h1);
            *(__half2*)(g_alo + base) = __halves2half2(
                __float2half(v0 - __half2float(h0)),
                __float2half(v1 - __half2float(h1)));
        }
    }
}

// ---------------------------------------------------------------------------
extern "C" void kernel_launch(void* const* d_in, const int* in_sizes, int n_in,
                              void* d_out, int out_size)
{
    const float* input = (const float*)d_in[0];
    const float* W_qkv = (const float*)d_in[1];
    const float* b_qkv = (const float*)d_in[2];
    const float* W_out = (const float*)d_in[3];
    const float* b_out = (const float*)d_in[4];
    float* out = (float*)d_out;

    cudaFuncSetAttribute(attn_mma_kernel,
                         cudaFuncAttributeMaxDynamicSharedMemorySize, ATTN_SMEM_BYTES);
    cudaFuncSetAttribute(gemm_mma_kernel,
                         cudaFuncAttributeMaxDynamicSharedMemorySize, GEMM_SMEM_BYTES);

    __half *xhi, *xlo, *wqT, *woT, *ahi, *alo;
    float* qkv;
    cudaGetSymbolAddress((void**)&xhi, g_xhi);
    cudaGetSymbolAddress((void**)&xlo, g_xlo);
    cudaGetSymbolAddress((void**)&wqT, g_wqkvT);
    cudaGetSymbolAddress((void**)&woT, g_woutT);
    cudaGetSymbolAddress((void**)&ahi, g_ahi);
    cudaGetSymbolAddress((void**)&alo, g_alo);
    cudaGetSymbolAddress((void**)&qkv, g_qkv);

    split_input_kernel<<<(MROWS * DM / 4) / 256, 256>>>(
        (const float4*)input, (__half2*)xhi, (__half2*)xlo);
    transpose_half_kernel<<<dim3(TD / 32, DM / 32), 256>>>(W_qkv, TD, wqT);
    transpose_half_kernel<<<dim3(DM / 32, DM / 32), 256>>>(W_out, DM, woT);

    gemm_mma_kernel<<<dim3(MROWS / 128, TD / 256), 256, GEMM_SMEM_BYTES>>>(
        xhi, xlo, wqT, b_qkv, qkv, TD);

    prep_kernel<<<dim3(SEQ / 64, NBH), 256>>>();

    attn_mma_kernel<<<dim3(SEQ / 128, NBH), 256, ATTN_SMEM_BYTES>>>();

    gemm_mma_kernel<<<dim3(MROWS / 128, DM / 256), 256, GEMM_SMEM_BYTES>>>(
        ahi, alo, woT, b_out, out, DM);
}

// round 10
// speedup vs baseline: 4.6387x; 1.2005x over previous
#include <cuda_runtime.h>
#include <cuda_fp16.h>
#include <cstdint>

#define BSZ 4
#define SEQ 2048
#define NH 16
#define DH 64
#define DM 1024
#define TD 3072
#define MROWS (BSZ * SEQ)
#define NBH (BSZ * NH)

#define NEG_BIG (-1e30f)
#define SCALE_L2E 0.18033688011112042f   // 0.125 * log2(e)

// ---------------------------------------------------------------------------
// Scratch (__device__ globals; no allocation allowed)
// ---------------------------------------------------------------------------
__device__ float g_qkv[(size_t)MROWS * TD];            // fp32 qkv (bias added)
__device__ __half g_xhi[(size_t)MROWS * DM];           // input split hi
__device__ __half g_xlo[(size_t)MROWS * DM];           // input split lo
__device__ __half g_wqkvT[(size_t)TD * DM];            // W_qkv^T fp16 [3072][1024]
__device__ __half g_woutT[(size_t)DM * DM];            // W_out^T fp16 [1024][1024]
__device__ __half g_ahi[(size_t)MROWS * DM];           // attention out split hi
__device__ __half g_alo[(size_t)MROWS * DM];           // attention out split lo
// per-head fp16 for attention (bh-major)
__device__ __half g_qh[(size_t)NBH * SEQ * DH];        // [bh][s][d], pre-scaled
__device__ __half g_ql[(size_t)NBH * SEQ * DH];
__device__ __half g_kh[(size_t)NBH * SEQ * DH];        // [bh][s][d]
__device__ __half g_vth[(size_t)NBH * DH * SEQ];       // [bh][d][s] (transposed)

// ---------------------------------------------------------------------------
// PTX helpers (valid for target sm_100)
// ---------------------------------------------------------------------------
__device__ __forceinline__ uint32_t smem_u32(const void* p) {
    uint32_t a;
    asm("{ .reg .u64 t; cvta.to.shared.u64 t, %1; cvt.u32.u64 %0, t; }" : "=r"(a) : "l"(p));
    return a;
}

#define CP_ASYNC16(dst, src) \
    asm volatile("cp.async.cg.shared.global [%0], [%1], 16;" :: "r"(dst), "l"(src))
#define CP_COMMIT() asm volatile("cp.async.commit_group;" ::: "memory")
#define CP_WAIT(n)  asm volatile("cp.async.wait_group %0;" :: "n"(n) : "memory")

#define LDSM_X4(r0, r1, r2, r3, addr) \
    asm volatile("ldmatrix.sync.aligned.m8n8.x4.shared.b16 {%0,%1,%2,%3}, [%4];" \
                 : "=r"(r0), "=r"(r1), "=r"(r2), "=r"(r3) : "r"(addr))

#define MMA_16816(d, a, b0, b1) \
    asm volatile("mma.sync.aligned.m16n8k16.row.col.f32.f16.f16.f32 " \
                 "{%0,%1,%2,%3}, {%4,%5,%6,%7}, {%8,%9}, {%0,%1,%2,%3};" \
                 : "+f"((d)[0]), "+f"((d)[1]), "+f"((d)[2]), "+f"((d)[3]) \
                 : "r"((a)[0]), "r"((a)[1]), "r"((a)[2]), "r"((a)[3]), \
                   "r"(b0), "r"(b1))

__device__ __forceinline__ float ex2f(float x) {
    float y;
    asm("ex2.approx.ftz.f32 %0, %1;" : "=f"(y) : "f"(x));
    return y;
}

__device__ __forceinline__ uint32_t pack_half(__half a, __half b) {
    __half2 t = __halves2half2(a, b);
    return *(uint32_t*)&t;
}

// 128B-per-row tile (64 fp16 per row): XOR-swizzled 16B chunks within line
__device__ __forceinline__ uint32_t addr128(uint32_t base, int row, int kc) {
    return base + (uint32_t)(row * 128 + ((kc ^ (row & 7)) * 16));
}

// ---------------------------------------------------------------------------
// Conversion kernels
// ---------------------------------------------------------------------------
__global__ void __launch_bounds__(256) split_input_kernel(
    const float4* __restrict__ in, __half2* __restrict__ hi,
    __half2* __restrict__ lo)
{
    const int i = blockIdx.x * 256 + threadIdx.x;
    const float4 v = in[i];
    const __half h0 = __float2half(v.x);
    const __half h1 = __float2half(v.y);
    const __half h2 = __float2half(v.z);
    const __half h3 = __float2half(v.w);
    hi[i * 2 + 0] = __halves2half2(h0, h1);
    hi[i * 2 + 1] = __halves2half2(h2, h3);
    lo[i * 2 + 0] = __halves2half2(__float2half(v.x - __half2float(h0)),
                                   __float2half(v.y - __half2float(h1)));
    lo[i * 2 + 1] = __halves2half2(__float2half(v.z - __half2float(h2)),
                                   __float2half(v.w - __half2float(h3)));
}

// W [1024][N] fp32 -> Wt fp16 [N][1024] (tiled transpose)
__global__ void __launch_bounds__(256) transpose_half_kernel(
    const float* __restrict__ W, int N, __half* __restrict__ T)
{
    __shared__ float t[32][33];
    const int n0 = blockIdx.x * 32;
    const int k0 = blockIdx.y * 32;
    const int tx = threadIdx.x & 31;
    const int ty = threadIdx.x >> 5;
#pragma unroll
    for (int i = 0; i < 32; i += 8)
        t[ty + i][tx] = W[(size_t)(k0 + ty + i) * N + n0 + tx];
    __syncthreads();
#pragma unroll
    for (int i = 0; i < 32; i += 8)
        T[(size_t)(n0 + ty + i) * DM + k0 + tx] = __float2half(t[tx][ty + i]);
}

// prep: Q(scaled) hi/lo, K hi fp16 [bh][s][d]; V hi transposed [bh][d][s]
__global__ void __launch_bounds__(256) prep_kernel()
{
    __shared__ float vs[64][65];
    const int st = blockIdx.x;
    const int bh = (int)blockIdx.y;
    const int b = bh >> 4;
    const int h = bh & 15;
    const int tid = (int)threadIdx.x;

#pragma unroll
    for (int i = 0; i < 16; i++) {
        const int idx = tid + i * 256;
        const int s = idx >> 6;
        const int d = idx & 63;
        const float* src = g_qkv + (size_t)(b * SEQ + st * 64 + s) * TD + h * DH + d;
        const float q = src[0] * SCALE_L2E;
        vs[s][d] = src[2 * DM];
        const size_t o = ((size_t)bh * SEQ + st * 64 + s) * DH + d;
        const __half qh = __float2half(q);
        g_qh[o] = qh;
        g_ql[o] = __float2half(q - __half2float(qh));
        g_kh[o] = __float2half(src[DM]);
    }
    __syncthreads();
#pragma unroll
    for (int i = 0; i < 16; i++) {
        const int idx = tid + i * 256;
        const int d = idx >> 6;
        const int s = idx & 63;
        g_vth[((size_t)bh * DH + d) * SEQ + st * 64 + s] = __float2half(vs[s][d]);
    }
}

// ---------------------------------------------------------------------------
// mma.sync GEMM (fp16, 2-term): C = [Ahi|Alo](K'=2048) x [B;B]^T + bias
// CTA tile 128x256, BK=64, 8 warps (2m x 4n), warp tile 64x64.
// 3-stage cp.async pipeline (prefetch depth 2), one barrier per chunk.
// CTAs with n0g >= n_locut skip the Alo half (hi-only, 16 chunks) — used
// to drop the correction for V columns of the qkv projection.
// ---------------------------------------------------------------------------
#define NCHUNK 32
#define GA(s) ((s) * 16384)              // A stages at 0, 16K, 32K
#define GB(s) (49152 + (s) * 32768)      // B stages at 48K, 80K, 112K
#define GEMM_SMEM_BYTES 147456

__global__ void __launch_bounds__(256, 1) gemm_mma_kernel(
    const __half* __restrict__ Ahi, const __half* __restrict__ Alo,
    const __half* __restrict__ Bh,
    const float* __restrict__ bias, float* __restrict__ C, int Ntot,
    int n_locut)
{
    extern __shared__ uint8_t gsm[];
    const uint32_t sbase = smem_u32(gsm);

    const int tid = (int)threadIdx.x;
    const int wid = tid >> 5;
    const int lane = tid & 31;
    const int wm = wid & 1;          // 64-row half
    const int wn = wid >> 1;         // 64-col slice

    const int m0g = blockIdx.x * 128;
    const int n0g = blockIdx.y * 256;
    const int nch = (n0g >= n_locut) ? (NCHUNK / 2) : NCHUNK;

    float acc[4][8][4];
#pragma unroll
    for (int mt = 0; mt < 4; mt++)
#pragma unroll
        for (int nt = 0; nt < 8; nt++)
#pragma unroll
            for (int j = 0; j < 4; j++) acc[mt][nt][j] = 0.f;

    // chunk c: c<16 -> Ahi, else Alo; k0=(c&15)*64; B always Bh.
    auto stage = [&](int c, int ss) {
        const int k0 = (c & 15) * 64;
        const __half* __restrict__ As = (c >= 16) ? Alo : Ahi;
#pragma unroll
        for (int it = 0; it < 4; ++it) {
            const int idx = tid + it * 256;      // 0..1023
            const int r = idx >> 3;
            const int kc = idx & 7;
            CP_ASYNC16(addr128(sbase + GA(ss), r, kc),
                       As + (size_t)(m0g + r) * DM + k0 + kc * 8);
        }
#pragma unroll
        for (int it = 0; it < 8; ++it) {
            const int idx = tid + it * 256;      // 0..2047
            const int r = idx >> 3;
            const int kc = idx & 7;
            CP_ASYNC16(addr128(sbase + GB(ss), r, kc),
                       Bh + (size_t)(n0g + r) * DM + k0 + kc * 8);
        }
    };

    stage(0, 0);
    CP_COMMIT();
    stage(1, 1);
    CP_COMMIT();

    const int mat = lane >> 3;
    const int arow7 = (lane & 7) + ((mat & 1) << 3);
    const int brow7 = (lane & 7) + ((mat >> 1) << 3);

    for (int c = 0; c < nch; ++c) {
        if (c + 1 < nch) {
            CP_WAIT(1);
        } else {
            CP_WAIT(0);
        }
        __syncthreads();

        if (c + 2 < nch) {
            stage(c + 2, (c + 2) % 3);
            CP_COMMIT();
        }

        const int ss = c % 3;
        const uint32_t abase = sbase + GA(ss);
        const uint32_t bbase = sbase + GB(ss);

#pragma unroll
        for (int ks = 0; ks < 4; ++ks) {
            uint32_t af[4][4];
#pragma unroll
            for (int mt = 0; mt < 4; mt++) {
                const int row = wm * 64 + mt * 16 + arow7;
                const int kc = ks * 2 + (mat >> 1);
                LDSM_X4(af[mt][0], af[mt][1], af[mt][2], af[mt][3],
                        addr128(abase, row, kc));
            }
            uint32_t bf[4][4];
#pragma unroll
            for (int ntp = 0; ntp < 4; ntp++) {
                const int row = wn * 64 + ntp * 16 + brow7;
                const int kc = ks * 2 + (mat & 1);
                LDSM_X4(bf[ntp][0], bf[ntp][1], bf[ntp][2], bf[ntp][3],
                        addr128(bbase, row, kc));
            }
#pragma unroll
            for (int mt = 0; mt < 4; mt++)
#pragma unroll
                for (int nt = 0; nt < 8; nt++)
                    MMA_16816(acc[mt][nt], af[mt],
                              bf[nt >> 1][2 * (nt & 1)], bf[nt >> 1][2 * (nt & 1) + 1]);
        }
    }

    // Epilogue: add bias, store fp32
    const int qrow = lane >> 2;
    const int qcol = (lane & 3) << 1;
    float2 bv[8];
#pragma unroll
    for (int nt = 0; nt < 8; nt++) {
        const int n = n0g + wn * 64 + nt * 8 + qcol;
        bv[nt] = make_float2(bias[n], bias[n + 1]);
    }
#pragma unroll
    for (int mt = 0; mt < 4; mt++) {
        const int r0 = m0g + wm * 64 + mt * 16 + qrow;
#pragma unroll
        for (int nt = 0; nt < 8; nt++) {
            const int n = n0g + wn * 64 + nt * 8 + qcol;
            *(float2*)(C + (size_t)r0 * Ntot + n) =
                make_float2(acc[mt][nt][0] + bv[nt].x, acc[mt][nt][1] + bv[nt].y);
            *(float2*)(C + (size_t)(r0 + 8) * Ntot + n) =
                make_float2(acc[mt][nt][2] + bv[nt].x, acc[mt][nt][3] + bv[nt].y);
        }
    }
}

// ---------------------------------------------------------------------------
// HMMA flash attention (fp16). Block = 128 q-rows x one (b,h).
// S = Qh K^T + Ql K^T (2-term).  PV = Ph V (1-term; P in [0,1] well-cond.).
// smem: QH 16K + QL 16K + KH dbuf 16K + VH dbuf 16K = 64KB dynamic.
// ---------------------------------------------------------------------------
#define SM_QH 0
#define SM_QL 16384
#define SM_KH(b) (32768 + (b) * 8192)
#define SM_VH(b) (49152 + (b) * 8192)
#define ATTN_SMEM_BYTES 65536

__global__ void __launch_bounds__(256) attn_mma_kernel()
{
    extern __shared__ uint8_t dsm[];
    const uint32_t sb = smem_u32(dsm);
    const int tid = (int)threadIdx.x;
    const int wid = tid >> 5;
    const int lane = tid & 31;
    const int qti = 15 - (int)blockIdx.x;       // heavy tiles first
    const int bh = (int)blockIdx.y;
    const int b = bh >> 4;
    const int h = bh & 15;

    const size_t qkbase = (size_t)bh * SEQ * DH;
    const size_t vbase = (size_t)bh * DH * SEQ;

#pragma unroll
    for (int i = 0; i < 4; i++) {
        const int idx = tid + i * 256;
        const int r = idx >> 3;
        const int kc = idx & 7;
        CP_ASYNC16(addr128(sb + SM_QH, r, kc),
                   g_qh + qkbase + (size_t)(qti * 128 + r) * DH + kc * 8);
        CP_ASYNC16(addr128(sb + SM_QL, r, kc),
                   g_ql + qkbase + (size_t)(qti * 128 + r) * DH + kc * 8);
    }

    const int nkt = 2 * qti + 2;

    auto stage_kv = [&](int kt, int bb) {
#pragma unroll
        for (int i = 0; i < 2; i++) {
            const int idx = tid + i * 256;
            const int r = idx >> 3;
            const int kc = idx & 7;
            CP_ASYNC16(addr128(sb + SM_KH(bb), r, kc),
                       g_kh + qkbase + (size_t)(kt * 64 + r) * DH + kc * 8);
            CP_ASYNC16(addr128(sb + SM_VH(bb), r, kc),
                       g_vth + vbase + (size_t)r * SEQ + kt * 64 + kc * 8);
        }
    };

    stage_kv(0, 0);
    CP_COMMIT();

    float o[8][4];
#pragma unroll
    for (int t = 0; t < 8; t++)
#pragma unroll
        for (int j = 0; j < 4; j++) o[t][j] = 0.f;
    float m_a = NEG_BIG, m_b = NEG_BIG, l_a = 0.f, l_b = 0.f;

    const int qrow_base = qti * 128 + wid * 16;
    const int ra = lane >> 2;
    const int c2 = (lane & 3) << 1;

    int buf = 0;
    for (int kt = 0; kt < nkt; kt++) {
        if (kt + 1 < nkt) {
            stage_kv(kt + 1, buf ^ 1);
            CP_COMMIT();
            CP_WAIT(1);
        } else {
            CP_WAIT(0);
        }
        __syncthreads();

        // ---- S = Q K^T (hi + lo terms) ----
        float s[8][4];
#pragma unroll
        for (int t = 0; t < 8; t++)
#pragma unroll
            for (int j = 0; j < 4; j++) s[t][j] = 0.f;

#pragma unroll
        for (int ks = 0; ks < 4; ks++) {
            const int mat = lane >> 3;
            const int arow = wid * 16 + (lane & 7) + ((mat & 1) << 3);
            const int akc = ks * 2 + (mat >> 1);
            uint32_t aqh[4], aql[4];
            LDSM_X4(aqh[0], aqh[1], aqh[2], aqh[3], addr128(sb + SM_QH, arow, akc));
            LDSM_X4(aql[0], aql[1], aql[2], aql[3], addr128(sb + SM_QL, arow, akc));

            const int brow7 = (lane & 7) + ((mat >> 1) << 3);
            const int bkc = ks * 2 + (mat & 1);
#pragma unroll
            for (int ntp = 0; ntp < 4; ntp++) {
                uint32_t bh4[4];
                LDSM_X4(bh4[0], bh4[1], bh4[2], bh4[3],
                        addr128(sb + SM_KH(buf), ntp * 16 + brow7, bkc));
#pragma unroll
                for (int half = 0; half < 2; half++) {
                    const int nt = ntp * 2 + half;
                    MMA_16816(s[nt], aqh, bh4[2 * half], bh4[2 * half + 1]);
                    MMA_16816(s[nt], aql, bh4[2 * half], bh4[2 * half + 1]);
                }
            }
        }

        // ---- causal mask (max col of tile vs MIN warp row) ----
        if (kt * 64 + 63 > qrow_base) {
#pragma unroll
            for (int t = 0; t < 8; t++) {
                const int col = kt * 64 + t * 8 + c2;
                const int rowa = qrow_base + ra;
                const int rowb = rowa + 8;
                if (col > rowa)     s[t][0] = NEG_BIG;
                if (col + 1 > rowa) s[t][1] = NEG_BIG;
                if (col > rowb)     s[t][2] = NEG_BIG;
                if (col + 1 > rowb) s[t][3] = NEG_BIG;
            }
        }

        // ---- online softmax (log2 domain) ----
        float pa = NEG_BIG, pb = NEG_BIG;
#pragma unroll
        for (int t = 0; t < 8; t++) {
            pa = fmaxf(pa, fmaxf(s[t][0], s[t][1]));
            pb = fmaxf(pb, fmaxf(s[t][2], s[t][3]));
        }
        pa = fmaxf(pa, __shfl_xor_sync(0xffffffffu, pa, 1));
        pa = fmaxf(pa, __shfl_xor_sync(0xffffffffu, pa, 2));
        pb = fmaxf(pb, __shfl_xor_sync(0xffffffffu, pb, 1));
        pb = fmaxf(pb, __shfl_xor_sync(0xffffffffu, pb, 2));
        const float nm_a = fmaxf(m_a, pa);
        const float nm_b = fmaxf(m_b, pb);
        const float al_a = ex2f(m_a - nm_a);
        const float al_b = ex2f(m_b - nm_b);
        m_a = nm_a;
        m_b = nm_b;

        float sum_a = 0.f, sum_b = 0.f;
#pragma unroll
        for (int t = 0; t < 8; t++) {
            s[t][0] = ex2f(s[t][0] - nm_a);
            s[t][1] = ex2f(s[t][1] - nm_a);
            s[t][2] = ex2f(s[t][2] - nm_b);
            s[t][3] = ex2f(s[t][3] - nm_b);
            sum_a += s[t][0] + s[t][1];
            sum_b += s[t][2] + s[t][3];
        }
        sum_a += __shfl_xor_sync(0xffffffffu, sum_a, 1);
        sum_a += __shfl_xor_sync(0xffffffffu, sum_a, 2);
        sum_b += __shfl_xor_sync(0xffffffffu, sum_b, 1);
        sum_b += __shfl_xor_sync(0xffffffffu, sum_b, 2);
        l_a = l_a * al_a + sum_a;
        l_b = l_b * al_b + sum_b;
#pragma unroll
        for (int t = 0; t < 8; t++) {
            o[t][0] *= al_a;
            o[t][1] *= al_a;
            o[t][2] *= al_b;
            o[t][3] *= al_b;
        }

        // ---- repack P into A fragments (hi only, fp16) ----
        uint32_t phi[4][4];
#pragma unroll
        for (int ks = 0; ks < 4; ks++) {
#pragma unroll
            for (int half = 0; half < 2; half++) {
                const int t = 2 * ks + half;
                phi[ks][2 * half + 0] = pack_half(__float2half(s[t][0]),
                                                  __float2half(s[t][1]));
                phi[ks][2 * half + 1] = pack_half(__float2half(s[t][2]),
                                                  __float2half(s[t][3]));
            }
        }

        // ---- O += P V (single term) ----
        const int mat = lane >> 3;
        const int vrow7 = (lane & 7) + ((mat >> 1) << 3);
#pragma unroll
        for (int ks = 0; ks < 4; ks++) {
            const int vkc = ks * 2 + (mat & 1);
#pragma unroll
            for (int ntp = 0; ntp < 4; ntp++) {
                uint32_t vh4[4];
                LDSM_X4(vh4[0], vh4[1], vh4[2], vh4[3],
                        addr128(sb + SM_VH(buf), ntp * 16 + vrow7, vkc));
#pragma unroll
                for (int half = 0; half < 2; half++) {
                    const int nt = ntp * 2 + half;
                    MMA_16816(o[nt], phi[ks], vh4[2 * half], vh4[2 * half + 1]);
                }
            }
        }

        __syncthreads();
        buf ^= 1;
    }

    // ---- epilogue: normalize, split to fp16 hi/lo for proj GEMM ----
    const float inv_a = 1.f / l_a;
    const float inv_b = 1.f / l_b;
#pragma unroll
    for (int t = 0; t < 8; t++) {
        const int col = h * DH + t * 8 + c2;
        const int rowa = qti * 128 + wid * 16 + ra;
        {
            const float v0 = o[t][0] * inv_a, v1 = o[t][1] * inv_a;
            const __half h0 = __float2half(v0);
            const __half h1 = __float2half(v1);
            const size_t base = (size_t)(b * SEQ + rowa) * DM + col;
            *(__half2*)(g_ahi + base) = __halves2half2(h0, h1);
            *(__half2*)(g_alo + base) = __halves2half2(
                __float2half(v0 - __half2float(h0)),
                __float2half(v1 - __half2float(h1)));
        }
        {
            const float v0 = o[t][2] * inv_b, v1 = o[t][3] * inv_b;
            const __half h0 = __float2half(v0);
            const __half h1 = __float2half(v1);
            const size_t base = (size_t)(b * SEQ + rowa + 8) * DM + col;
            *(__half2*)(g_ahi + base) = __halves2half2(h0, h1);
            *(__half2*)(g_alo + base) = __halves2half2(
                __float2half(v0 - __half2float(h0)),
                __float2half(v1 - __half2float(h1)));
        }
    }
}

// ---------------------------------------------------------------------------
extern "C" void kernel_launch(void* const* d_in, const int* in_sizes, int n_in,
                              void* d_out, int out_size)
{
    const float* input = (const float*)d_in[0];
    const float* W_qkv = (const float*)d_in[1];
    const float* b_qkv = (const float*)d_in[2];
    const float* W_out = (const float*)d_in[3];
    const float* b_out = (const float*)d_in[4];
    float* out = (float*)d_out;

    cudaFuncSetAttribute(attn_mma_kernel,
                         cudaFuncAttributeMaxDynamicSharedMemorySize, ATTN_SMEM_BYTES);
    cudaFuncSetAttribute(gemm_mma_kernel,
                         cudaFuncAttributeMaxDynamicSharedMemorySize, GEMM_SMEM_BYTES);

    __half *xhi, *xlo, *wqT, *woT, *ahi, *alo;
    float* qkv;
    cudaGetSymbolAddress((void**)&xhi, g_xhi);
    cudaGetSymbolAddress((void**)&xlo, g_xlo);
    cudaGetSymbolAddress((void**)&wqT, g_wqkvT);
    cudaGetSymbolAddress((void**)&woT, g_woutT);
    cudaGetSymbolAddress((void**)&ahi, g_ahi);
    cudaGetSymbolAddress((void**)&alo, g_alo);
    cudaGetSymbolAddress((void**)&qkv, g_qkv);

    split_input_kernel<<<(MROWS * DM / 4) / 256, 256>>>(
        (const float4*)input, (__half2*)xhi, (__half2*)xlo);
    transpose_half_kernel<<<dim3(TD / 32, DM / 32), 256>>>(W_qkv, TD, wqT);
    transpose_half_kernel<<<dim3(DM / 32, DM / 32), 256>>>(W_out, DM, woT);

    // qkv: lo-correction skipped for V columns (n >= 2048)
    gemm_mma_kernel<<<dim3(MROWS / 128, TD / 256), 256, GEMM_SMEM_BYTES>>>(
        xhi, xlo, wqT, b_qkv, qkv, TD, 2 * DM);

    prep_kernel<<<dim3(SEQ / 64, NBH), 256>>>();

    attn_mma_kernel<<<dim3(SEQ / 128, NBH), 256, ATTN_SMEM_BYTES>>>();

    // proj: full 2-term
    gemm_mma_kernel<<<dim3(MROWS / 128, DM / 256), 256, GEMM_SMEM_BYTES>>>(
        ahi, alo, woT, b_out, out, DM, 1 << 30);
}

// round 11
// speedup vs baseline: 5.5880x; 1.2046x over previous
#include <cuda_runtime.h>
#include <cuda_fp16.h>
#include <cstdint>

#define BSZ 4
#define SEQ 2048
#define NH 16
#define DH 64
#define DM 1024
#define TD 3072
#define MROWS (BSZ * SEQ)
#define NBH (BSZ * NH)

#define NEG_BIG (-1e30f)
#define SCALE_L2E 0.18033688011112042f   // 0.125 * log2(e)

// ---------------------------------------------------------------------------
// Scratch (__device__ globals; no allocation allowed)
// ---------------------------------------------------------------------------
__device__ float g_qkv[(size_t)MROWS * TD];            // fp32 qkv (bias added)
__device__ __half g_xhi[(size_t)MROWS * DM];           // input split hi
__device__ __half g_xlo[(size_t)MROWS * DM];           // input split lo
__device__ __half g_wqkvT[(size_t)TD * DM];            // W_qkv^T fp16 [3072][1024]
__device__ __half g_woutT[(size_t)DM * DM];            // W_out^T fp16 [1024][1024]
__device__ __half g_ahi[(size_t)MROWS * DM];           // attention out fp16
// per-head fp16 for attention (bh-major)
__device__ __half g_qh[(size_t)NBH * SEQ * DH];        // [bh][s][d], pre-scaled
__device__ __half g_ql[(size_t)NBH * SEQ * DH];
__device__ __half g_kh[(size_t)NBH * SEQ * DH];        // [bh][s][d]
__device__ __half g_vth[(size_t)NBH * DH * SEQ];       // [bh][d][s] (transposed)

// ---------------------------------------------------------------------------
// PTX helpers (valid for target sm_100)
// ---------------------------------------------------------------------------
__device__ __forceinline__ uint32_t smem_u32(const void* p) {
    uint32_t a;
    asm("{ .reg .u64 t; cvta.to.shared.u64 t, %1; cvt.u32.u64 %0, t; }" : "=r"(a) : "l"(p));
    return a;
}

#define CP_ASYNC16(dst, src) \
    asm volatile("cp.async.cg.shared.global [%0], [%1], 16;" :: "r"(dst), "l"(src))
#define CP_COMMIT() asm volatile("cp.async.commit_group;" ::: "memory")
#define CP_WAIT(n)  asm volatile("cp.async.wait_group %0;" :: "n"(n) : "memory")

#define LDSM_X4(r0, r1, r2, r3, addr) \
    asm volatile("ldmatrix.sync.aligned.m8n8.x4.shared.b16 {%0,%1,%2,%3}, [%4];" \
                 : "=r"(r0), "=r"(r1), "=r"(r2), "=r"(r3) : "r"(addr))

#define MMA_16816(d, a, b0, b1) \
    asm volatile("mma.sync.aligned.m16n8k16.row.col.f32.f16.f16.f32 " \
                 "{%0,%1,%2,%3}, {%4,%5,%6,%7}, {%8,%9}, {%0,%1,%2,%3};" \
                 : "+f"((d)[0]), "+f"((d)[1]), "+f"((d)[2]), "+f"((d)[3]) \
                 : "r"((a)[0]), "r"((a)[1]), "r"((a)[2]), "r"((a)[3]), \
                   "r"(b0), "r"(b1))

__device__ __forceinline__ float ex2f(float x) {
    float y;
    asm("ex2.approx.ftz.f32 %0, %1;" : "=f"(y) : "f"(x));
    return y;
}

__device__ __forceinline__ uint32_t pack_half(__half a, __half b) {
    __half2 t = __halves2half2(a, b);
    return *(uint32_t*)&t;
}

// 128B-per-row tile (64 fp16 per row): XOR-swizzled 16B chunks within line
__device__ __forceinline__ uint32_t addr128(uint32_t base, int row, int kc) {
    return base + (uint32_t)(row * 128 + ((kc ^ (row & 7)) * 16));
}

// ---------------------------------------------------------------------------
// Conversion kernels
// ---------------------------------------------------------------------------
__global__ void __launch_bounds__(256) split_input_kernel(
    const float4* __restrict__ in, __half2* __restrict__ hi,
    __half2* __restrict__ lo)
{
    const int i = blockIdx.x * 256 + threadIdx.x;
    const float4 v = in[i];
    const __half h0 = __float2half(v.x);
    const __half h1 = __float2half(v.y);
    const __half h2 = __float2half(v.z);
    const __half h3 = __float2half(v.w);
    hi[i * 2 + 0] = __halves2half2(h0, h1);
    hi[i * 2 + 1] = __halves2half2(h2, h3);
    lo[i * 2 + 0] = __halves2half2(__float2half(v.x - __half2float(h0)),
                                   __float2half(v.y - __half2float(h1)));
    lo[i * 2 + 1] = __halves2half2(__float2half(v.z - __half2float(h2)),
                                   __float2half(v.w - __half2float(h3)));
}

// W [1024][N] fp32 -> Wt fp16 [N][1024] (tiled transpose)
__global__ void __launch_bounds__(256) transpose_half_kernel(
    const float* __restrict__ W, int N, __half* __restrict__ T)
{
    __shared__ float t[32][33];
    const int n0 = blockIdx.x * 32;
    const int k0 = blockIdx.y * 32;
    const int tx = threadIdx.x & 31;
    const int ty = threadIdx.x >> 5;
#pragma unroll
    for (int i = 0; i < 32; i += 8)
        t[ty + i][tx] = W[(size_t)(k0 + ty + i) * N + n0 + tx];
    __syncthreads();
#pragma unroll
    for (int i = 0; i < 32; i += 8)
        T[(size_t)(n0 + ty + i) * DM + k0 + tx] = __float2half(t[tx][ty + i]);
}

// prep: Q(scaled) hi/lo, K hi fp16 [bh][s][d]; V hi transposed [bh][d][s]
__global__ void __launch_bounds__(256) prep_kernel()
{
    __shared__ float vs[64][65];
    const int st = blockIdx.x;
    const int bh = (int)blockIdx.y;
    const int b = bh >> 4;
    const int h = bh & 15;
    const int tid = (int)threadIdx.x;

#pragma unroll
    for (int i = 0; i < 16; i++) {
        const int idx = tid + i * 256;
        const int s = idx >> 6;
        const int d = idx & 63;
        const float* src = g_qkv + (size_t)(b * SEQ + st * 64 + s) * TD + h * DH + d;
        const float q = src[0] * SCALE_L2E;
        vs[s][d] = src[2 * DM];
        const size_t o = ((size_t)bh * SEQ + st * 64 + s) * DH + d;
        const __half qh = __float2half(q);
        g_qh[o] = qh;
        g_ql[o] = __float2half(q - __half2float(qh));
        g_kh[o] = __float2half(src[DM]);
    }
    __syncthreads();
#pragma unroll
    for (int i = 0; i < 16; i++) {
        const int idx = tid + i * 256;
        const int d = idx >> 6;
        const int s = idx & 63;
        g_vth[((size_t)bh * DH + d) * SEQ + st * 64 + s] = __float2half(vs[s][d]);
    }
}

// ---------------------------------------------------------------------------
// mma.sync GEMM (fp16): C = [Ahi|Alo](K'<=2048) x [B;B]^T + bias
// CTA tile 128x256, BK=64, 8 warps (2m x 4n), warp tile 64x64.
// 3-stage cp.async pipeline (prefetch depth 2), one barrier per chunk.
// CTAs with n0g >= n_locut run hi-only (16 chunks). n_locut=0 -> whole GEMM
// hi-only.
// ---------------------------------------------------------------------------
#define NCHUNK 32
#define GA(s) ((s) * 16384)              // A stages at 0, 16K, 32K
#define GB(s) (49152 + (s) * 32768)      // B stages at 48K, 80K, 112K
#define GEMM_SMEM_BYTES 147456

__global__ void __launch_bounds__(256, 1) gemm_mma_kernel(
    const __half* __restrict__ Ahi, const __half* __restrict__ Alo,
    const __half* __restrict__ Bh,
    const float* __restrict__ bias, float* __restrict__ C, int Ntot,
    int n_locut)
{
    extern __shared__ uint8_t gsm[];
    const uint32_t sbase = smem_u32(gsm);

    const int tid = (int)threadIdx.x;
    const int wid = tid >> 5;
    const int lane = tid & 31;
    const int wm = wid & 1;          // 64-row half
    const int wn = wid >> 1;         // 64-col slice

    const int m0g = blockIdx.x * 128;
    const int n0g = blockIdx.y * 256;
    const int nch = (n0g >= n_locut) ? (NCHUNK / 2) : NCHUNK;

    float acc[4][8][4];
#pragma unroll
    for (int mt = 0; mt < 4; mt++)
#pragma unroll
        for (int nt = 0; nt < 8; nt++)
#pragma unroll
            for (int j = 0; j < 4; j++) acc[mt][nt][j] = 0.f;

    // chunk c: c<16 -> Ahi, else Alo; k0=(c&15)*64; B always Bh.
    auto stage = [&](int c, int ss) {
        const int k0 = (c & 15) * 64;
        const __half* __restrict__ As = (c >= 16) ? Alo : Ahi;
#pragma unroll
        for (int it = 0; it < 4; ++it) {
            const int idx = tid + it * 256;      // 0..1023
            const int r = idx >> 3;
            const int kc = idx & 7;
            CP_ASYNC16(addr128(sbase + GA(ss), r, kc),
                       As + (size_t)(m0g + r) * DM + k0 + kc * 8);
        }
#pragma unroll
        for (int it = 0; it < 8; ++it) {
            const int idx = tid + it * 256;      // 0..2047
            const int r = idx >> 3;
            const int kc = idx & 7;
            CP_ASYNC16(addr128(sbase + GB(ss), r, kc),
                       Bh + (size_t)(n0g + r) * DM + k0 + kc * 8);
        }
    };

    stage(0, 0);
    CP_COMMIT();
    stage(1, 1);
    CP_COMMIT();

    const int mat = lane >> 3;
    const int arow7 = (lane & 7) + ((mat & 1) << 3);
    const int brow7 = (lane & 7) + ((mat >> 1) << 3);

    for (int c = 0; c < nch; ++c) {
        if (c + 1 < nch) {
            CP_WAIT(1);
        } else {
            CP_WAIT(0);
        }
        __syncthreads();

        if (c + 2 < nch) {
            stage(c + 2, (c + 2) % 3);
            CP_COMMIT();
        }

        const int ss = c % 3;
        const uint32_t abase = sbase + GA(ss);
        const uint32_t bbase = sbase + GB(ss);

#pragma unroll
        for (int ks = 0; ks < 4; ++ks) {
            uint32_t af[4][4];
#pragma unroll
            for (int mt = 0; mt < 4; mt++) {
                const int row = wm * 64 + mt * 16 + arow7;
                const int kc = ks * 2 + (mat >> 1);
                LDSM_X4(af[mt][0], af[mt][1], af[mt][2], af[mt][3],
                        addr128(abase, row, kc));
            }
            uint32_t bf[4][4];
#pragma unroll
            for (int ntp = 0; ntp < 4; ntp++) {
                const int row = wn * 64 + ntp * 16 + brow7;
                const int kc = ks * 2 + (mat & 1);
                LDSM_X4(bf[ntp][0], bf[ntp][1], bf[ntp][2], bf[ntp][3],
                        addr128(bbase, row, kc));
            }
#pragma unroll
            for (int mt = 0; mt < 4; mt++)
#pragma unroll
                for (int nt = 0; nt < 8; nt++)
                    MMA_16816(acc[mt][nt], af[mt],
                              bf[nt >> 1][2 * (nt & 1)], bf[nt >> 1][2 * (nt & 1) + 1]);
        }
    }

    // Epilogue: add bias, store fp32
    const int qrow = lane >> 2;
    const int qcol = (lane & 3) << 1;
    float2 bv[8];
#pragma unroll
    for (int nt = 0; nt < 8; nt++) {
        const int n = n0g + wn * 64 + nt * 8 + qcol;
        bv[nt] = make_float2(bias[n], bias[n + 1]);
    }
#pragma unroll
    for (int mt = 0; mt < 4; mt++) {
        const int r0 = m0g + wm * 64 + mt * 16 + qrow;
#pragma unroll
        for (int nt = 0; nt < 8; nt++) {
            const int n = n0g + wn * 64 + nt * 8 + qcol;
            *(float2*)(C + (size_t)r0 * Ntot + n) =
                make_float2(acc[mt][nt][0] + bv[nt].x, acc[mt][nt][1] + bv[nt].y);
            *(float2*)(C + (size_t)(r0 + 8) * Ntot + n) =
                make_float2(acc[mt][nt][2] + bv[nt].x, acc[mt][nt][3] + bv[nt].y);
        }
    }
}

// ---------------------------------------------------------------------------
// HMMA flash attention (fp16). Block = 128 q-rows x one (b,h).
// S = Qh K^T + Ql K^T (2-term).  PV = Ph V (1-term).
// Output: single fp16 (hi only) — proj GEMM runs hi-only.
// smem: QH 16K + QL 16K + KH dbuf 16K + VH dbuf 16K = 64KB dynamic.
// ---------------------------------------------------------------------------
#define SM_QH 0
#define SM_QL 16384
#define SM_KH(b) (32768 + (b) * 8192)
#define SM_VH(b) (49152 + (b) * 8192)
#define ATTN_SMEM_BYTES 65536

__global__ void __launch_bounds__(256) attn_mma_kernel()
{
    extern __shared__ uint8_t dsm[];
    const uint32_t sb = smem_u32(dsm);
    const int tid = (int)threadIdx.x;
    const int wid = tid >> 5;
    const int lane = tid & 31;
    const int qti = 15 - (int)blockIdx.x;       // heavy tiles first
    const int bh = (int)blockIdx.y;
    const int b = bh >> 4;
    const int h = bh & 15;

    const size_t qkbase = (size_t)bh * SEQ * DH;
    const size_t vbase = (size_t)bh * DH * SEQ;

#pragma unroll
    for (int i = 0; i < 4; i++) {
        const int idx = tid + i * 256;
        const int r = idx >> 3;
        const int kc = idx & 7;
        CP_ASYNC16(addr128(sb + SM_QH, r, kc),
                   g_qh + qkbase + (size_t)(qti * 128 + r) * DH + kc * 8);
        CP_ASYNC16(addr128(sb + SM_QL, r, kc),
                   g_ql + qkbase + (size_t)(qti * 128 + r) * DH + kc * 8);
    }

    const int nkt = 2 * qti + 2;

    auto stage_kv = [&](int kt, int bb) {
#pragma unroll
        for (int i = 0; i < 2; i++) {
            const int idx = tid + i * 256;
            const int r = idx >> 3;
            const int kc = idx & 7;
            CP_ASYNC16(addr128(sb + SM_KH(bb), r, kc),
                       g_kh + qkbase + (size_t)(kt * 64 + r) * DH + kc * 8);
            CP_ASYNC16(addr128(sb + SM_VH(bb), r, kc),
                       g_vth + vbase + (size_t)r * SEQ + kt * 64 + kc * 8);
        }
    };

    stage_kv(0, 0);
    CP_COMMIT();

    float o[8][4];
#pragma unroll
    for (int t = 0; t < 8; t++)
#pragma unroll
        for (int j = 0; j < 4; j++) o[t][j] = 0.f;
    float m_a = NEG_BIG, m_b = NEG_BIG, l_a = 0.f, l_b = 0.f;

    const int qrow_base = qti * 128 + wid * 16;
    const int ra = lane >> 2;
    const int c2 = (lane & 3) << 1;

    int buf = 0;
    for (int kt = 0; kt < nkt; kt++) {
        if (kt + 1 < nkt) {
            stage_kv(kt + 1, buf ^ 1);
            CP_COMMIT();
            CP_WAIT(1);
        } else {
            CP_WAIT(0);
        }
        __syncthreads();

        // ---- S = Q K^T (hi + lo terms) ----
        float s[8][4];
#pragma unroll
        for (int t = 0; t < 8; t++)
#pragma unroll
            for (int j = 0; j < 4; j++) s[t][j] = 0.f;

#pragma unroll
        for (int ks = 0; ks < 4; ks++) {
            const int mat = lane >> 3;
            const int arow = wid * 16 + (lane & 7) + ((mat & 1) << 3);
            const int akc = ks * 2 + (mat >> 1);
            uint32_t aqh[4], aql[4];
            LDSM_X4(aqh[0], aqh[1], aqh[2], aqh[3], addr128(sb + SM_QH, arow, akc));
            LDSM_X4(aql[0], aql[1], aql[2], aql[3], addr128(sb + SM_QL, arow, akc));

            const int brow7 = (lane & 7) + ((mat >> 1) << 3);
            const int bkc = ks * 2 + (mat & 1);
#pragma unroll
            for (int ntp = 0; ntp < 4; ntp++) {
                uint32_t bh4[4];
                LDSM_X4(bh4[0], bh4[1], bh4[2], bh4[3],
                        addr128(sb + SM_KH(buf), ntp * 16 + brow7, bkc));
#pragma unroll
                for (int half = 0; half < 2; half++) {
                    const int nt = ntp * 2 + half;
                    MMA_16816(s[nt], aqh, bh4[2 * half], bh4[2 * half + 1]);
                    MMA_16816(s[nt], aql, bh4[2 * half], bh4[2 * half + 1]);
                }
            }
        }

        // ---- causal mask (max col of tile vs MIN warp row) ----
        if (kt * 64 + 63 > qrow_base) {
#pragma unroll
            for (int t = 0; t < 8; t++) {
                const int col = kt * 64 + t * 8 + c2;
                const int rowa = qrow_base + ra;
                const int rowb = rowa + 8;
                if (col > rowa)     s[t][0] = NEG_BIG;
                if (col + 1 > rowa) s[t][1] = NEG_BIG;
                if (col > rowb)     s[t][2] = NEG_BIG;
                if (col + 1 > rowb) s[t][3] = NEG_BIG;
            }
        }

        // ---- online softmax (log2 domain) ----
        float pa = NEG_BIG, pb = NEG_BIG;
#pragma unroll
        for (int t = 0; t < 8; t++) {
            pa = fmaxf(pa, fmaxf(s[t][0], s[t][1]));
            pb = fmaxf(pb, fmaxf(s[t][2], s[t][3]));
        }
        pa = fmaxf(pa, __shfl_xor_sync(0xffffffffu, pa, 1));
        pa = fmaxf(pa, __shfl_xor_sync(0xffffffffu, pa, 2));
        pb = fmaxf(pb, __shfl_xor_sync(0xffffffffu, pb, 1));
        pb = fmaxf(pb, __shfl_xor_sync(0xffffffffu, pb, 2));
        const float nm_a = fmaxf(m_a, pa);
        const float nm_b = fmaxf(m_b, pb);
        const float al_a = ex2f(m_a - nm_a);
        const float al_b = ex2f(m_b - nm_b);
        m_a = nm_a;
        m_b = nm_b;

        float sum_a = 0.f, sum_b = 0.f;
#pragma unroll
        for (int t = 0; t < 8; t++) {
            s[t][0] = ex2f(s[t][0] - nm_a);
            s[t][1] = ex2f(s[t][1] - nm_a);
            s[t][2] = ex2f(s[t][2] - nm_b);
            s[t][3] = ex2f(s[t][3] - nm_b);
            sum_a += s[t][0] + s[t][1];
            sum_b += s[t][2] + s[t][3];
        }
        sum_a += __shfl_xor_sync(0xffffffffu, sum_a, 1);
        sum_a += __shfl_xor_sync(0xffffffffu, sum_a, 2);
        sum_b += __shfl_xor_sync(0xffffffffu, sum_b, 1);
        sum_b += __shfl_xor_sync(0xffffffffu, sum_b, 2);
        l_a = l_a * al_a + sum_a;
        l_b = l_b * al_b + sum_b;
#pragma unroll
        for (int t = 0; t < 8; t++) {
            o[t][0] *= al_a;
            o[t][1] *= al_a;
            o[t][2] *= al_b;
            o[t][3] *= al_b;
        }

        // ---- repack P into A fragments (hi only, fp16) ----
        uint32_t phi[4][4];
#pragma unroll
        for (int ks = 0; ks < 4; ks++) {
#pragma unroll
            for (int half = 0; half < 2; half++) {
                const int t = 2 * ks + half;
                phi[ks][2 * half + 0] = pack_half(__float2half(s[t][0]),
                                                  __float2half(s[t][1]));
                phi[ks][2 * half + 1] = pack_half(__float2half(s[t][2]),
                                                  __float2half(s[t][3]));
            }
        }

        // ---- O += P V (single term) ----
        const int mat = lane >> 3;
        const int vrow7 = (lane & 7) + ((mat >> 1) << 3);
#pragma unroll
        for (int ks = 0; ks < 4; ks++) {
            const int vkc = ks * 2 + (mat & 1);
#pragma unroll
            for (int ntp = 0; ntp < 4; ntp++) {
                uint32_t vh4[4];
                LDSM_X4(vh4[0], vh4[1], vh4[2], vh4[3],
                        addr128(sb + SM_VH(buf), ntp * 16 + vrow7, vkc));
#pragma unroll
                for (int half = 0; half < 2; half++) {
                    const int nt = ntp * 2 + half;
                    MMA_16816(o[nt], phi[ks], vh4[2 * half], vh4[2 * half + 1]);
                }
            }
        }

        __syncthreads();
        buf ^= 1;
    }

    // ---- epilogue: normalize, fp16 (hi only) for proj GEMM ----
    const float inv_a = 1.f / l_a;
    const float inv_b = 1.f / l_b;
#pragma unroll
    for (int t = 0; t < 8; t++) {
        const int col = h * DH + t * 8 + c2;
        const int rowa = qti * 128 + wid * 16 + ra;
        *(__half2*)(g_ahi + (size_t)(b * SEQ + rowa) * DM + col) =
            __halves2half2(__float2half(o[t][0] * inv_a),
                           __float2half(o[t][1] * inv_a));
        *(__half2*)(g_ahi + (size_t)(b * SEQ + rowa + 8) * DM + col) =
            __halves2half2(__float2half(o[t][2] * inv_b),
                           __float2half(o[t][3] * inv_b));
    }
}

// ---------------------------------------------------------------------------
extern "C" void kernel_launch(void* const* d_in, const int* in_sizes, int n_in,
                              void* d_out, int out_size)
{
    const float* input = (const float*)d_in[0];
    const float* W_qkv = (const float*)d_in[1];
    const float* b_qkv = (const float*)d_in[2];
    const float* W_out = (const float*)d_in[3];
    const float* b_out = (const float*)d_in[4];
    float* out = (float*)d_out;

    cudaFuncSetAttribute(attn_mma_kernel,
                         cudaFuncAttributeMaxDynamicSharedMemorySize, ATTN_SMEM_BYTES);
    cudaFuncSetAttribute(gemm_mma_kernel,
                         cudaFuncAttributeMaxDynamicSharedMemorySize, GEMM_SMEM_BYTES);

    __half *xhi, *xlo, *wqT, *woT, *ahi;
    float* qkv;
    cudaGetSymbolAddress((void**)&xhi, g_xhi);
    cudaGetSymbolAddress((void**)&xlo, g_xlo);
    cudaGetSymbolAddress((void**)&wqT, g_wqkvT);
    cudaGetSymbolAddress((void**)&woT, g_woutT);
    cudaGetSymbolAddress((void**)&ahi, g_ahi);
    cudaGetSymbolAddress((void**)&qkv, g_qkv);

    split_input_kernel<<<(MROWS * DM / 4) / 256, 256>>>(
        (const float4*)input, (__half2*)xhi, (__half2*)xlo);
    transpose_half_kernel<<<dim3(TD / 32, DM / 32), 256>>>(W_qkv, TD, wqT);
    transpose_half_kernel<<<dim3(DM / 32, DM / 32), 256>>>(W_out, DM, woT);

    // qkv: lo-correction only for Q columns (n < 1024); K & V are rounded to
    // a single fp16 downstream, so their correction term is wasted work.
    gemm_mma_kernel<<<dim3(MROWS / 128, TD / 256), 256, GEMM_SMEM_BYTES>>>(
        xhi, xlo, wqT, b_qkv, qkv, TD, DM);

    prep_kernel<<<dim3(SEQ / 64, NBH), 256>>>();

    attn_mma_kernel<<<dim3(SEQ / 128, NBH), 256, ATTN_SMEM_BYTES>>>();

    // proj: hi-only (attention output error is fp16-class regardless)
    gemm_mma_kernel<<<dim3(MROWS / 128, DM / 256), 256, GEMM_SMEM_BYTES>>>(
        ahi, ahi, woT, b_out, out, DM, 0);
}

// round 12
// speedup vs baseline: 7.1734x; 1.2837x over previous
#include <cuda_runtime.h>
#include <cuda_fp16.h>
#include <cstdint>

#define BSZ 4
#define SEQ 2048
#define NH 16
#define DH 64
#define DM 1024
#define TD 3072
#define MROWS (BSZ * SEQ)
#define NBH (BSZ * NH)

#define NEG_BIG (-1e30f)
#define SCALE_L2E 0.18033688011112042f   // 0.125 * log2(e)

// ---------------------------------------------------------------------------
// Scratch (__device__ globals; no allocation allowed)
// ---------------------------------------------------------------------------
__device__ __half g_xhi[(size_t)MROWS * DM];           // input fp16
__device__ __half g_wqkvT[(size_t)TD * DM];            // W_qkv^T fp16 [3072][1024]
__device__ __half g_woutT[(size_t)DM * DM];            // W_out^T fp16 [1024][1024]
__device__ __half g_ahi[(size_t)MROWS * DM];           // attention out fp16
// per-head fp16 (bh-major), written directly by qkv GEMM epilogue
__device__ __half g_qh[(size_t)NBH * SEQ * DH];        // [bh][s][d], pre-scaled
__device__ __half g_kh[(size_t)NBH * SEQ * DH];        // [bh][s][d]
__device__ __half g_vh[(size_t)NBH * SEQ * DH];        // [bh][s][d] (NOT transposed)

// ---------------------------------------------------------------------------
// PTX helpers (valid for target sm_100)
// ---------------------------------------------------------------------------
__device__ __forceinline__ uint32_t smem_u32(const void* p) {
    uint32_t a;
    asm("{ .reg .u64 t; cvta.to.shared.u64 t, %1; cvt.u32.u64 %0, t; }" : "=r"(a) : "l"(p));
    return a;
}

#define CP_ASYNC16(dst, src) \
    asm volatile("cp.async.cg.shared.global [%0], [%1], 16;" :: "r"(dst), "l"(src))
#define CP_COMMIT() asm volatile("cp.async.commit_group;" ::: "memory")
#define CP_WAIT(n)  asm volatile("cp.async.wait_group %0;" :: "n"(n) : "memory")

#define LDSM_X4(r0, r1, r2, r3, addr) \
    asm volatile("ldmatrix.sync.aligned.m8n8.x4.shared.b16 {%0,%1,%2,%3}, [%4];" \
                 : "=r"(r0), "=r"(r1), "=r"(r2), "=r"(r3) : "r"(addr))

#define LDSM_X4T(r0, r1, r2, r3, addr) \
    asm volatile("ldmatrix.sync.aligned.m8n8.x4.trans.shared.b16 {%0,%1,%2,%3}, [%4];" \
                 : "=r"(r0), "=r"(r1), "=r"(r2), "=r"(r3) : "r"(addr))

#define MMA_16816(d, a, b0, b1) \
    asm volatile("mma.sync.aligned.m16n8k16.row.col.f32.f16.f16.f32 " \
                 "{%0,%1,%2,%3}, {%4,%5,%6,%7}, {%8,%9}, {%0,%1,%2,%3};" \
                 : "+f"((d)[0]), "+f"((d)[1]), "+f"((d)[2]), "+f"((d)[3]) \
                 : "r"((a)[0]), "r"((a)[1]), "r"((a)[2]), "r"((a)[3]), \
                   "r"(b0), "r"(b1))

__device__ __forceinline__ float ex2f(float x) {
    float y;
    asm("ex2.approx.ftz.f32 %0, %1;" : "=f"(y) : "f"(x));
    return y;
}

__device__ __forceinline__ uint32_t pack_half(__half a, __half b) {
    __half2 t = __halves2half2(a, b);
    return *(uint32_t*)&t;
}

// 128B-per-row tile (64 fp16 per row): XOR-swizzled 16B chunks within line
__device__ __forceinline__ uint32_t addr128(uint32_t base, int row, int kc) {
    return base + (uint32_t)(row * 128 + ((kc ^ (row & 7)) * 16));
}

// ---------------------------------------------------------------------------
// Conversion kernels
// ---------------------------------------------------------------------------
__global__ void __launch_bounds__(256) convert_input_kernel(
    const float4* __restrict__ in, __half2* __restrict__ hi)
{
    const int i = blockIdx.x * 256 + threadIdx.x;
    const float4 v = in[i];
    hi[i * 2 + 0] = __halves2half2(__float2half(v.x), __float2half(v.y));
    hi[i * 2 + 1] = __halves2half2(__float2half(v.z), __float2half(v.w));
}

// W [1024][N] fp32 -> Wt fp16 [N][1024] (tiled transpose)
__global__ void __launch_bounds__(256) transpose_half_kernel(
    const float* __restrict__ W, int N, __half* __restrict__ T)
{
    __shared__ float t[32][33];
    const int n0 = blockIdx.x * 32;
    const int k0 = blockIdx.y * 32;
    const int tx = threadIdx.x & 31;
    const int ty = threadIdx.x >> 5;
#pragma unroll
    for (int i = 0; i < 32; i += 8)
        t[ty + i][tx] = W[(size_t)(k0 + ty + i) * N + n0 + tx];
    __syncthreads();
#pragma unroll
    for (int i = 0; i < 32; i += 8)
        T[(size_t)(n0 + ty + i) * DM + k0 + tx] = __float2half(t[tx][ty + i]);
}

// ---------------------------------------------------------------------------
// mma.sync GEMM (fp16 hi-only): C = A x B^T + bias
// CTA tile 128x256, BK=64, 8 warps (2m x 4n), warp tile 64x64, 16 chunks.
// 3-stage cp.async pipeline (prefetch depth 2), one barrier per chunk.
// mode 0: fp32 C.  mode 1 (qkv): write fp16 Q(scaled)/K/V [bh][s][d] direct.
// ---------------------------------------------------------------------------
#define NCHUNK 16
#define GA(s) ((s) * 16384)              // A stages at 0, 16K, 32K
#define GB(s) (49152 + (s) * 32768)      // B stages at 48K, 80K, 112K
#define GEMM_SMEM_BYTES 147456

__device__ __forceinline__ void store_qkv_half2(
    __half* __restrict__ qh, __half* __restrict__ kh, __half* __restrict__ vh,
    int r, int n, float v0, float v1)
{
    const int b = r >> 11;               // / SEQ
    const int s = r & (SEQ - 1);
    const int type = n >> 10;
    const int h = (n >> 6) & 15;
    const int d = n & 63;
    const size_t off = ((size_t)(b * NH + h) * SEQ + s) * DH + d;
    if (type == 0) {
        *(__half2*)(qh + off) = __halves2half2(__float2half(v0 * SCALE_L2E),
                                               __float2half(v1 * SCALE_L2E));
    } else if (type == 1) {
        *(__half2*)(kh + off) = __halves2half2(__float2half(v0), __float2half(v1));
    } else {
        *(__half2*)(vh + off) = __halves2half2(__float2half(v0), __float2half(v1));
    }
}

__global__ void __launch_bounds__(256, 1) gemm_mma_kernel(
    const __half* __restrict__ A, const __half* __restrict__ Bh,
    const float* __restrict__ bias, float* __restrict__ C, int Ntot,
    __half* __restrict__ qh, __half* __restrict__ kh, __half* __restrict__ vh,
    int mode)
{
    extern __shared__ uint8_t gsm[];
    const uint32_t sbase = smem_u32(gsm);

    const int tid = (int)threadIdx.x;
    const int wid = tid >> 5;
    const int lane = tid & 31;
    const int wm = wid & 1;          // 64-row half
    const int wn = wid >> 1;         // 64-col slice

    const int m0g = blockIdx.x * 128;
    const int n0g = blockIdx.y * 256;

    float acc[4][8][4];
#pragma unroll
    for (int mt = 0; mt < 4; mt++)
#pragma unroll
        for (int nt = 0; nt < 8; nt++)
#pragma unroll
            for (int j = 0; j < 4; j++) acc[mt][nt][j] = 0.f;

    auto stage = [&](int c, int ss) {
        const int k0 = c * 64;
#pragma unroll
        for (int it = 0; it < 4; ++it) {
            const int idx = tid + it * 256;      // 0..1023
            const int r = idx >> 3;
            const int kc = idx & 7;
            CP_ASYNC16(addr128(sbase + GA(ss), r, kc),
                       A + (size_t)(m0g + r) * DM + k0 + kc * 8);
        }
#pragma unroll
        for (int it = 0; it < 8; ++it) {
            const int idx = tid + it * 256;      // 0..2047
            const int r = idx >> 3;
            const int kc = idx & 7;
            CP_ASYNC16(addr128(sbase + GB(ss), r, kc),
                       Bh + (size_t)(n0g + r) * DM + k0 + kc * 8);
        }
    };

    stage(0, 0);
    CP_COMMIT();
    stage(1, 1);
    CP_COMMIT();

    const int mat = lane >> 3;
    const int arow7 = (lane & 7) + ((mat & 1) << 3);
    const int brow7 = (lane & 7) + ((mat >> 1) << 3);

    for (int c = 0; c < NCHUNK; ++c) {
        if (c + 1 < NCHUNK) {
            CP_WAIT(1);
        } else {
            CP_WAIT(0);
        }
        __syncthreads();

        if (c + 2 < NCHUNK) {
            stage(c + 2, (c + 2) % 3);
            CP_COMMIT();
        }

        const int ss = c % 3;
        const uint32_t abase = sbase + GA(ss);
        const uint32_t bbase = sbase + GB(ss);

#pragma unroll
        for (int ks = 0; ks < 4; ++ks) {
            uint32_t af[4][4];
#pragma unroll
            for (int mt = 0; mt < 4; mt++) {
                const int row = wm * 64 + mt * 16 + arow7;
                const int kc = ks * 2 + (mat >> 1);
                LDSM_X4(af[mt][0], af[mt][1], af[mt][2], af[mt][3],
                        addr128(abase, row, kc));
            }
            uint32_t bf[4][4];
#pragma unroll
            for (int ntp = 0; ntp < 4; ntp++) {
                const int row = wn * 64 + ntp * 16 + brow7;
                const int kc = ks * 2 + (mat & 1);
                LDSM_X4(bf[ntp][0], bf[ntp][1], bf[ntp][2], bf[ntp][3],
                        addr128(bbase, row, kc));
            }
#pragma unroll
            for (int mt = 0; mt < 4; mt++)
#pragma unroll
                for (int nt = 0; nt < 8; nt++)
                    MMA_16816(acc[mt][nt], af[mt],
                              bf[nt >> 1][2 * (nt & 1)], bf[nt >> 1][2 * (nt & 1) + 1]);
        }
    }

    // Epilogue
    const int qrow = lane >> 2;
    const int qcol = (lane & 3) << 1;
    float2 bv[8];
#pragma unroll
    for (int nt = 0; nt < 8; nt++) {
        const int n = n0g + wn * 64 + nt * 8 + qcol;
        bv[nt] = make_float2(bias[n], bias[n + 1]);
    }
    if (mode == 0) {
#pragma unroll
        for (int mt = 0; mt < 4; mt++) {
            const int r0 = m0g + wm * 64 + mt * 16 + qrow;
#pragma unroll
            for (int nt = 0; nt < 8; nt++) {
                const int n = n0g + wn * 64 + nt * 8 + qcol;
                *(float2*)(C + (size_t)r0 * Ntot + n) =
                    make_float2(acc[mt][nt][0] + bv[nt].x, acc[mt][nt][1] + bv[nt].y);
                *(float2*)(C + (size_t)(r0 + 8) * Ntot + n) =
                    make_float2(acc[mt][nt][2] + bv[nt].x, acc[mt][nt][3] + bv[nt].y);
            }
        }
    } else {
#pragma unroll
        for (int mt = 0; mt < 4; mt++) {
            const int r0 = m0g + wm * 64 + mt * 16 + qrow;
#pragma unroll
            for (int nt = 0; nt < 8; nt++) {
                const int n = n0g + wn * 64 + nt * 8 + qcol;
                store_qkv_half2(qh, kh, vh, r0, n,
                                acc[mt][nt][0] + bv[nt].x, acc[mt][nt][1] + bv[nt].y);
                store_qkv_half2(qh, kh, vh, r0 + 8, n,
                                acc[mt][nt][2] + bv[nt].x, acc[mt][nt][3] + bv[nt].y);
            }
        }
    }
}

// ---------------------------------------------------------------------------
// HMMA flash attention (fp16, single-term). Block = 128 q-rows x one (b,h).
// S = Q K^T.  PV = P V with V [s][d] via ldmatrix.trans (no pre-transpose).
// smem: QH 16K + KH dbuf 2x8K + VH dbuf 2x8K = 48KB dynamic.
// ---------------------------------------------------------------------------
#define SM_QH 0
#define SM_KH(b) (16384 + (b) * 8192)
#define SM_VH(b) (32768 + (b) * 8192)
#define ATTN_SMEM_BYTES 49152

__global__ void __launch_bounds__(256) attn_mma_kernel()
{
    extern __shared__ uint8_t dsm[];
    const uint32_t sb = smem_u32(dsm);
    const int tid = (int)threadIdx.x;
    const int wid = tid >> 5;
    const int lane = tid & 31;
    const int qti = 15 - (int)blockIdx.x;       // heavy tiles first
    const int bh = (int)blockIdx.y;
    const int b = bh >> 4;
    const int h = bh & 15;

    const size_t base = (size_t)bh * SEQ * DH;

#pragma unroll
    for (int i = 0; i < 4; i++) {
        const int idx = tid + i * 256;
        const int r = idx >> 3;
        const int kc = idx & 7;
        CP_ASYNC16(addr128(sb + SM_QH, r, kc),
                   g_qh + base + (size_t)(qti * 128 + r) * DH + kc * 8);
    }

    const int nkt = 2 * qti + 2;

    auto stage_kv = [&](int kt, int bb) {
#pragma unroll
        for (int i = 0; i < 2; i++) {
            const int idx = tid + i * 256;
            const int r = idx >> 3;
            const int kc = idx & 7;
            const size_t o = base + (size_t)(kt * 64 + r) * DH + kc * 8;
            CP_ASYNC16(addr128(sb + SM_KH(bb), r, kc), g_kh + o);
            CP_ASYNC16(addr128(sb + SM_VH(bb), r, kc), g_vh + o);
        }
    };

    stage_kv(0, 0);
    CP_COMMIT();

    float o[8][4];
#pragma unroll
    for (int t = 0; t < 8; t++)
#pragma unroll
        for (int j = 0; j < 4; j++) o[t][j] = 0.f;
    float m_a = NEG_BIG, m_b = NEG_BIG, l_a = 0.f, l_b = 0.f;

    const int qrow_base = qti * 128 + wid * 16;
    const int ra = lane >> 2;
    const int c2 = (lane & 3) << 1;

    int buf = 0;
    for (int kt = 0; kt < nkt; kt++) {
        if (kt + 1 < nkt) {
            stage_kv(kt + 1, buf ^ 1);
            CP_COMMIT();
            CP_WAIT(1);
        } else {
            CP_WAIT(0);
        }
        __syncthreads();

        // ---- S = Q K^T (single term) ----
        float s[8][4];
#pragma unroll
        for (int t = 0; t < 8; t++)
#pragma unroll
            for (int j = 0; j < 4; j++) s[t][j] = 0.f;

        const int mat = lane >> 3;
#pragma unroll
        for (int ks = 0; ks < 4; ks++) {
            const int arow = wid * 16 + (lane & 7) + ((mat & 1) << 3);
            const int akc = ks * 2 + (mat >> 1);
            uint32_t aqh[4];
            LDSM_X4(aqh[0], aqh[1], aqh[2], aqh[3], addr128(sb + SM_QH, arow, akc));

            const int brow7 = (lane & 7) + ((mat >> 1) << 3);
            const int bkc = ks * 2 + (mat & 1);
#pragma unroll
            for (int ntp = 0; ntp < 4; ntp++) {
                uint32_t bh4[4];
                LDSM_X4(bh4[0], bh4[1], bh4[2], bh4[3],
                        addr128(sb + SM_KH(buf), ntp * 16 + brow7, bkc));
#pragma unroll
                for (int half = 0; half < 2; half++) {
                    const int nt = ntp * 2 + half;
                    MMA_16816(s[nt], aqh, bh4[2 * half], bh4[2 * half + 1]);
                }
            }
        }

        // ---- causal mask (max col of tile vs MIN warp row) ----
        if (kt * 64 + 63 > qrow_base) {
#pragma unroll
            for (int t = 0; t < 8; t++) {
                const int col = kt * 64 + t * 8 + c2;
                const int rowa = qrow_base + ra;
                const int rowb = rowa + 8;
                if (col > rowa)     s[t][0] = NEG_BIG;
                if (col + 1 > rowa) s[t][1] = NEG_BIG;
                if (col > rowb)     s[t][2] = NEG_BIG;
                if (col + 1 > rowb) s[t][3] = NEG_BIG;
            }
        }

        // ---- online softmax (log2 domain) ----
        float pa = NEG_BIG, pb = NEG_BIG;
#pragma unroll
        for (int t = 0; t < 8; t++) {
            pa = fmaxf(pa, fmaxf(s[t][0], s[t][1]));
            pb = fmaxf(pb, fmaxf(s[t][2], s[t][3]));
        }
        pa = fmaxf(pa, __shfl_xor_sync(0xffffffffu, pa, 1));
        pa = fmaxf(pa, __shfl_xor_sync(0xffffffffu, pa, 2));
        pb = fmaxf(pb, __shfl_xor_sync(0xffffffffu, pb, 1));
        pb = fmaxf(pb, __shfl_xor_sync(0xffffffffu, pb, 2));
        const float nm_a = fmaxf(m_a, pa);
        const float nm_b = fmaxf(m_b, pb);
        const float al_a = ex2f(m_a - nm_a);
        const float al_b = ex2f(m_b - nm_b);
        m_a = nm_a;
        m_b = nm_b;

        float sum_a = 0.f, sum_b = 0.f;
#pragma unroll
        for (int t = 0; t < 8; t++) {
            s[t][0] = ex2f(s[t][0] - nm_a);
            s[t][1] = ex2f(s[t][1] - nm_a);
            s[t][2] = ex2f(s[t][2] - nm_b);
            s[t][3] = ex2f(s[t][3] - nm_b);
            sum_a += s[t][0] + s[t][1];
            sum_b += s[t][2] + s[t][3];
        }
        sum_a += __shfl_xor_sync(0xffffffffu, sum_a, 1);
        sum_a += __shfl_xor_sync(0xffffffffu, sum_a, 2);
        sum_b += __shfl_xor_sync(0xffffffffu, sum_b, 1);
        sum_b += __shfl_xor_sync(0xffffffffu, sum_b, 2);
        l_a = l_a * al_a + sum_a;
        l_b = l_b * al_b + sum_b;
#pragma unroll
        for (int t = 0; t < 8; t++) {
            o[t][0] *= al_a;
            o[t][1] *= al_a;
            o[t][2] *= al_b;
            o[t][3] *= al_b;
        }

        // ---- repack P into A fragments (fp16) ----
        uint32_t phi[4][4];
#pragma unroll
        for (int ks = 0; ks < 4; ks++) {
#pragma unroll
            for (int half = 0; half < 2; half++) {
                const int t = 2 * ks + half;
                phi[ks][2 * half + 0] = pack_half(__float2half(s[t][0]),
                                                  __float2half(s[t][1]));
                phi[ks][2 * half + 1] = pack_half(__float2half(s[t][2]),
                                                  __float2half(s[t][3]));
            }
        }

        // ---- O += P V, V in [s][d] via trans-ldmatrix ----
        // matrix m covers (d = ntp*16 + 8*(m>>1) + 0..7, s = ks*16 + 8*(m&1) + 0..7)
        const int vsrow7 = (lane & 7) + ((mat & 1) << 3);
#pragma unroll
        for (int ks = 0; ks < 4; ks++) {
            const int srow = ks * 16 + vsrow7;
#pragma unroll
            for (int ntp = 0; ntp < 4; ntp++) {
                const int vkc = ntp * 2 + (mat >> 1);
                uint32_t v4[4];
                LDSM_X4T(v4[0], v4[1], v4[2], v4[3],
                         addr128(sb + SM_VH(buf), srow, vkc));
#pragma unroll
                for (int half = 0; half < 2; half++) {
                    const int nt = ntp * 2 + half;
                    MMA_16816(o[nt], phi[ks], v4[2 * half], v4[2 * half + 1]);
                }
            }
        }

        __syncthreads();
        buf ^= 1;
    }

    // ---- epilogue: normalize, fp16 for proj GEMM ----
    const float inv_a = 1.f / l_a;
    const float inv_b = 1.f / l_b;
#pragma unroll
    for (int t = 0; t < 8; t++) {
        const int col = h * DH + t * 8 + c2;
        const int rowa = qti * 128 + wid * 16 + ra;
        *(__half2*)(g_ahi + (size_t)(b * SEQ + rowa) * DM + col) =
            __halves2half2(__float2half(o[t][0] * inv_a),
                           __float2half(o[t][1] * inv_a));
        *(__half2*)(g_ahi + (size_t)(b * SEQ + rowa + 8) * DM + col) =
            __halves2half2(__float2half(o[t][2] * inv_b),
                           __float2half(o[t][3] * inv_b));
    }
}

// ---------------------------------------------------------------------------
extern "C" void kernel_launch(void* const* d_in, const int* in_sizes, int n_in,
                              void* d_out, int out_size)
{
    const float* input = (const float*)d_in[0];
    const float* W_qkv = (const float*)d_in[1];
    const float* b_qkv = (const float*)d_in[2];
    const float* W_out = (const float*)d_in[3];
    const float* b_out = (const float*)d_in[4];
    float* out = (float*)d_out;

    cudaFuncSetAttribute(attn_mma_kernel,
                         cudaFuncAttributeMaxDynamicSharedMemorySize, ATTN_SMEM_BYTES);
    cudaFuncSetAttribute(gemm_mma_kernel,
                         cudaFuncAttributeMaxDynamicSharedMemorySize, GEMM_SMEM_BYTES);

    __half *xhi, *wqT, *woT, *ahi, *qh, *kh, *vh;
    cudaGetSymbolAddress((void**)&xhi, g_xhi);
    cudaGetSymbolAddress((void**)&wqT, g_wqkvT);
    cudaGetSymbolAddress((void**)&woT, g_woutT);
    cudaGetSymbolAddress((void**)&ahi, g_ahi);
    cudaGetSymbolAddress((void**)&qh, g_qh);
    cudaGetSymbolAddress((void**)&kh, g_kh);
    cudaGetSymbolAddress((void**)&vh, g_vh);

    convert_input_kernel<<<(MROWS * DM / 4) / 256, 256>>>(
        (const float4*)input, (__half2*)xhi);
    transpose_half_kernel<<<dim3(TD / 32, DM / 32), 256>>>(W_qkv, TD, wqT);
    transpose_half_kernel<<<dim3(DM / 32, DM / 32), 256>>>(W_out, DM, woT);

    // qkv: hi-only; epilogue writes fp16 Q(scaled)/K/V [bh][s][d] directly
    gemm_mma_kernel<<<dim3(MROWS / 128, TD / 256), 256, GEMM_SMEM_BYTES>>>(
        xhi, wqT, b_qkv, nullptr, TD, qh, kh, vh, 1);

    attn_mma_kernel<<<dim3(SEQ / 128, NBH), 256, ATTN_SMEM_BYTES>>>();

    // proj: hi-only, fp32 out
    gemm_mma_kernel<<<dim3(MROWS / 128, DM / 256), 256, GEMM_SMEM_BYTES>>>(
        ahi, woT, b_out, out, DM, qh, kh, vh, 0);
}

// round 13
// speedup vs baseline: 7.4807x; 1.0428x over previous
#include <cuda_runtime.h>
#include <cuda_fp16.h>
#include <cstdint>

#define BSZ 4
#define SEQ 2048
#define NH 16
#define DH 64
#define DM 1024
#define TD 3072
#define MROWS (BSZ * SEQ)
#define NBH (BSZ * NH)

#define NEG_BIG (-1e30f)
#define SCALE_L2E 0.18033688011112042f   // 0.125 * log2(e)

// ---------------------------------------------------------------------------
// Scratch (__device__ globals; no allocation allowed)
// ---------------------------------------------------------------------------
__device__ __half g_xhi[(size_t)MROWS * DM];           // input fp16
__device__ __half g_wqkvT[(size_t)TD * DM];            // W_qkv^T fp16 [3072][1024]
__device__ __half g_woutT[(size_t)DM * DM];            // W_out^T fp16 [1024][1024]
__device__ __half g_ahi[(size_t)MROWS * DM];           // attention out fp16
// per-head fp16 (bh-major), written directly by qkv GEMM epilogue
__device__ __half g_qh[(size_t)NBH * SEQ * DH];        // [bh][s][d], pre-scaled
__device__ __half g_kh[(size_t)NBH * SEQ * DH];        // [bh][s][d]
__device__ __half g_vh[(size_t)NBH * SEQ * DH];        // [bh][s][d] (NOT transposed)

// ---------------------------------------------------------------------------
// PTX helpers (valid for target sm_100)
// ---------------------------------------------------------------------------
__device__ __forceinline__ uint32_t smem_u32(const void* p) {
    uint32_t a;
    asm("{ .reg .u64 t; cvta.to.shared.u64 t, %1; cvt.u32.u64 %0, t; }" : "=r"(a) : "l"(p));
    return a;
}

#define CP_ASYNC16(dst, src) \
    asm volatile("cp.async.cg.shared.global [%0], [%1], 16;" :: "r"(dst), "l"(src))
#define CP_COMMIT() asm volatile("cp.async.commit_group;" ::: "memory")
#define CP_WAIT(n)  asm volatile("cp.async.wait_group %0;" :: "n"(n) : "memory")

#define LDSM_X4(r0, r1, r2, r3, addr) \
    asm volatile("ldmatrix.sync.aligned.m8n8.x4.shared.b16 {%0,%1,%2,%3}, [%4];" \
                 : "=r"(r0), "=r"(r1), "=r"(r2), "=r"(r3) : "r"(addr))

#define LDSM_X4T(r0, r1, r2, r3, addr) \
    asm volatile("ldmatrix.sync.aligned.m8n8.x4.trans.shared.b16 {%0,%1,%2,%3}, [%4];" \
                 : "=r"(r0), "=r"(r1), "=r"(r2), "=r"(r3) : "r"(addr))

#define MMA_16816(d, a, b0, b1) \
    asm volatile("mma.sync.aligned.m16n8k16.row.col.f32.f16.f16.f32 " \
                 "{%0,%1,%2,%3}, {%4,%5,%6,%7}, {%8,%9}, {%0,%1,%2,%3};" \
                 : "+f"((d)[0]), "+f"((d)[1]), "+f"((d)[2]), "+f"((d)[3]) \
                 : "r"((a)[0]), "r"((a)[1]), "r"((a)[2]), "r"((a)[3]), \
                   "r"(b0), "r"(b1))

__device__ __forceinline__ float ex2f(float x) {
    float y;
    asm("ex2.approx.ftz.f32 %0, %1;" : "=f"(y) : "f"(x));
    return y;
}

__device__ __forceinline__ uint32_t pack_half(__half a, __half b) {
    __half2 t = __halves2half2(a, b);
    return *(uint32_t*)&t;
}

// 128B-per-row tile (64 fp16 per row): XOR-swizzled 16B chunks within line
__device__ __forceinline__ uint32_t addr128(uint32_t base, int row, int kc) {
    return base + (uint32_t)(row * 128 + ((kc ^ (row & 7)) * 16));
}

// ---------------------------------------------------------------------------
// Conversion kernels
// ---------------------------------------------------------------------------
__global__ void __launch_bounds__(256) convert_input_kernel(
    const float4* __restrict__ in, __half2* __restrict__ hi)
{
    const int i = blockIdx.x * 256 + threadIdx.x;
    const float4 v = in[i];
    hi[i * 2 + 0] = __halves2half2(__float2half(v.x), __float2half(v.y));
    hi[i * 2 + 1] = __halves2half2(__float2half(v.z), __float2half(v.w));
}

// W [1024][N] fp32 -> Wt fp16 [N][1024] (tiled transpose)
__global__ void __launch_bounds__(256) transpose_half_kernel(
    const float* __restrict__ W, int N, __half* __restrict__ T)
{
    __shared__ float t[32][33];
    const int n0 = blockIdx.x * 32;
    const int k0 = blockIdx.y * 32;
    const int tx = threadIdx.x & 31;
    const int ty = threadIdx.x >> 5;
#pragma unroll
    for (int i = 0; i < 32; i += 8)
        t[ty + i][tx] = W[(size_t)(k0 + ty + i) * N + n0 + tx];
    __syncthreads();
#pragma unroll
    for (int i = 0; i < 32; i += 8)
        T[(size_t)(n0 + ty + i) * DM + k0 + tx] = __float2half(t[tx][ty + i]);
}

// ---------------------------------------------------------------------------
// mma.sync GEMM (fp16): C = A x B^T + bias
// CTA tile 128x256, BK=64, 8 warps (2m x 4n), warp tile 64x64, 16 chunks.
// 3-stage cp.async pipeline (prefetch depth 2), one barrier per chunk.
// mode 0: fp32 C.
// mode 1 (qkv): restage fp16 tile in smem, then coalesced 16B stores into
//               Q(scaled)/K/V [bh][s][d].
// ---------------------------------------------------------------------------
#define NCHUNK 16
#define GA(s) ((s) * 16384)              // A stages at 0, 16K, 32K
#define GB(s) (49152 + (s) * 32768)      // B stages at 48K, 80K, 112K
#define GEMM_SMEM_BYTES 147456
#define EPI_STRIDE 528                   // 256 fp16 = 512B + 16B pad

__global__ void __launch_bounds__(256, 1) gemm_mma_kernel(
    const __half* __restrict__ A, const __half* __restrict__ Bh,
    const float* __restrict__ bias, float* __restrict__ C, int Ntot,
    __half* __restrict__ qh, __half* __restrict__ kh, __half* __restrict__ vh,
    int mode)
{
    extern __shared__ uint8_t gsm[];
    const uint32_t sbase = smem_u32(gsm);

    const int tid = (int)threadIdx.x;
    const int wid = tid >> 5;
    const int lane = tid & 31;
    const int wm = wid & 1;          // 64-row half
    const int wn = wid >> 1;         // 64-col slice

    const int m0g = blockIdx.x * 128;
    const int n0g = blockIdx.y * 256;

    float acc[4][8][4];
#pragma unroll
    for (int mt = 0; mt < 4; mt++)
#pragma unroll
        for (int nt = 0; nt < 8; nt++)
#pragma unroll
            for (int j = 0; j < 4; j++) acc[mt][nt][j] = 0.f;

    auto stage = [&](int c, int ss) {
        const int k0 = c * 64;
#pragma unroll
        for (int it = 0; it < 4; ++it) {
            const int idx = tid + it * 256;      // 0..1023
            const int r = idx >> 3;
            const int kc = idx & 7;
            CP_ASYNC16(addr128(sbase + GA(ss), r, kc),
                       A + (size_t)(m0g + r) * DM + k0 + kc * 8);
        }
#pragma unroll
        for (int it = 0; it < 8; ++it) {
            const int idx = tid + it * 256;      // 0..2047
            const int r = idx >> 3;
            const int kc = idx & 7;
            CP_ASYNC16(addr128(sbase + GB(ss), r, kc),
                       Bh + (size_t)(n0g + r) * DM + k0 + kc * 8);
        }
    };

    stage(0, 0);
    CP_COMMIT();
    stage(1, 1);
    CP_COMMIT();

    const int mat = lane >> 3;
    const int arow7 = (lane & 7) + ((mat & 1) << 3);
    const int brow7 = (lane & 7) + ((mat >> 1) << 3);

    for (int c = 0; c < NCHUNK; ++c) {
        if (c + 1 < NCHUNK) {
            CP_WAIT(1);
        } else {
            CP_WAIT(0);
        }
        __syncthreads();

        if (c + 2 < NCHUNK) {
            stage(c + 2, (c + 2) % 3);
            CP_COMMIT();
        }

        const int ss = c % 3;
        const uint32_t abase = sbase + GA(ss);
        const uint32_t bbase = sbase + GB(ss);

#pragma unroll
        for (int ks = 0; ks < 4; ++ks) {
            uint32_t af[4][4];
#pragma unroll
            for (int mt = 0; mt < 4; mt++) {
                const int row = wm * 64 + mt * 16 + arow7;
                const int kc = ks * 2 + (mat >> 1);
                LDSM_X4(af[mt][0], af[mt][1], af[mt][2], af[mt][3],
                        addr128(abase, row, kc));
            }
            uint32_t bf[4][4];
#pragma unroll
            for (int ntp = 0; ntp < 4; ntp++) {
                const int row = wn * 64 + ntp * 16 + brow7;
                const int kc = ks * 2 + (mat & 1);
                LDSM_X4(bf[ntp][0], bf[ntp][1], bf[ntp][2], bf[ntp][3],
                        addr128(bbase, row, kc));
            }
#pragma unroll
            for (int mt = 0; mt < 4; mt++)
#pragma unroll
                for (int nt = 0; nt < 8; nt++)
                    MMA_16816(acc[mt][nt], af[mt],
                              bf[nt >> 1][2 * (nt & 1)], bf[nt >> 1][2 * (nt & 1) + 1]);
        }
    }

    // Epilogue
    const int qrow = lane >> 2;
    const int qcol = (lane & 3) << 1;
    float2 bv[8];
#pragma unroll
    for (int nt = 0; nt < 8; nt++) {
        const int n = n0g + wn * 64 + nt * 8 + qcol;
        bv[nt] = make_float2(bias[n], bias[n + 1]);
    }
    if (mode == 0) {
#pragma unroll
        for (int mt = 0; mt < 4; mt++) {
            const int r0 = m0g + wm * 64 + mt * 16 + qrow;
#pragma unroll
            for (int nt = 0; nt < 8; nt++) {
                const int n = n0g + wn * 64 + nt * 8 + qcol;
                *(float2*)(C + (size_t)r0 * Ntot + n) =
                    make_float2(acc[mt][nt][0] + bv[nt].x, acc[mt][nt][1] + bv[nt].y);
                *(float2*)(C + (size_t)(r0 + 8) * Ntot + n) =
                    make_float2(acc[mt][nt][2] + bv[nt].x, acc[mt][nt][3] + bv[nt].y);
            }
        }
    } else {
        // restage fp16 tile [128][256] in smem, then coalesced 16B stores
        __syncthreads();                 // pipeline smem reads done everywhere
        const float scale = (n0g < DM) ? SCALE_L2E : 1.0f;
#pragma unroll
        for (int mt = 0; mt < 4; mt++) {
            const int row = wm * 64 + mt * 16 + qrow;
#pragma unroll
            for (int nt = 0; nt < 8; nt++) {
                const int colb = (wn * 64 + nt * 8 + qcol) * 2;
                *(__half2*)(gsm + row * EPI_STRIDE + colb) = __halves2half2(
                    __float2half((acc[mt][nt][0] + bv[nt].x) * scale),
                    __float2half((acc[mt][nt][1] + bv[nt].y) * scale));
                *(__half2*)(gsm + (row + 8) * EPI_STRIDE + colb) = __halves2half2(
                    __float2half((acc[mt][nt][2] + bv[nt].x) * scale),
                    __float2half((acc[mt][nt][3] + bv[nt].y) * scale));
            }
        }
        __syncthreads();
        __half* __restrict__ dst = (n0g < DM) ? qh : (n0g < 2 * DM) ? kh : vh;
        const int bb = m0g >> 11;              // batch
        const int s0 = m0g & (SEQ - 1);
        const int h0 = (n0g >> 6) & 15;
#pragma unroll
        for (int it = 0; it < 16; it++) {
            const int idx = tid + it * 256;     // 0..4095
            const int r = idx >> 5;             // row 0..127
            const int ch = idx & 31;            // 16B chunk 0..31
            const uint4 v = *(const uint4*)(gsm + r * EPI_STRIDE + ch * 16);
            const int hh = h0 + (ch >> 3);
            const int d = (ch & 7) * 8;
            *(uint4*)(dst + ((size_t)(bb * NH + hh) * SEQ + (s0 + r)) * DH + d) = v;
        }
    }
}

// ---------------------------------------------------------------------------
// HMMA flash attention (fp16, single-term, 128-wide k tiles).
// Block = 128 q-rows x one (b,h). S = Q K^T; PV = P V (ldmatrix.trans).
// smem: QH 16K + KH dbuf 2x16K + VH dbuf 2x16K = 80KB dynamic.
// ---------------------------------------------------------------------------
#define SM_QH 0
#define SM_KH(b) (16384 + (b) * 16384)
#define SM_VH(b) (49152 + (b) * 16384)
#define ATTN_SMEM_BYTES 81920

__global__ void __launch_bounds__(256) attn_mma_kernel()
{
    extern __shared__ uint8_t dsm[];
    const uint32_t sb = smem_u32(dsm);
    const int tid = (int)threadIdx.x;
    const int wid = tid >> 5;
    const int lane = tid & 31;
    const int qti = 15 - (int)blockIdx.x;       // heavy tiles first
    const int bh = (int)blockIdx.y;
    const int b = bh >> 4;
    const int h = bh & 15;

    const size_t base = (size_t)bh * SEQ * DH;

#pragma unroll
    for (int i = 0; i < 4; i++) {
        const int idx = tid + i * 256;
        const int r = idx >> 3;
        const int kc = idx & 7;
        CP_ASYNC16(addr128(sb + SM_QH, r, kc),
                   g_qh + base + (size_t)(qti * 128 + r) * DH + kc * 8);
    }

    const int nkt = qti + 1;                    // 128-wide k tiles

    auto stage_kv = [&](int kt, int bb) {
#pragma unroll
        for (int i = 0; i < 4; i++) {
            const int idx = tid + i * 256;      // 0..1023
            const int r = idx >> 3;
            const int kc = idx & 7;
            const size_t o = base + (size_t)(kt * 128 + r) * DH + kc * 8;
            CP_ASYNC16(addr128(sb + SM_KH(bb), r, kc), g_kh + o);
            CP_ASYNC16(addr128(sb + SM_VH(bb), r, kc), g_vh + o);
        }
    };

    stage_kv(0, 0);
    CP_COMMIT();

    float o[8][4];
#pragma unroll
    for (int t = 0; t < 8; t++)
#pragma unroll
        for (int j = 0; j < 4; j++) o[t][j] = 0.f;
    float m_a = NEG_BIG, m_b = NEG_BIG, l_a = 0.f, l_b = 0.f;

    const int qrow_base = qti * 128 + wid * 16;
    const int ra = lane >> 2;
    const int c2 = (lane & 3) << 1;
    const int mat = lane >> 3;

    int buf = 0;
    for (int kt = 0; kt < nkt; kt++) {
        if (kt + 1 < nkt) {
            stage_kv(kt + 1, buf ^ 1);
            CP_COMMIT();
            CP_WAIT(1);
        } else {
            CP_WAIT(0);
        }
        __syncthreads();

        // ---- S = Q K^T over 128 keys ----
        float s[16][4];
#pragma unroll
        for (int t = 0; t < 16; t++)
#pragma unroll
            for (int j = 0; j < 4; j++) s[t][j] = 0.f;

#pragma unroll
        for (int ks = 0; ks < 4; ks++) {
            const int arow = wid * 16 + (lane & 7) + ((mat & 1) << 3);
            const int akc = ks * 2 + (mat >> 1);
            uint32_t aqh[4];
            LDSM_X4(aqh[0], aqh[1], aqh[2], aqh[3], addr128(sb + SM_QH, arow, akc));

            const int brow7 = (lane & 7) + ((mat >> 1) << 3);
            const int bkc = ks * 2 + (mat & 1);
#pragma unroll
            for (int ntp = 0; ntp < 8; ntp++) {
                uint32_t bh4[4];
                LDSM_X4(bh4[0], bh4[1], bh4[2], bh4[3],
                        addr128(sb + SM_KH(buf), ntp * 16 + brow7, bkc));
#pragma unroll
                for (int half = 0; half < 2; half++) {
                    const int nt = ntp * 2 + half;
                    MMA_16816(s[nt], aqh, bh4[2 * half], bh4[2 * half + 1]);
                }
            }
        }

        // ---- causal mask (only the last tile is diagonal) ----
        if (kt * 128 + 127 > qrow_base) {
#pragma unroll
            for (int t = 0; t < 16; t++) {
                const int col = kt * 128 + t * 8 + c2;
                const int rowa = qrow_base + ra;
                const int rowb = rowa + 8;
                if (col > rowa)     s[t][0] = NEG_BIG;
                if (col + 1 > rowa) s[t][1] = NEG_BIG;
                if (col > rowb)     s[t][2] = NEG_BIG;
                if (col + 1 > rowb) s[t][3] = NEG_BIG;
            }
        }

        // ---- online softmax (log2 domain) ----
        float pa = NEG_BIG, pb = NEG_BIG;
#pragma unroll
        for (int t = 0; t < 16; t++) {
            pa = fmaxf(pa, fmaxf(s[t][0], s[t][1]));
            pb = fmaxf(pb, fmaxf(s[t][2], s[t][3]));
        }
        pa = fmaxf(pa, __shfl_xor_sync(0xffffffffu, pa, 1));
        pa = fmaxf(pa, __shfl_xor_sync(0xffffffffu, pa, 2));
        pb = fmaxf(pb, __shfl_xor_sync(0xffffffffu, pb, 1));
        pb = fmaxf(pb, __shfl_xor_sync(0xffffffffu, pb, 2));
        const float nm_a = fmaxf(m_a, pa);
        const float nm_b = fmaxf(m_b, pb);
        const float al_a = ex2f(m_a - nm_a);
        const float al_b = ex2f(m_b - nm_b);
        m_a = nm_a;
        m_b = nm_b;

        float sum_a = 0.f, sum_b = 0.f;
#pragma unroll
        for (int t = 0; t < 16; t++) {
            s[t][0] = ex2f(s[t][0] - nm_a);
            s[t][1] = ex2f(s[t][1] - nm_a);
            s[t][2] = ex2f(s[t][2] - nm_b);
            s[t][3] = ex2f(s[t][3] - nm_b);
            sum_a += s[t][0] + s[t][1];
            sum_b += s[t][2] + s[t][3];
        }
        sum_a += __shfl_xor_sync(0xffffffffu, sum_a, 1);
        sum_a += __shfl_xor_sync(0xffffffffu, sum_a, 2);
        sum_b += __shfl_xor_sync(0xffffffffu, sum_b, 1);
        sum_b += __shfl_xor_sync(0xffffffffu, sum_b, 2);
        l_a = l_a * al_a + sum_a;
        l_b = l_b * al_b + sum_b;
#pragma unroll
        for (int t = 0; t < 8; t++) {
            o[t][0] *= al_a;
            o[t][1] *= al_a;
            o[t][2] *= al_b;
            o[t][3] *= al_b;
        }

        // ---- repack P into A fragments (fp16) ----
        uint32_t phi[8][4];
#pragma unroll
        for (int ks = 0; ks < 8; ks++) {
#pragma unroll
            for (int half = 0; half < 2; half++) {
                const int t = 2 * ks + half;
                phi[ks][2 * half + 0] = pack_half(__float2half(s[t][0]),
                                                  __float2half(s[t][1]));
                phi[ks][2 * half + 1] = pack_half(__float2half(s[t][2]),
                                                  __float2half(s[t][3]));
            }
        }

        // ---- O += P V, V in [s][d] via trans-ldmatrix ----
        const int vsrow7 = (lane & 7) + ((mat & 1) << 3);
#pragma unroll
        for (int ks = 0; ks < 8; ks++) {
            const int srow = ks * 16 + vsrow7;
#pragma unroll
            for (int ntp = 0; ntp < 4; ntp++) {
                const int vkc = ntp * 2 + (mat >> 1);
                uint32_t v4[4];
                LDSM_X4T(v4[0], v4[1], v4[2], v4[3],
                         addr128(sb + SM_VH(buf), srow, vkc));
#pragma unroll
                for (int half = 0; half < 2; half++) {
                    const int nt = ntp * 2 + half;
                    MMA_16816(o[nt], phi[ks], v4[2 * half], v4[2 * half + 1]);
                }
            }
        }

        __syncthreads();
        buf ^= 1;
    }

    // ---- epilogue: normalize, fp16 for proj GEMM ----
    const float inv_a = 1.f / l_a;
    const float inv_b = 1.f / l_b;
#pragma unroll
    for (int t = 0; t < 8; t++) {
        const int col = h * DH + t * 8 + c2;
        const int rowa = qti * 128 + wid * 16 + ra;
        *(__half2*)(g_ahi + (size_t)(b * SEQ + rowa) * DM + col) =
            __halves2half2(__float2half(o[t][0] * inv_a),
                           __float2half(o[t][1] * inv_a));
        *(__half2*)(g_ahi + (size_t)(b * SEQ + rowa + 8) * DM + col) =
            __halves2half2(__float2half(o[t][2] * inv_b),
                           __float2half(o[t][3] * inv_b));
    }
}

// ---------------------------------------------------------------------------
extern "C" void kernel_launch(void* const* d_in, const int* in_sizes, int n_in,
                              void* d_out, int out_size)
{
    const float* input = (const float*)d_in[0];
    const float* W_qkv = (const float*)d_in[1];
    const float* b_qkv = (const float*)d_in[2];
    const float* W_out = (const float*)d_in[3];
    const float* b_out = (const float*)d_in[4];
    float* out = (float*)d_out;

    cudaFuncSetAttribute(attn_mma_kernel,
                         cudaFuncAttributeMaxDynamicSharedMemorySize, ATTN_SMEM_BYTES);
    cudaFuncSetAttribute(gemm_mma_kernel,
                         cudaFuncAttributeMaxDynamicSharedMemorySize, GEMM_SMEM_BYTES);

    __half *xhi, *wqT, *woT, *ahi, *qh, *kh, *vh;
    cudaGetSymbolAddress((void**)&xhi, g_xhi);
    cudaGetSymbolAddress((void**)&wqT, g_wqkvT);
    cudaGetSymbolAddress((void**)&woT, g_woutT);
    cudaGetSymbolAddress((void**)&ahi, g_ahi);
    cudaGetSymbolAddress((void**)&qh, g_qh);
    cudaGetSymbolAddress((void**)&kh, g_kh);
    cudaGetSymbolAddress((void**)&vh, g_vh);

    convert_input_kernel<<<(MROWS * DM / 4) / 256, 256>>>(
        (const float4*)input, (__half2*)xhi);
    transpose_half_kernel<<<dim3(TD / 32, DM / 32), 256>>>(W_qkv, TD, wqT);
    transpose_half_kernel<<<dim3(DM / 32, DM / 32), 256>>>(W_out, DM, woT);

    // qkv: hi-only; smem-restaged epilogue writes fp16 Q(scaled)/K/V directly
    gemm_mma_kernel<<<dim3(MROWS / 128, TD / 256), 256, GEMM_SMEM_BYTES>>>(
        xhi, wqT, b_qkv, nullptr, TD, qh, kh, vh, 1);

    attn_mma_kernel<<<dim3(SEQ / 128, NBH), 256, ATTN_SMEM_BYTES>>>();

    // proj: fp32 out
    gemm_mma_kernel<<<dim3(MROWS / 128, DM / 256), 256, GEMM_SMEM_BYTES>>>(
        ahi, woT, b_out, out, DM, qh, kh, vh, 0);
}